// round 1
// baseline (speedup 1.0000x reference)
#include <cuda_runtime.h>
#include <math.h>

// ---------------- problem constants ----------------
#define BB    16
#define NNN   4096
#define CCH   256
#define HHH   64
#define WWW   64
#define HIDD  1024
#define NHEAD 8
#define HDIM  32
#define MTOT  (BB*NNN)          // 65536 rows

// ---------------- scratch (device globals; no allocs allowed) ----------------
__device__ float g_xn  [MTOT*CCH];
__device__ float g_xa  [MTOT*CCH];
__device__ float g_qkv [MTOT*3*CCH];
__device__ float g_attn[MTOT*CCH];
__device__ float g_x   [MTOT*CCH];
__device__ float g_h1  [MTOT*HIDD];
__device__ float g_h2  [MTOT*HIDD];
__device__ float g_ctx [BB*NHEAD*HDIM*HDIM];
__device__ float g_qmax[BB*CCH];
__device__ float g_qsum[BB*CCH];
__device__ float g_avg [BB*CCH];
__device__ float g_mx  [BB*CCH];
__device__ float g_cab [BB*CCH];
__device__ float g_smean[MTOT];
__device__ float g_smax [MTOT];
__device__ float g_sa   [MTOT];

// ---------------- helpers ----------------
__device__ __forceinline__ float geluf(float x) {
    return 0.5f * x * (1.0f + erff(x * 0.70710678118654752f));
}
__device__ __forceinline__ float sigmoidf_(float x) {
    return 1.0f / (1.0f + expf(-x));
}
__device__ __forceinline__ void atomicMaxF(float* addr, float v) {
    int* ai = (int*)addr;
    int old = *ai;
    while (__int_as_float(old) < v) {
        int prev = atomicCAS(ai, old, __float_as_int(v));
        if (prev == old) break;
        old = prev;
    }
}

// ---------------- init (per-call, deterministic reset) ----------------
__global__ void init_kernel() {
    int i = blockIdx.x * blockDim.x + threadIdx.x;
    if (i < BB*NHEAD*HDIM*HDIM) g_ctx[i] = 0.f;
    if (i < BB*CCH) {
        g_qmax[i] = -1e30f;
        g_qsum[i] = 0.f;
        g_avg[i]  = 0.f;
        g_mx[i]   = -1e30f;
    }
}

// ---------------- LayerNorm over C=256, one warp per row ----------------
__global__ void ln_kernel(const float* __restrict__ in,
                          const float* __restrict__ gg,
                          const float* __restrict__ bb,
                          float* __restrict__ out) {
    int gid  = blockIdx.x * blockDim.x + threadIdx.x;
    int warp = gid >> 5;
    int lane = gid & 31;
    if (warp >= MTOT) return;
    const float* row = in + (size_t)warp * CCH;
    float4 a = ((const float4*)row)[lane*2];
    float4 b = ((const float4*)row)[lane*2+1];
    float s1 = a.x+a.y+a.z+a.w + b.x+b.y+b.z+b.w;
    float s2 = a.x*a.x+a.y*a.y+a.z*a.z+a.w*a.w + b.x*b.x+b.y*b.y+b.z*b.z+b.w*b.w;
    #pragma unroll
    for (int off = 16; off; off >>= 1) {
        s1 += __shfl_xor_sync(0xffffffffu, s1, off);
        s2 += __shfl_xor_sync(0xffffffffu, s2, off);
    }
    float mean = s1 * (1.0f/CCH);
    float var  = s2 * (1.0f/CCH) - mean*mean;
    float rstd = rsqrtf(var + 1e-5f);
    float4 g0 = ((const float4*)gg)[lane*2];
    float4 g1 = ((const float4*)gg)[lane*2+1];
    float4 b0 = ((const float4*)bb)[lane*2];
    float4 b1 = ((const float4*)bb)[lane*2+1];
    float4 o0, o1;
    o0.x=(a.x-mean)*rstd*g0.x+b0.x; o0.y=(a.y-mean)*rstd*g0.y+b0.y;
    o0.z=(a.z-mean)*rstd*g0.z+b0.z; o0.w=(a.w-mean)*rstd*g0.w+b0.w;
    o1.x=(b.x-mean)*rstd*g1.x+b1.x; o1.y=(b.y-mean)*rstd*g1.y+b1.y;
    o1.z=(b.z-mean)*rstd*g1.z+b1.z; o1.w=(b.w-mean)*rstd*g1.w+b1.w;
    float* orow = out + (size_t)warp * CCH;
    ((float4*)orow)[lane*2]   = o0;
    ((float4*)orow)[lane*2+1] = o1;
}

// ---------------- sr dwconv 3x3 + LN + gelu + residual -> xa ----------------
__global__ void sr_an_kernel(const float* __restrict__ sr_w, const float* __restrict__ sr_b,
                             const float* __restrict__ an_g, const float* __restrict__ an_b) {
    int row = blockIdx.x;                 // b*N + n
    int b = row >> 12, n = row & 4095;
    int h = n >> 6, w = n & 63;
    int c = threadIdx.x;
    float acc = sr_b[c];
    #pragma unroll
    for (int kh = 0; kh < 3; kh++) {
        int hh = h + kh - 1;
        if (hh < 0 || hh >= HHH) continue;
        #pragma unroll
        for (int kw = 0; kw < 3; kw++) {
            int ww = w + kw - 1;
            if (ww < 0 || ww >= WWW) continue;
            size_t src = ((size_t)((b<<12) | (hh<<6) | ww) << 8) + c;
            acc += g_xn[src] * sr_w[c*9 + kh*3 + kw];
        }
    }
    // block LN over 256 conv outputs
    float s1 = acc, s2 = acc*acc;
    #pragma unroll
    for (int off = 16; off; off >>= 1) {
        s1 += __shfl_xor_sync(0xffffffffu, s1, off);
        s2 += __shfl_xor_sync(0xffffffffu, s2, off);
    }
    __shared__ float r1[8], r2[8];
    int lane = c & 31, wid = c >> 5;
    if (lane == 0) { r1[wid] = s1; r2[wid] = s2; }
    __syncthreads();
    if (c == 0) {
        float a = 0.f, q = 0.f;
        #pragma unroll
        for (int i = 0; i < 8; i++) { a += r1[i]; q += r2[i]; }
        float mean = a * (1.0f/CCH);
        float var  = q * (1.0f/CCH) - mean*mean;
        r1[0] = mean; r2[0] = rsqrtf(var + 1e-5f);
    }
    __syncthreads();
    float mean = r1[0], rstd = r2[0];
    float yn = (acc - mean) * rstd * an_g[c] + an_b[c];
    size_t idx = ((size_t)row << 8) + c;
    g_xa[idx] = g_xn[idx] + geluf(yn);
}

// ---------------- fp32 GEMM: out = A[M,K] @ W[Nout,K]^T (+epi) ----------------
// EPI: 0 none, 1 +bias, 2 +bias+add1+add2, 3 +bias+add1
template<int EPI>
__global__ void __launch_bounds__(256)
gemm_kernel(const float* __restrict__ A, const float* __restrict__ Wt,
            const float* __restrict__ bias,
            const float* __restrict__ add1, const float* __restrict__ add2,
            float* __restrict__ out, int Nout, int K) {
    __shared__ float As[8][132];
    __shared__ float Ws[8][132];
    int row0 = blockIdx.y * 128;
    int col0 = blockIdx.x * 128;
    int t  = threadIdx.x;
    int tr = t >> 1, tc = (t & 1) * 4;
    int tx = t & 15, ty = t >> 4;
    float acc[8][8];
    #pragma unroll
    for (int i = 0; i < 8; i++)
        #pragma unroll
        for (int j = 0; j < 8; j++) acc[i][j] = 0.f;

    for (int k0 = 0; k0 < K; k0 += 8) {
        float4 a4 = *(const float4*)(A  + (size_t)(row0 + tr) * K + k0 + tc);
        float4 w4 = *(const float4*)(Wt + (size_t)(col0 + tr) * K + k0 + tc);
        As[tc+0][tr] = a4.x; As[tc+1][tr] = a4.y; As[tc+2][tr] = a4.z; As[tc+3][tr] = a4.w;
        Ws[tc+0][tr] = w4.x; Ws[tc+1][tr] = w4.y; Ws[tc+2][tr] = w4.z; Ws[tc+3][tr] = w4.w;
        __syncthreads();
        #pragma unroll
        for (int kk = 0; kk < 8; kk++) {
            float ar[8], wr[8];
            #pragma unroll
            for (int i = 0; i < 8; i++) ar[i] = As[kk][ty*8 + i];
            #pragma unroll
            for (int j = 0; j < 8; j++) wr[j] = Ws[kk][tx*8 + j];
            #pragma unroll
            for (int i = 0; i < 8; i++)
                #pragma unroll
                for (int j = 0; j < 8; j++) acc[i][j] += ar[i] * wr[j];
        }
        __syncthreads();
    }
    #pragma unroll
    for (int i = 0; i < 8; i++) {
        int r = row0 + ty*8 + i;
        size_t base = (size_t)r * Nout + col0 + tx*8;
        #pragma unroll
        for (int j = 0; j < 8; j++) {
            float v = acc[i][j];
            int cidx = col0 + tx*8 + j;
            if (EPI >= 1) v += bias[cidx];
            if (EPI == 2) v += add1[base + j] + add2[base + j];
            if (EPI == 3) v += add1[base + j];
            out[base + j] = v;
        }
    }
}

// ---------------- k softmax over head dim (in place on qkv cols 256..511) ----
__global__ void ksm_kernel() {
    int row  = blockIdx.x;
    int wid  = threadIdx.x >> 5;
    int lane = threadIdx.x & 31;
    float* p = g_qkv + (size_t)row * 768 + 256 + wid * 32;
    float v = p[lane];
    float m = v;
    #pragma unroll
    for (int off = 16; off; off >>= 1) m = fmaxf(m, __shfl_xor_sync(0xffffffffu, m, off));
    float e = expf(v - m);
    float s = e;
    #pragma unroll
    for (int off = 16; off; off >>= 1) s += __shfl_xor_sync(0xffffffffu, s, off);
    p[lane] = e / s;
}

// ---------------- q column max / sumexp over tokens ----------------
__global__ void qmax_kernel() {
    int b = blockIdx.y, chunk = blockIdx.x, c = threadIdx.x;
    float m = -1e30f;
    int base = b * NNN + chunk * 128;
    for (int r = 0; r < 128; r++)
        m = fmaxf(m, g_qkv[(size_t)(base + r) * 768 + c]);
    atomicMaxF(&g_qmax[b * CCH + c], m);
}
__global__ void qsum_kernel() {
    int b = blockIdx.y, chunk = blockIdx.x, c = threadIdx.x;
    float qm = g_qmax[b * CCH + c];
    float s = 0.f;
    int base = b * NNN + chunk * 128;
    for (int r = 0; r < 128; r++)
        s += expf(g_qkv[(size_t)(base + r) * 768 + c] - qm);
    atomicAdd(&g_qsum[b * CCH + c], s);
}

// ---------------- ctx = k_sm^T v  (per head 32x32), split-N atomic ----------
__global__ void ctx_kernel() {
    int bh = blockIdx.y;              // b*8+h
    int b = bh >> 3, h = bh & 7;
    int d = threadIdx.x >> 5, e = threadIdx.x & 31;
    __shared__ float ks[8][32], vs[8][32];
    int base = b * NNN + blockIdx.x * 256;
    float acc = 0.f;
    for (int it = 0; it < 32; it++) {
        int t = threadIdx.x;
        if (t < 256) {
            int r = t >> 5, cc = t & 31;
            ks[r][cc] = g_qkv[(size_t)(base + it*8 + r) * 768 + 256 + h*32 + cc];
        } else if (t < 512) {
            int tt = t - 256, r = tt >> 5, cc = tt & 31;
            vs[r][cc] = g_qkv[(size_t)(base + it*8 + r) * 768 + 512 + h*32 + cc];
        }
        __syncthreads();
        #pragma unroll
        for (int r = 0; r < 8; r++) acc += ks[r][d] * vs[r][e];
        __syncthreads();
    }
    atomicAdd(&g_ctx[bh * 1024 + d * 32 + e], acc);
}

// ---------------- attn = softmax_N(q) @ ctx ----------------
__global__ void attn_kernel() {
    int b = blockIdx.y;
    __shared__ float ctxs[NHEAD*HDIM*HDIM];   // 32KB
    __shared__ float qs[CCH];
    for (int i = threadIdx.x; i < NHEAD*HDIM*HDIM; i += 256)
        ctxs[i] = g_ctx[b * (NHEAD*HDIM*HDIM) + i];
    int c = threadIdx.x;
    int h = c >> 5, e = c & 31;
    float qm = g_qmax[b * CCH + c];
    float qi = 1.0f / g_qsum[b * CCH + c];
    __syncthreads();
    for (int r = 0; r < 64; r++) {
        int row = b * NNN + blockIdx.x * 64 + r;
        float qv = g_qkv[(size_t)row * 768 + c];
        qs[c] = expf(qv - qm) * qi;
        __syncthreads();
        float acc = 0.f;
        #pragma unroll
        for (int d = 0; d < 32; d++)
            acc += qs[h*32 + d] * ctxs[h*1024 + d*32 + e];
        g_attn[(size_t)row * CCH + c] = acc;
        __syncthreads();
    }
}

// ---------------- MixFFN dwconv 3x3 (1024 ch) + gelu ----------------
__global__ void dw_gelu_kernel(const float* __restrict__ dw_w, const float* __restrict__ dw_b) {
    int row = blockIdx.x;
    int b = row >> 12, n = row & 4095;
    int h = n >> 6, w = n & 63;
    for (int cc = 0; cc < 4; cc++) {
        int c = cc * 256 + threadIdx.x;
        float acc = dw_b[c];
        #pragma unroll
        for (int kh = 0; kh < 3; kh++) {
            int hh = h + kh - 1;
            if (hh < 0 || hh >= HHH) continue;
            #pragma unroll
            for (int kw = 0; kw < 3; kw++) {
                int ww = w + kw - 1;
                if (ww < 0 || ww >= WWW) continue;
                size_t src = ((size_t)((b<<12) | (hh<<6) | ww)) * HIDD + c;
                acc += g_h1[src] * dw_w[c*9 + kh*3 + kw];
            }
        }
        g_h2[(size_t)row * HIDD + c] = geluf(acc);
    }
}

// ---------------- CSDA channel stats ----------------
__global__ void avgmax_kernel() {
    int b = blockIdx.y, chunk = blockIdx.x, c = threadIdx.x;
    float s = 0.f, m = -1e30f;
    int base = b * NNN + chunk * 128;
    for (int r = 0; r < 128; r++) {
        float v = g_x[(size_t)(base + r) * CCH + c];
        s += v; m = fmaxf(m, v);
    }
    atomicAdd(&g_avg[b * CCH + c], s);
    atomicMaxF(&g_mx[b * CCH + c], m);
}

__global__ void ca_kernel(const float* __restrict__ w1, const float* __restrict__ w2) {
    int b = blockIdx.x, t = threadIdx.x;
    __shared__ float sav[CCH], smx[CCH], hid[32];
    sav[t] = g_avg[b * CCH + t] * (1.0f / NNN);
    smx[t] = g_mx[b * CCH + t];
    __syncthreads();
    if (t < 16) {
        float a = 0.f;
        for (int c = 0; c < CCH; c++) a += sav[c] * w1[t * CCH + c];
        hid[t] = fmaxf(a, 0.f);
    } else if (t < 32) {
        int j = t - 16;
        float a = 0.f;
        for (int c = 0; c < CCH; c++) a += smx[c] * w1[j * CCH + c];
        hid[16 + j] = fmaxf(a, 0.f);
    }
    __syncthreads();
    float a = 0.f;
    #pragma unroll
    for (int j = 0; j < 16; j++) a += (hid[j] + hid[16 + j]) * w2[t * 16 + j];
    g_cab[b * CCH + t] = sigmoidf_(a);
}

// ---------------- spatial map: mean/max over channels of x*ca ----------------
__global__ void smap_kernel() {
    int gid  = blockIdx.x * blockDim.x + threadIdx.x;
    int warp = gid >> 5, lane = gid & 31;
    if (warp >= MTOT) return;
    int b = warp >> 12;
    const float* row = g_x + (size_t)warp * CCH;
    const float* ca  = g_cab + b * CCH;
    float4 a = ((const float4*)row)[lane*2];
    float4 c4 = ((const float4*)ca)[lane*2];
    float4 b4 = ((const float4*)row)[lane*2+1];
    float4 d4 = ((const float4*)ca)[lane*2+1];
    float v0=a.x*c4.x, v1=a.y*c4.y, v2=a.z*c4.z, v3=a.w*c4.w;
    float v4=b4.x*d4.x, v5=b4.y*d4.y, v6=b4.z*d4.z, v7=b4.w*d4.w;
    float s = v0+v1+v2+v3+v4+v5+v6+v7;
    float m = fmaxf(fmaxf(fmaxf(v0,v1),fmaxf(v2,v3)), fmaxf(fmaxf(v4,v5),fmaxf(v6,v7)));
    #pragma unroll
    for (int off = 16; off; off >>= 1) {
        s += __shfl_xor_sync(0xffffffffu, s, off);
        m = fmaxf(m, __shfl_xor_sync(0xffffffffu, m, off));
    }
    if (lane == 0) {
        g_smean[warp] = s * (1.0f / CCH);
        g_smax[warp]  = m;
    }
}

// ---------------- spatial attention 7x7 conv + sigmoid ----------------
__global__ void sa_kernel(const float* __restrict__ sp_w, const float* __restrict__ sp_b) {
    int idx = blockIdx.x * blockDim.x + threadIdx.x;   // b*N+n
    int b = idx >> 12, n = idx & 4095;
    int h = n >> 6, w = n & 63;
    float acc = sp_b[0];
    for (int kh = 0; kh < 7; kh++) {
        int hh = h + kh - 3;
        if (hh < 0 || hh >= HHH) continue;
        for (int kw = 0; kw < 7; kw++) {
            int ww = w + kw - 3;
            if (ww < 0 || ww >= WWW) continue;
            int nn = b * NNN + hh * 64 + ww;
            acc += g_smean[nn] * sp_w[kh*7 + kw] + g_smax[nn] * sp_w[49 + kh*7 + kw];
        }
    }
    g_sa[idx] = sigmoidf_(acc);
}

// ---------------- final: out = x * ca * sa ----------------
__global__ void final_kernel(float* __restrict__ out) {
    int gid = blockIdx.x * blockDim.x + threadIdx.x;
    size_t idx4 = (size_t)gid * 4;
    int row = (int)(idx4 >> 8);
    int c   = (int)(idx4 & 255);
    int b   = row >> 12;
    float sa = g_sa[row];
    float4 ca = *(const float4*)(g_cab + b * CCH + c);
    float4 xv = *(const float4*)(g_x + idx4);
    float4 o;
    o.x = xv.x * ca.x * sa; o.y = xv.y * ca.y * sa;
    o.z = xv.z * ca.z * sa; o.w = xv.w * ca.w * sa;
    *(float4*)(out + idx4) = o;
}

// ---------------- launch ----------------
extern "C" void kernel_launch(void* const* d_in, const int* in_sizes, int n_in,
                              void* d_out, int out_size) {
    const float* x      = (const float*)d_in[0];
    const float* n1_g   = (const float*)d_in[3];
    const float* n1_b   = (const float*)d_in[4];
    const float* sr_w   = (const float*)d_in[5];
    const float* sr_b   = (const float*)d_in[6];
    const float* an_g   = (const float*)d_in[7];
    const float* an_b   = (const float*)d_in[8];
    const float* qkv_w  = (const float*)d_in[9];
    const float* proj_w = (const float*)d_in[10];
    const float* proj_b = (const float*)d_in[11];
    const float* n2_g   = (const float*)d_in[12];
    const float* n2_b   = (const float*)d_in[13];
    const float* fc1_w  = (const float*)d_in[14];
    const float* fc1_b  = (const float*)d_in[15];
    const float* dw_w   = (const float*)d_in[16];
    const float* dw_b   = (const float*)d_in[17];
    const float* fc2_w  = (const float*)d_in[18];
    const float* fc2_b  = (const float*)d_in[19];
    const float* ca_w1  = (const float*)d_in[20];
    const float* ca_w2  = (const float*)d_in[21];
    const float* sp_w   = (const float*)d_in[22];
    const float* sp_b   = (const float*)d_in[23];
    float* out = (float*)d_out;

    float *p_xn, *p_xa, *p_qkv, *p_attn, *p_x, *p_h1, *p_h2;
    cudaGetSymbolAddress((void**)&p_xn,   g_xn);
    cudaGetSymbolAddress((void**)&p_xa,   g_xa);
    cudaGetSymbolAddress((void**)&p_qkv,  g_qkv);
    cudaGetSymbolAddress((void**)&p_attn, g_attn);
    cudaGetSymbolAddress((void**)&p_x,    g_x);
    cudaGetSymbolAddress((void**)&p_h1,   g_h1);
    cudaGetSymbolAddress((void**)&p_h2,   g_h2);

    init_kernel<<<512, 256>>>();

    // --- attention branch ---
    ln_kernel<<<MTOT/8, 256>>>(x, n1_g, n1_b, p_xn);
    sr_an_kernel<<<MTOT, 256>>>(sr_w, sr_b, an_g, an_b);
    gemm_kernel<0><<<dim3(768/128, MTOT/128), 256>>>(p_xa, qkv_w, nullptr, nullptr, nullptr,
                                                     p_qkv, 768, 256);
    ksm_kernel<<<MTOT, 256>>>();
    qmax_kernel<<<dim3(32, BB), 256>>>();
    qsum_kernel<<<dim3(32, BB), 256>>>();
    ctx_kernel<<<dim3(16, BB*NHEAD), 1024>>>();
    attn_kernel<<<dim3(64, BB), 256>>>();
    gemm_kernel<2><<<dim3(256/128, MTOT/128), 256>>>(p_attn, proj_w, proj_b, p_xn, x,
                                                     p_x, 256, 256);

    // --- MixFFN ---
    ln_kernel<<<MTOT/8, 256>>>(p_x, n2_g, n2_b, p_xn);
    gemm_kernel<1><<<dim3(1024/128, MTOT/128), 256>>>(p_xn, fc1_w, fc1_b, nullptr, nullptr,
                                                      p_h1, 1024, 256);
    dw_gelu_kernel<<<MTOT, 256>>>(dw_w, dw_b);
    gemm_kernel<3><<<dim3(256/128, MTOT/128), 256>>>(p_h2, fc2_w, fc2_b, p_x, nullptr,
                                                     p_x, 256, 1024);

    // --- CSDA ---
    avgmax_kernel<<<dim3(32, BB), 256>>>();
    ca_kernel<<<BB, 256>>>(ca_w1, ca_w2);
    smap_kernel<<<MTOT/8, 256>>>();
    sa_kernel<<<MTOT/256, 256>>>(sp_w, sp_b);
    final_kernel<<<(MTOT*CCH/4)/256, 256>>>(out);
}

// round 2
// speedup vs baseline: 1.7656x; 1.7656x over previous
#include <cuda_runtime.h>
#include <math.h>

// ---------------- problem constants ----------------
#define BB    16
#define NNN   4096
#define CCH   256
#define HHH   64
#define WWW   64
#define HIDD  1024
#define NHEAD 8
#define HDIM  32
#define MTOT  (BB*NNN)          // 65536 rows

// ---------------- scratch (device globals; no allocs allowed) ----------------
__device__ float g_xn  [MTOT*CCH];
__device__ float g_xa  [MTOT*CCH];
__device__ float g_qkv [MTOT*3*CCH];
__device__ float g_attn[MTOT*CCH];
__device__ float g_x   [MTOT*CCH];
__device__ float g_h1  [MTOT*HIDD];
__device__ float g_h2  [MTOT*HIDD];
__device__ float g_ctx [BB*NHEAD*HDIM*HDIM];
__device__ float g_qmax[BB*CCH];
__device__ float g_qsum[BB*CCH];
__device__ float g_avg [BB*CCH];
__device__ float g_mx  [BB*CCH];
__device__ float g_cab [BB*CCH];
__device__ float g_smean[MTOT];
__device__ float g_smax [MTOT];
__device__ float g_sa   [MTOT];

// ---------------- helpers ----------------
__device__ __forceinline__ float geluf(float x) {
    return 0.5f * x * (1.0f + erff(x * 0.70710678118654752f));
}
__device__ __forceinline__ float sigmoidf_(float x) {
    return 1.0f / (1.0f + expf(-x));
}
__device__ __forceinline__ void atomicMaxF(float* addr, float v) {
    int* ai = (int*)addr;
    int old = *ai;
    while (__int_as_float(old) < v) {
        int prev = atomicCAS(ai, old, __float_as_int(v));
        if (prev == old) break;
        old = prev;
    }
}
__device__ __forceinline__ float to_tf32(float x) {
    asm("cvt.rna.tf32.f32 %0, %0;" : "+f"(x));
    return x;
}

// ---------------- init (per-call, deterministic reset) ----------------
__global__ void init_kernel() {
    int i = blockIdx.x * blockDim.x + threadIdx.x;
    if (i < BB*NHEAD*HDIM*HDIM) g_ctx[i] = 0.f;
    if (i < BB*CCH) {
        g_qmax[i] = -1e30f;
        g_qsum[i] = 0.f;
        g_avg[i]  = 0.f;
        g_mx[i]   = -1e30f;
    }
}

// ---------------- LayerNorm over C=256, one warp per row ----------------
__global__ void ln_kernel(const float* __restrict__ in,
                          const float* __restrict__ gg,
                          const float* __restrict__ bb,
                          float* __restrict__ out) {
    int gid  = blockIdx.x * blockDim.x + threadIdx.x;
    int warp = gid >> 5;
    int lane = gid & 31;
    if (warp >= MTOT) return;
    const float* row = in + (size_t)warp * CCH;
    float4 a = ((const float4*)row)[lane*2];
    float4 b = ((const float4*)row)[lane*2+1];
    float s1 = a.x+a.y+a.z+a.w + b.x+b.y+b.z+b.w;
    float s2 = a.x*a.x+a.y*a.y+a.z*a.z+a.w*a.w + b.x*b.x+b.y*b.y+b.z*b.z+b.w*b.w;
    #pragma unroll
    for (int off = 16; off; off >>= 1) {
        s1 += __shfl_xor_sync(0xffffffffu, s1, off);
        s2 += __shfl_xor_sync(0xffffffffu, s2, off);
    }
    float mean = s1 * (1.0f/CCH);
    float var  = s2 * (1.0f/CCH) - mean*mean;
    float rstd = rsqrtf(var + 1e-5f);
    float4 g0 = ((const float4*)gg)[lane*2];
    float4 g1 = ((const float4*)gg)[lane*2+1];
    float4 b0 = ((const float4*)bb)[lane*2];
    float4 b1 = ((const float4*)bb)[lane*2+1];
    float4 o0, o1;
    o0.x=(a.x-mean)*rstd*g0.x+b0.x; o0.y=(a.y-mean)*rstd*g0.y+b0.y;
    o0.z=(a.z-mean)*rstd*g0.z+b0.z; o0.w=(a.w-mean)*rstd*g0.w+b0.w;
    o1.x=(b.x-mean)*rstd*g1.x+b1.x; o1.y=(b.y-mean)*rstd*g1.y+b1.y;
    o1.z=(b.z-mean)*rstd*g1.z+b1.z; o1.w=(b.w-mean)*rstd*g1.w+b1.w;
    float* orow = out + (size_t)warp * CCH;
    ((float4*)orow)[lane*2]   = o0;
    ((float4*)orow)[lane*2+1] = o1;
}

// ---------------- sr dwconv 3x3 + LN + gelu + residual -> xa ----------------
__global__ void sr_an_kernel(const float* __restrict__ sr_w, const float* __restrict__ sr_b,
                             const float* __restrict__ an_g, const float* __restrict__ an_b) {
    int row = blockIdx.x;                 // b*N + n
    int b = row >> 12, n = row & 4095;
    int h = n >> 6, w = n & 63;
    int c = threadIdx.x;
    float acc = sr_b[c];
    #pragma unroll
    for (int kh = 0; kh < 3; kh++) {
        int hh = h + kh - 1;
        if (hh < 0 || hh >= HHH) continue;
        #pragma unroll
        for (int kw = 0; kw < 3; kw++) {
            int ww = w + kw - 1;
            if (ww < 0 || ww >= WWW) continue;
            size_t src = ((size_t)((b<<12) | (hh<<6) | ww) << 8) + c;
            acc += g_xn[src] * sr_w[c*9 + kh*3 + kw];
        }
    }
    // block LN over 256 conv outputs
    float s1 = acc, s2 = acc*acc;
    #pragma unroll
    for (int off = 16; off; off >>= 1) {
        s1 += __shfl_xor_sync(0xffffffffu, s1, off);
        s2 += __shfl_xor_sync(0xffffffffu, s2, off);
    }
    __shared__ float r1[8], r2[8];
    int lane = c & 31, wid = c >> 5;
    if (lane == 0) { r1[wid] = s1; r2[wid] = s2; }
    __syncthreads();
    if (c == 0) {
        float a = 0.f, q = 0.f;
        #pragma unroll
        for (int i = 0; i < 8; i++) { a += r1[i]; q += r2[i]; }
        float mean = a * (1.0f/CCH);
        float var  = q * (1.0f/CCH) - mean*mean;
        r1[0] = mean; r2[0] = rsqrtf(var + 1e-5f);
    }
    __syncthreads();
    float mean = r1[0], rstd = r2[0];
    float yn = (acc - mean) * rstd * an_g[c] + an_b[c];
    size_t idx = ((size_t)row << 8) + c;
    g_xa[idx] = g_xn[idx] + geluf(yn);
}

// ---------------- tf32 tensor-core GEMM: out = A[M,K] @ W[Nout,K]^T (+epi) ----
// EPI: 0 none, 1 +bias, 2 +bias+add1+add2, 3 +bias+add1
// Tiles: block 128x128xBK16, 8 warps of 32x64, mma m16n8k8.
#define SST 136   // smem row stride (floats): k*136 mod 32 = k*8 -> conflict-free frags

__device__ __forceinline__ void mma_tf32(float* d, const unsigned* a, const unsigned* b) {
    asm volatile(
        "mma.sync.aligned.m16n8k8.row.col.f32.tf32.tf32.f32 "
        "{%0,%1,%2,%3}, {%4,%5,%6,%7}, {%8,%9}, {%0,%1,%2,%3};"
        : "+f"(d[0]), "+f"(d[1]), "+f"(d[2]), "+f"(d[3])
        : "r"(a[0]), "r"(a[1]), "r"(a[2]), "r"(a[3]), "r"(b[0]), "r"(b[1]));
}

template<int EPI>
__global__ void __launch_bounds__(256)
gemm_tf32(const float* __restrict__ A, const float* __restrict__ Wt,
          const float* __restrict__ bias,
          const float* __restrict__ add1, const float* __restrict__ add2,
          float* __restrict__ out, int Nout, int K) {
    __shared__ float As[2][16][SST];
    __shared__ float Bs[2][16][SST];

    const int t = threadIdx.x;
    const int warp = t >> 5, lane = t & 31;
    const int wm = (warp & 3) * 32;      // warp row offset in block
    const int wn = (warp >> 2) * 64;     // warp col offset in block
    const int grp = lane >> 2;           // 0..7
    const int kq  = lane & 3;            // 0..3
    const int row0 = blockIdx.y * 128;
    const int col0 = blockIdx.x * 128;

    // global load mapping: thread loads row (t>>1), cols (t&1)*8 .. +7 (two float4)
    const int lr = t >> 1;
    const int lc = (t & 1) * 8;
    const float* pA = A  + (size_t)(row0 + lr) * K + lc;
    const float* pB = Wt + (size_t)(col0 + lr) * K + lc;

    float acc[2][8][4];
    #pragma unroll
    for (int i = 0; i < 2; i++)
        #pragma unroll
        for (int j = 0; j < 8; j++)
            #pragma unroll
            for (int q = 0; q < 4; q++) acc[i][j][q] = 0.f;

    // preload k0 = 0
    {
        float4 a0 = *(const float4*)(pA);
        float4 a1 = *(const float4*)(pA + 4);
        float4 b0 = *(const float4*)(pB);
        float4 b1 = *(const float4*)(pB + 4);
        As[0][lc+0][lr] = to_tf32(a0.x); As[0][lc+1][lr] = to_tf32(a0.y);
        As[0][lc+2][lr] = to_tf32(a0.z); As[0][lc+3][lr] = to_tf32(a0.w);
        As[0][lc+4][lr] = to_tf32(a1.x); As[0][lc+5][lr] = to_tf32(a1.y);
        As[0][lc+6][lr] = to_tf32(a1.z); As[0][lc+7][lr] = to_tf32(a1.w);
        Bs[0][lc+0][lr] = to_tf32(b0.x); Bs[0][lc+1][lr] = to_tf32(b0.y);
        Bs[0][lc+2][lr] = to_tf32(b0.z); Bs[0][lc+3][lr] = to_tf32(b0.w);
        Bs[0][lc+4][lr] = to_tf32(b1.x); Bs[0][lc+5][lr] = to_tf32(b1.y);
        Bs[0][lc+6][lr] = to_tf32(b1.z); Bs[0][lc+7][lr] = to_tf32(b1.w);
    }
    __syncthreads();

    int buf = 0;
    for (int k0 = 0; k0 < K; k0 += 16) {
        const bool last = (k0 + 16 >= K);
        float4 pa0, pa1, pb0, pb1;
        if (!last) {
            const float* qA = pA + k0 + 16;
            const float* qB = pB + k0 + 16;
            pa0 = *(const float4*)(qA);
            pa1 = *(const float4*)(qA + 4);
            pb0 = *(const float4*)(qB);
            pb1 = *(const float4*)(qB + 4);
        }
        // compute two k8 sub-steps from smem[buf]
        #pragma unroll
        for (int s = 0; s < 2; s++) {
            const int kb = s * 8;
            unsigned af[2][4], bf[8][2];
            #pragma unroll
            for (int i = 0; i < 2; i++) {
                int m = wm + i * 16 + grp;
                af[i][0] = __float_as_uint(As[buf][kb + kq    ][m]);
                af[i][1] = __float_as_uint(As[buf][kb + kq    ][m + 8]);
                af[i][2] = __float_as_uint(As[buf][kb + kq + 4][m]);
                af[i][3] = __float_as_uint(As[buf][kb + kq + 4][m + 8]);
            }
            #pragma unroll
            for (int j = 0; j < 8; j++) {
                int n = wn + j * 8 + grp;
                bf[j][0] = __float_as_uint(Bs[buf][kb + kq    ][n]);
                bf[j][1] = __float_as_uint(Bs[buf][kb + kq + 4][n]);
            }
            #pragma unroll
            for (int i = 0; i < 2; i++)
                #pragma unroll
                for (int j = 0; j < 8; j++)
                    mma_tf32(acc[i][j], af[i], bf[j]);
        }
        if (!last) {
            int nb = buf ^ 1;
            As[nb][lc+0][lr] = to_tf32(pa0.x); As[nb][lc+1][lr] = to_tf32(pa0.y);
            As[nb][lc+2][lr] = to_tf32(pa0.z); As[nb][lc+3][lr] = to_tf32(pa0.w);
            As[nb][lc+4][lr] = to_tf32(pa1.x); As[nb][lc+5][lr] = to_tf32(pa1.y);
            As[nb][lc+6][lr] = to_tf32(pa1.z); As[nb][lc+7][lr] = to_tf32(pa1.w);
            Bs[nb][lc+0][lr] = to_tf32(pb0.x); Bs[nb][lc+1][lr] = to_tf32(pb0.y);
            Bs[nb][lc+2][lr] = to_tf32(pb0.z); Bs[nb][lc+3][lr] = to_tf32(pb0.w);
            Bs[nb][lc+4][lr] = to_tf32(pb1.x); Bs[nb][lc+5][lr] = to_tf32(pb1.y);
            Bs[nb][lc+6][lr] = to_tf32(pb1.z); Bs[nb][lc+7][lr] = to_tf32(pb1.w);
        }
        __syncthreads();
        buf ^= 1;
    }

    // epilogue: c0,c1 -> (row, col), (row, col+1); c2,c3 -> row+8
    #pragma unroll
    for (int i = 0; i < 2; i++) {
        int r_lo = row0 + wm + i * 16 + grp;
        #pragma unroll
        for (int j = 0; j < 8; j++) {
            int cidx = col0 + wn + j * 8 + kq * 2;
            float bv0 = 0.f, bv1 = 0.f;
            if (EPI >= 1) { bv0 = bias[cidx]; bv1 = bias[cidx + 1]; }
            size_t o_lo = (size_t)r_lo * Nout + cidx;
            size_t o_hi = o_lo + (size_t)8 * Nout;
            float v0 = acc[i][j][0] + bv0;
            float v1 = acc[i][j][1] + bv1;
            float v2 = acc[i][j][2] + bv0;
            float v3 = acc[i][j][3] + bv1;
            if (EPI == 2) {
                v0 += add1[o_lo] + add2[o_lo];
                v1 += add1[o_lo + 1] + add2[o_lo + 1];
                v2 += add1[o_hi] + add2[o_hi];
                v3 += add1[o_hi + 1] + add2[o_hi + 1];
            }
            if (EPI == 3) {
                v0 += add1[o_lo];     v1 += add1[o_lo + 1];
                v2 += add1[o_hi];     v3 += add1[o_hi + 1];
            }
            *(float2*)(out + o_lo) = make_float2(v0, v1);
            *(float2*)(out + o_hi) = make_float2(v2, v3);
        }
    }
}

// ---------------- k softmax over head dim (in place on qkv cols 256..511) ----
__global__ void ksm_kernel() {
    int row  = blockIdx.x;
    int wid  = threadIdx.x >> 5;
    int lane = threadIdx.x & 31;
    float* p = g_qkv + (size_t)row * 768 + 256 + wid * 32;
    float v = p[lane];
    float m = v;
    #pragma unroll
    for (int off = 16; off; off >>= 1) m = fmaxf(m, __shfl_xor_sync(0xffffffffu, m, off));
    float e = expf(v - m);
    float s = e;
    #pragma unroll
    for (int off = 16; off; off >>= 1) s += __shfl_xor_sync(0xffffffffu, s, off);
    p[lane] = e / s;
}

// ---------------- q column max / sumexp over tokens ----------------
__global__ void qmax_kernel() {
    int b = blockIdx.y, chunk = blockIdx.x, c = threadIdx.x;
    float m = -1e30f;
    int base = b * NNN + chunk * 128;
    for (int r = 0; r < 128; r++)
        m = fmaxf(m, g_qkv[(size_t)(base + r) * 768 + c]);
    atomicMaxF(&g_qmax[b * CCH + c], m);
}
__global__ void qsum_kernel() {
    int b = blockIdx.y, chunk = blockIdx.x, c = threadIdx.x;
    float qm = g_qmax[b * CCH + c];
    float s = 0.f;
    int base = b * NNN + chunk * 128;
    for (int r = 0; r < 128; r++)
        s += expf(g_qkv[(size_t)(base + r) * 768 + c] - qm);
    atomicAdd(&g_qsum[b * CCH + c], s);
}

// ---------------- ctx = k_sm^T v  (per head 32x32), split-N atomic ----------
__global__ void ctx_kernel() {
    int bh = blockIdx.y;              // b*8+h
    int b = bh >> 3, h = bh & 7;
    int d = threadIdx.x >> 5, e = threadIdx.x & 31;
    __shared__ float ks[8][32], vs[8][32];
    int base = b * NNN + blockIdx.x * 256;
    float acc = 0.f;
    for (int it = 0; it < 32; it++) {
        int t = threadIdx.x;
        if (t < 256) {
            int r = t >> 5, cc = t & 31;
            ks[r][cc] = g_qkv[(size_t)(base + it*8 + r) * 768 + 256 + h*32 + cc];
        } else if (t < 512) {
            int tt = t - 256, r = tt >> 5, cc = tt & 31;
            vs[r][cc] = g_qkv[(size_t)(base + it*8 + r) * 768 + 512 + h*32 + cc];
        }
        __syncthreads();
        #pragma unroll
        for (int r = 0; r < 8; r++) acc += ks[r][d] * vs[r][e];
        __syncthreads();
    }
    atomicAdd(&g_ctx[bh * 1024 + d * 32 + e], acc);
}

// ---------------- attn = softmax_N(q) @ ctx ----------------
__global__ void attn_kernel() {
    int b = blockIdx.y;
    __shared__ float ctxs[NHEAD*HDIM*HDIM];   // 32KB
    __shared__ float qs[CCH];
    for (int i = threadIdx.x; i < NHEAD*HDIM*HDIM; i += 256)
        ctxs[i] = g_ctx[b * (NHEAD*HDIM*HDIM) + i];
    int c = threadIdx.x;
    int h = c >> 5, e = c & 31;
    float qm = g_qmax[b * CCH + c];
    float qi = 1.0f / g_qsum[b * CCH + c];
    __syncthreads();
    for (int r = 0; r < 64; r++) {
        int row = b * NNN + blockIdx.x * 64 + r;
        float qv = g_qkv[(size_t)row * 768 + c];
        qs[c] = expf(qv - qm) * qi;
        __syncthreads();
        float acc = 0.f;
        #pragma unroll
        for (int d = 0; d < 32; d++)
            acc += qs[h*32 + d] * ctxs[h*1024 + d*32 + e];
        g_attn[(size_t)row * CCH + c] = acc;
        __syncthreads();
    }
}

// ---------------- MixFFN dwconv 3x3 (1024 ch) + gelu ----------------
__global__ void dw_gelu_kernel(const float* __restrict__ dw_w, const float* __restrict__ dw_b) {
    int row = blockIdx.x;
    int b = row >> 12, n = row & 4095;
    int h = n >> 6, w = n & 63;
    for (int cc = 0; cc < 4; cc++) {
        int c = cc * 256 + threadIdx.x;
        float acc = dw_b[c];
        #pragma unroll
        for (int kh = 0; kh < 3; kh++) {
            int hh = h + kh - 1;
            if (hh < 0 || hh >= HHH) continue;
            #pragma unroll
            for (int kw = 0; kw < 3; kw++) {
                int ww = w + kw - 1;
                if (ww < 0 || ww >= WWW) continue;
                size_t src = ((size_t)((b<<12) | (hh<<6) | ww)) * HIDD + c;
                acc += g_h1[src] * dw_w[c*9 + kh*3 + kw];
            }
        }
        g_h2[(size_t)row * HIDD + c] = geluf(acc);
    }
}

// ---------------- CSDA channel stats ----------------
__global__ void avgmax_kernel() {
    int b = blockIdx.y, chunk = blockIdx.x, c = threadIdx.x;
    float s = 0.f, m = -1e30f;
    int base = b * NNN + chunk * 128;
    for (int r = 0; r < 128; r++) {
        float v = g_x[(size_t)(base + r) * CCH + c];
        s += v; m = fmaxf(m, v);
    }
    atomicAdd(&g_avg[b * CCH + c], s);
    atomicMaxF(&g_mx[b * CCH + c], m);
}

__global__ void ca_kernel(const float* __restrict__ w1, const float* __restrict__ w2) {
    int b = blockIdx.x, t = threadIdx.x;
    __shared__ float sav[CCH], smx[CCH], hid[32];
    sav[t] = g_avg[b * CCH + t] * (1.0f / NNN);
    smx[t] = g_mx[b * CCH + t];
    __syncthreads();
    if (t < 16) {
        float a = 0.f;
        for (int c = 0; c < CCH; c++) a += sav[c] * w1[t * CCH + c];
        hid[t] = fmaxf(a, 0.f);
    } else if (t < 32) {
        int j = t - 16;
        float a = 0.f;
        for (int c = 0; c < CCH; c++) a += smx[c] * w1[j * CCH + c];
        hid[16 + j] = fmaxf(a, 0.f);
    }
    __syncthreads();
    float a = 0.f;
    #pragma unroll
    for (int j = 0; j < 16; j++) a += (hid[j] + hid[16 + j]) * w2[t * 16 + j];
    g_cab[b * CCH + t] = sigmoidf_(a);
}

// ---------------- spatial map: mean/max over channels of x*ca ----------------
__global__ void smap_kernel() {
    int gid  = blockIdx.x * blockDim.x + threadIdx.x;
    int warp = gid >> 5, lane = gid & 31;
    if (warp >= MTOT) return;
    int b = warp >> 12;
    const float* row = g_x + (size_t)warp * CCH;
    const float* ca  = g_cab + b * CCH;
    float4 a = ((const float4*)row)[lane*2];
    float4 c4 = ((const float4*)ca)[lane*2];
    float4 b4 = ((const float4*)row)[lane*2+1];
    float4 d4 = ((const float4*)ca)[lane*2+1];
    float v0=a.x*c4.x, v1=a.y*c4.y, v2=a.z*c4.z, v3=a.w*c4.w;
    float v4=b4.x*d4.x, v5=b4.y*d4.y, v6=b4.z*d4.z, v7=b4.w*d4.w;
    float s = v0+v1+v2+v3+v4+v5+v6+v7;
    float m = fmaxf(fmaxf(fmaxf(v0,v1),fmaxf(v2,v3)), fmaxf(fmaxf(v4,v5),fmaxf(v6,v7)));
    #pragma unroll
    for (int off = 16; off; off >>= 1) {
        s += __shfl_xor_sync(0xffffffffu, s, off);
        m = fmaxf(m, __shfl_xor_sync(0xffffffffu, m, off));
    }
    if (lane == 0) {
        g_smean[warp] = s * (1.0f / CCH);
        g_smax[warp]  = m;
    }
}

// ---------------- spatial attention 7x7 conv + sigmoid ----------------
__global__ void sa_kernel(const float* __restrict__ sp_w, const float* __restrict__ sp_b) {
    int idx = blockIdx.x * blockDim.x + threadIdx.x;   // b*N+n
    int b = idx >> 12, n = idx & 4095;
    int h = n >> 6, w = n & 63;
    float acc = sp_b[0];
    for (int kh = 0; kh < 7; kh++) {
        int hh = h + kh - 3;
        if (hh < 0 || hh >= HHH) continue;
        for (int kw = 0; kw < 7; kw++) {
            int ww = w + kw - 3;
            if (ww < 0 || ww >= WWW) continue;
            int nn = b * NNN + hh * 64 + ww;
            acc += g_smean[nn] * sp_w[kh*7 + kw] + g_smax[nn] * sp_w[49 + kh*7 + kw];
        }
    }
    g_sa[idx] = sigmoidf_(acc);
}

// ---------------- final: out = x * ca * sa ----------------
__global__ void final_kernel(float* __restrict__ out) {
    int gid = blockIdx.x * blockDim.x + threadIdx.x;
    size_t idx4 = (size_t)gid * 4;
    int row = (int)(idx4 >> 8);
    int c   = (int)(idx4 & 255);
    int b   = row >> 12;
    float sa = g_sa[row];
    float4 ca = *(const float4*)(g_cab + b * CCH + c);
    float4 xv = *(const float4*)(g_x + idx4);
    float4 o;
    o.x = xv.x * ca.x * sa; o.y = xv.y * ca.y * sa;
    o.z = xv.z * ca.z * sa; o.w = xv.w * ca.w * sa;
    *(float4*)(out + idx4) = o;
}

// ---------------- launch ----------------
extern "C" void kernel_launch(void* const* d_in, const int* in_sizes, int n_in,
                              void* d_out, int out_size) {
    const float* x      = (const float*)d_in[0];
    const float* n1_g   = (const float*)d_in[3];
    const float* n1_b   = (const float*)d_in[4];
    const float* sr_w   = (const float*)d_in[5];
    const float* sr_b   = (const float*)d_in[6];
    const float* an_g   = (const float*)d_in[7];
    const float* an_b   = (const float*)d_in[8];
    const float* qkv_w  = (const float*)d_in[9];
    const float* proj_w = (const float*)d_in[10];
    const float* proj_b = (const float*)d_in[11];
    const float* n2_g   = (const float*)d_in[12];
    const float* n2_b   = (const float*)d_in[13];
    const float* fc1_w  = (const float*)d_in[14];
    const float* fc1_b  = (const float*)d_in[15];
    const float* dw_w   = (const float*)d_in[16];
    const float* dw_b   = (const float*)d_in[17];
    const float* fc2_w  = (const float*)d_in[18];
    const float* fc2_b  = (const float*)d_in[19];
    const float* ca_w1  = (const float*)d_in[20];
    const float* ca_w2  = (const float*)d_in[21];
    const float* sp_w   = (const float*)d_in[22];
    const float* sp_b   = (const float*)d_in[23];
    float* out = (float*)d_out;

    float *p_xn, *p_xa, *p_qkv, *p_attn, *p_x, *p_h1, *p_h2;
    cudaGetSymbolAddress((void**)&p_xn,   g_xn);
    cudaGetSymbolAddress((void**)&p_xa,   g_xa);
    cudaGetSymbolAddress((void**)&p_qkv,  g_qkv);
    cudaGetSymbolAddress((void**)&p_attn, g_attn);
    cudaGetSymbolAddress((void**)&p_x,    g_x);
    cudaGetSymbolAddress((void**)&p_h1,   g_h1);
    cudaGetSymbolAddress((void**)&p_h2,   g_h2);

    init_kernel<<<512, 256>>>();

    // --- attention branch ---
    ln_kernel<<<MTOT/8, 256>>>(x, n1_g, n1_b, p_xn);
    sr_an_kernel<<<MTOT, 256>>>(sr_w, sr_b, an_g, an_b);
    gemm_tf32<0><<<dim3(768/128, MTOT/128), 256>>>(p_xa, qkv_w, nullptr, nullptr, nullptr,
                                                   p_qkv, 768, 256);
    ksm_kernel<<<MTOT, 256>>>();
    qmax_kernel<<<dim3(32, BB), 256>>>();
    qsum_kernel<<<dim3(32, BB), 256>>>();
    ctx_kernel<<<dim3(16, BB*NHEAD), 1024>>>();
    attn_kernel<<<dim3(64, BB), 256>>>();
    gemm_tf32<2><<<dim3(256/128, MTOT/128), 256>>>(p_attn, proj_w, proj_b, p_xn, x,
                                                   p_x, 256, 256);

    // --- MixFFN ---
    ln_kernel<<<MTOT/8, 256>>>(p_x, n2_g, n2_b, p_xn);
    gemm_tf32<1><<<dim3(1024/128, MTOT/128), 256>>>(p_xn, fc1_w, fc1_b, nullptr, nullptr,
                                                    p_h1, 1024, 256);
    dw_gelu_kernel<<<MTOT, 256>>>(dw_w, dw_b);
    gemm_tf32<3><<<dim3(256/128, MTOT/128), 256>>>(p_h2, fc2_w, fc2_b, p_x, nullptr,
                                                   p_x, 256, 1024);

    // --- CSDA ---
    avgmax_kernel<<<dim3(32, BB), 256>>>();
    ca_kernel<<<BB, 256>>>(ca_w1, ca_w2);
    smap_kernel<<<MTOT/8, 256>>>();
    sa_kernel<<<MTOT/256, 256>>>(sp_w, sp_b);
    final_kernel<<<(MTOT*CCH/4)/256, 256>>>(out);
}

// round 3
// speedup vs baseline: 3.2191x; 1.8232x over previous
#include <cuda_runtime.h>
#include <cuda_bf16.h>
#include <math.h>

// ---------------- problem constants ----------------
#define BB    16
#define NNN   4096
#define CCH   256
#define HHH   64
#define WWW   64
#define HIDD  1024
#define NHEAD 8
#define HDIM  32
#define MTOT  (BB*NNN)          // 65536 rows

// ---------------- scratch (device globals; no allocs allowed) ----------------
__device__ float g_xn  [MTOT*CCH];            // ln1 out (fp32, reused for residuals)
__device__ float g_qkv [MTOT*3*CCH];          // qkv gemm out fp32
__device__ float g_x   [MTOT*CCH];            // trunk fp32
__device__ float g_h1  [MTOT*HIDD];           // fc1 out fp32
__device__ __nv_bfloat16 g_xabf  [MTOT*CCH];  // attn-branch gemm A
__device__ __nv_bfloat16 g_xnbf  [MTOT*CCH];  // ln2 out (fc1 A)
__device__ __nv_bfloat16 g_attnbf[MTOT*CCH];  // proj A
__device__ __nv_bfloat16 g_h2bf  [MTOT*HIDD]; // fc2 A
__device__ __nv_bfloat16 g_wqkv [3*CCH*CCH];
__device__ __nv_bfloat16 g_wproj[CCH*CCH];
__device__ __nv_bfloat16 g_wfc1 [HIDD*CCH];
__device__ __nv_bfloat16 g_wfc2 [CCH*HIDD];
__device__ float g_ctx [BB*NHEAD*HDIM*HDIM];
__device__ float g_qpm [BB*32*CCH];
__device__ float g_qps [BB*32*CCH];
__device__ float g_qmax[BB*CCH];
__device__ float g_qsum[BB*CCH];
__device__ float g_avg [BB*CCH];
__device__ float g_mx  [BB*CCH];
__device__ float g_cab [BB*CCH];
__device__ float g_smean[MTOT];
__device__ float g_smax [MTOT];
__device__ float g_sa   [MTOT];

// ---------------- helpers ----------------
__device__ __forceinline__ float geluf(float x) {
    return 0.5f * x * (1.0f + erff(x * 0.70710678118654752f));
}
__device__ __forceinline__ float sigmoidf_(float x) {
    return 1.0f / (1.0f + expf(-x));
}
__device__ __forceinline__ void atomicMaxF(float* addr, float v) {
    int* ai = (int*)addr;
    int old = *ai;
    while (__int_as_float(old) < v) {
        int prev = atomicCAS(ai, old, __float_as_int(v));
        if (prev == old) break;
        old = prev;
    }
}

// ---------------- init (per-call, deterministic reset) ----------------
__global__ void init_kernel() {
    int i = blockIdx.x * blockDim.x + threadIdx.x;
    if (i < BB*NHEAD*HDIM*HDIM) g_ctx[i] = 0.f;
    if (i < BB*CCH) {
        g_avg[i]  = 0.f;
        g_mx[i]   = -1e30f;
    }
}

// ---------------- fp32 -> bf16 weight convert ----------------
__global__ void cvt_kernel(const float* __restrict__ src, __nv_bfloat16* __restrict__ dst, int n) {
    int i = blockIdx.x * blockDim.x + threadIdx.x;
    if (i < n) dst[i] = __float2bfloat16(src[i]);
}

// ---------------- LayerNorm over C=256, one warp per row ----------------
template<bool BFOUT>
__global__ void ln_kernel(const float* __restrict__ in,
                          const float* __restrict__ gg,
                          const float* __restrict__ bb,
                          float* __restrict__ out,
                          __nv_bfloat16* __restrict__ outbf) {
    int gid  = blockIdx.x * blockDim.x + threadIdx.x;
    int warp = gid >> 5;
    int lane = gid & 31;
    if (warp >= MTOT) return;
    const float* row = in + (size_t)warp * CCH;
    float4 a = ((const float4*)row)[lane*2];
    float4 b = ((const float4*)row)[lane*2+1];
    float s1 = a.x+a.y+a.z+a.w + b.x+b.y+b.z+b.w;
    float s2 = a.x*a.x+a.y*a.y+a.z*a.z+a.w*a.w + b.x*b.x+b.y*b.y+b.z*b.z+b.w*b.w;
    #pragma unroll
    for (int off = 16; off; off >>= 1) {
        s1 += __shfl_xor_sync(0xffffffffu, s1, off);
        s2 += __shfl_xor_sync(0xffffffffu, s2, off);
    }
    float mean = s1 * (1.0f/CCH);
    float var  = s2 * (1.0f/CCH) - mean*mean;
    float rstd = rsqrtf(var + 1e-5f);
    float4 g0 = ((const float4*)gg)[lane*2];
    float4 g1 = ((const float4*)gg)[lane*2+1];
    float4 b0 = ((const float4*)bb)[lane*2];
    float4 b1 = ((const float4*)bb)[lane*2+1];
    float4 o0, o1;
    o0.x=(a.x-mean)*rstd*g0.x+b0.x; o0.y=(a.y-mean)*rstd*g0.y+b0.y;
    o0.z=(a.z-mean)*rstd*g0.z+b0.z; o0.w=(a.w-mean)*rstd*g0.w+b0.w;
    o1.x=(b.x-mean)*rstd*g1.x+b1.x; o1.y=(b.y-mean)*rstd*g1.y+b1.y;
    o1.z=(b.z-mean)*rstd*g1.z+b1.z; o1.w=(b.w-mean)*rstd*g1.w+b1.w;
    if (BFOUT) {
        union { __nv_bfloat162 h[4]; uint4 u; } pk;
        pk.h[0]=__float22bfloat162_rn(make_float2(o0.x,o0.y));
        pk.h[1]=__float22bfloat162_rn(make_float2(o0.z,o0.w));
        pk.h[2]=__float22bfloat162_rn(make_float2(o1.x,o1.y));
        pk.h[3]=__float22bfloat162_rn(make_float2(o1.z,o1.w));
        ((uint4*)(outbf + (size_t)warp*CCH))[lane] = pk.u;
    } else {
        float* orow = out + (size_t)warp * CCH;
        ((float4*)orow)[lane*2]   = o0;
        ((float4*)orow)[lane*2+1] = o1;
    }
}

// ---------------- sr dwconv 3x3 + LN + gelu + residual -> xa (bf16) ----------
__global__ void sr_an_kernel(const float* __restrict__ sr_w, const float* __restrict__ sr_b,
                             const float* __restrict__ an_g, const float* __restrict__ an_b) {
    int row = blockIdx.x;                 // b*N + n
    int b = row >> 12, n = row & 4095;
    int h = n >> 6, w = n & 63;
    int c = threadIdx.x;
    float acc = sr_b[c];
    #pragma unroll
    for (int kh = 0; kh < 3; kh++) {
        int hh = h + kh - 1;
        if (hh < 0 || hh >= HHH) continue;
        #pragma unroll
        for (int kw = 0; kw < 3; kw++) {
            int ww = w + kw - 1;
            if (ww < 0 || ww >= WWW) continue;
            size_t src = ((size_t)((b<<12) | (hh<<6) | ww) << 8) + c;
            acc += g_xn[src] * sr_w[c*9 + kh*3 + kw];
        }
    }
    float s1 = acc, s2 = acc*acc;
    #pragma unroll
    for (int off = 16; off; off >>= 1) {
        s1 += __shfl_xor_sync(0xffffffffu, s1, off);
        s2 += __shfl_xor_sync(0xffffffffu, s2, off);
    }
    __shared__ float r1[8], r2[8];
    int lane = c & 31, wid = c >> 5;
    if (lane == 0) { r1[wid] = s1; r2[wid] = s2; }
    __syncthreads();
    if (c == 0) {
        float a = 0.f, q = 0.f;
        #pragma unroll
        for (int i = 0; i < 8; i++) { a += r1[i]; q += r2[i]; }
        float mean = a * (1.0f/CCH);
        float var  = q * (1.0f/CCH) - mean*mean;
        r1[0] = mean; r2[0] = rsqrtf(var + 1e-5f);
    }
    __syncthreads();
    float mean = r1[0], rstd = r2[0];
    float yn = (acc - mean) * rstd * an_g[c] + an_b[c];
    size_t idx = ((size_t)row << 8) + c;
    g_xabf[idx] = __float2bfloat16(g_xn[idx] + geluf(yn));
}

// ---------------- bf16 tensor-core GEMM ----------------
// out[M,Nout] fp32 = A[M,K]bf16 @ Wt[Nout,K]bf16^T (+epi)
// EPI: 0 none, 1 +bias, 2 +bias+add1+add2, 3 +bias+add1
#define SAST 40   // smem row stride in bf16 units (80B, conflict-free for LDSM)

__device__ __forceinline__ void ldsm4(unsigned& r0, unsigned& r1, unsigned& r2, unsigned& r3,
                                      const __nv_bfloat16* p) {
    unsigned addr = (unsigned)__cvta_generic_to_shared(p);
    asm volatile("ldmatrix.sync.aligned.m8n8.x4.shared.b16 {%0,%1,%2,%3}, [%4];"
                 : "=r"(r0), "=r"(r1), "=r"(r2), "=r"(r3) : "r"(addr));
}
__device__ __forceinline__ void mma_bf16(float* d, const unsigned* a, const unsigned* b) {
    asm volatile(
        "mma.sync.aligned.m16n8k16.row.col.f32.bf16.bf16.f32 "
        "{%0,%1,%2,%3}, {%4,%5,%6,%7}, {%8,%9}, {%0,%1,%2,%3};"
        : "+f"(d[0]), "+f"(d[1]), "+f"(d[2]), "+f"(d[3])
        : "r"(a[0]), "r"(a[1]), "r"(a[2]), "r"(a[3]), "r"(b[0]), "r"(b[1]));
}
__device__ __forceinline__ void cpasync16(__nv_bfloat16* dst, const __nv_bfloat16* src) {
    unsigned saddr = (unsigned)__cvta_generic_to_shared(dst);
    asm volatile("cp.async.ca.shared.global [%0], [%1], 16;" :: "r"(saddr), "l"(src));
}

template<int EPI>
__global__ void __launch_bounds__(256)
gemm_bf16(const __nv_bfloat16* __restrict__ A, const __nv_bfloat16* __restrict__ Wt,
          const float* __restrict__ bias,
          const float* __restrict__ add1, const float* __restrict__ add2,
          float* __restrict__ out, int Nout, int K) {
    __shared__ __nv_bfloat16 As[2][128*SAST];
    __shared__ __nv_bfloat16 Bs[2][128*SAST];

    const int t = threadIdx.x;
    const int warp = t >> 5, lane = t & 31;
    const int wm = (warp & 3) * 32;
    const int wn = (warp >> 2) * 64;
    const int grp = lane >> 2;
    const int kq  = lane & 3;
    const int row0 = blockIdx.y * 128;
    const int col0 = blockIdx.x * 128;

    // chunk mapping for cp.async: 512 16B chunks per matrix per tile, 2 per thread
    const int c0r = t >> 2,        c0s = (t & 3) * 8;         // chunk t
    const int c1r = (t + 256) >> 2, c1s = ((t + 256) & 3) * 8; // chunk t+256

    // lane-dependent LDSM source offsets (within current k16 sub-block)
    const int a_row = (lane & 7) + ((lane >> 3) & 1) * 8;
    const int a_kof = (lane >> 4) * 8;
    const int b_row = (lane & 7) + (lane >> 4) * 8;
    const int b_kof = ((lane >> 3) & 1) * 8;

    float acc[2][8][4];
    #pragma unroll
    for (int i = 0; i < 2; i++)
        #pragma unroll
        for (int j = 0; j < 8; j++)
            #pragma unroll
            for (int q = 0; q < 4; q++) acc[i][j][q] = 0.f;

    const int ntiles = K >> 5;   // BK=32

    // prologue: tile 0
    cpasync16(&As[0][c0r*SAST + c0s], A  + (size_t)(row0 + c0r) * K + c0s);
    cpasync16(&As[0][c1r*SAST + c1s], A  + (size_t)(row0 + c1r) * K + c1s);
    cpasync16(&Bs[0][c0r*SAST + c0s], Wt + (size_t)(col0 + c0r) * K + c0s);
    cpasync16(&Bs[0][c1r*SAST + c1s], Wt + (size_t)(col0 + c1r) * K + c1s);
    asm volatile("cp.async.commit_group;");

    int buf = 0;
    for (int kt = 0; kt < ntiles; kt++) {
        __syncthreads();   // previous compute done; safe to overwrite buf^1
        if (kt + 1 < ntiles) {
            int nb = buf ^ 1;
            int kg = (kt + 1) << 5;
            cpasync16(&As[nb][c0r*SAST + c0s], A  + (size_t)(row0 + c0r) * K + kg + c0s);
            cpasync16(&As[nb][c1r*SAST + c1s], A  + (size_t)(row0 + c1r) * K + kg + c1s);
            cpasync16(&Bs[nb][c0r*SAST + c0s], Wt + (size_t)(col0 + c0r) * K + kg + c0s);
            cpasync16(&Bs[nb][c1r*SAST + c1s], Wt + (size_t)(col0 + c1r) * K + kg + c1s);
            asm volatile("cp.async.commit_group;");
            asm volatile("cp.async.wait_group 1;");
        } else {
            asm volatile("cp.async.wait_group 0;");
        }
        __syncthreads();   // tile kt visible

        #pragma unroll
        for (int s = 0; s < 2; s++) {
            const int kb = s * 16;
            unsigned af[2][4], bf[4][4];
            #pragma unroll
            for (int i = 0; i < 2; i++)
                ldsm4(af[i][0], af[i][1], af[i][2], af[i][3],
                      &As[buf][(wm + i*16 + a_row)*SAST + kb + a_kof]);
            #pragma unroll
            for (int j2 = 0; j2 < 4; j2++)
                ldsm4(bf[j2][0], bf[j2][1], bf[j2][2], bf[j2][3],
                      &Bs[buf][(wn + j2*16 + b_row)*SAST + kb + b_kof]);
            #pragma unroll
            for (int i = 0; i < 2; i++)
                #pragma unroll
                for (int j = 0; j < 8; j++)
                    mma_bf16(acc[i][j], af[i], &bf[j >> 1][(j & 1) * 2]);
        }
        buf ^= 1;
    }

    // epilogue (c-frag: c0,c1 -> (grp, 2kq/2kq+1); c2,c3 -> grp+8)
    #pragma unroll
    for (int i = 0; i < 2; i++) {
        int r_lo = row0 + wm + i * 16 + grp;
        #pragma unroll
        for (int j = 0; j < 8; j++) {
            int cidx = col0 + wn + j * 8 + kq * 2;
            float bv0 = 0.f, bv1 = 0.f;
            if (EPI >= 1) { bv0 = bias[cidx]; bv1 = bias[cidx + 1]; }
            size_t o_lo = (size_t)r_lo * Nout + cidx;
            size_t o_hi = o_lo + (size_t)8 * Nout;
            float v0 = acc[i][j][0] + bv0;
            float v1 = acc[i][j][1] + bv1;
            float v2 = acc[i][j][2] + bv0;
            float v3 = acc[i][j][3] + bv1;
            if (EPI == 2) {
                v0 += add1[o_lo] + add2[o_lo];
                v1 += add1[o_lo + 1] + add2[o_lo + 1];
                v2 += add1[o_hi] + add2[o_hi];
                v3 += add1[o_hi + 1] + add2[o_hi + 1];
            }
            if (EPI == 3) {
                v0 += add1[o_lo];     v1 += add1[o_lo + 1];
                v2 += add1[o_hi];     v3 += add1[o_hi + 1];
            }
            *(float2*)(out + o_lo) = make_float2(v0, v1);
            *(float2*)(out + o_hi) = make_float2(v2, v3);
        }
    }
}

// ---------------- q stats: online per-chunk max/sumexp + reduce ----------------
__global__ void qstats_kernel() {
    int b = blockIdx.y, chunk = blockIdx.x, c = threadIdx.x;
    float m = -1e30f, s = 0.f;
    int base = b * NNN + chunk * 128;
    for (int r = 0; r < 128; r++) {
        float v = g_qkv[(size_t)(base + r) * 768 + c];
        if (v > m) { s = s * expf(m - v) + 1.f; m = v; }
        else s += expf(v - m);
    }
    g_qpm[(b*32 + chunk)*CCH + c] = m;
    g_qps[(b*32 + chunk)*CCH + c] = s;
}
__global__ void qfinal_kernel() {
    int b = blockIdx.x, c = threadIdx.x;
    float m = -1e30f;
    for (int k = 0; k < 32; k++) m = fmaxf(m, g_qpm[(b*32 + k)*CCH + c]);
    float s = 0.f;
    for (int k = 0; k < 32; k++) s += g_qps[(b*32 + k)*CCH + c] * expf(g_qpm[(b*32 + k)*CCH + c] - m);
    g_qmax[b*CCH + c] = m;
    g_qsum[b*CCH + c] = s;
}

// ---------------- ctx = softmax_d(k)^T v  (fused k-softmax) ----------------
__global__ void ctx_kernel() {
    int chunk = blockIdx.x;           // 0..7 : 512 rows each
    int bh = blockIdx.y;              // b*8+h
    int b = bh >> 3, h = bh & 7;
    int w = threadIdx.x >> 5, lane = threadIdx.x & 31;
    __shared__ float ks[32][33], vs[32][33];
    float acc[4] = {0.f, 0.f, 0.f, 0.f};
    int base = b * NNN + chunk * 512;
    for (int tile = 0; tile < 16; tile++) {
        #pragma unroll
        for (int rr = 0; rr < 4; rr++) {
            int rl = w * 4 + rr;
            size_t row = (size_t)(base + tile * 32 + rl);
            float kv = g_qkv[row * 768 + 256 + h * 32 + lane];
            float mx = kv;
            #pragma unroll
            for (int off = 16; off; off >>= 1) mx = fmaxf(mx, __shfl_xor_sync(0xffffffffu, mx, off));
            float e = expf(kv - mx);
            float ss = e;
            #pragma unroll
            for (int off = 16; off; off >>= 1) ss += __shfl_xor_sync(0xffffffffu, ss, off);
            ks[rl][lane] = e / ss;
            vs[rl][lane] = g_qkv[row * 768 + 512 + h * 32 + lane];
        }
        __syncthreads();
        for (int r = 0; r < 32; r++) {
            float vv = vs[r][lane];
            #pragma unroll
            for (int i = 0; i < 4; i++) acc[i] += ks[r][w*4 + i] * vv;
        }
        __syncthreads();
    }
    #pragma unroll
    for (int i = 0; i < 4; i++)
        atomicAdd(&g_ctx[bh * 1024 + (w*4 + i) * 32 + lane], acc[i]);
}

// ---------------- attn = softmax_N(q) @ ctx  (warp per head, bf16 out) -------
__global__ void attn_kernel() {
    int blk = blockIdx.x;             // 1024 blocks, 64 rows each
    int w = threadIdx.x >> 5, lane = threadIdx.x & 31;
    int b = blk >> 6;
    int h = w;
    float c[32];
    const float* cp = g_ctx + ((size_t)((b << 3) + h)) * 1024 + lane;
    #pragma unroll
    for (int d = 0; d < 32; d++) c[d] = cp[d * 32];
    float qm = g_qmax[b*CCH + h*32 + lane];
    float qi = 1.0f / g_qsum[b*CCH + h*32 + lane];
    int row0 = blk * 64;
    for (int r = 0; r < 64; r++) {
        size_t row = (size_t)(row0 + r);
        float qv = g_qkv[row * 768 + h*32 + lane];
        float qe = expf(qv - qm) * qi;
        float a0 = 0.f, a1 = 0.f;
        #pragma unroll
        for (int d = 0; d < 32; d += 2) {
            a0 += __shfl_sync(0xffffffffu, qe, d)     * c[d];
            a1 += __shfl_sync(0xffffffffu, qe, d + 1) * c[d + 1];
        }
        g_attnbf[row * CCH + h*32 + lane] = __float2bfloat16(a0 + a1);
    }
}

// ---------------- MixFFN dwconv 3x3 + gelu (tiled, bf16 out) ----------------
__global__ void __launch_bounds__(256) dw_kernel(const float* __restrict__ dw_w,
                                                 const float* __restrict__ dw_b) {
    __shared__ float s[10*10*64];
    int tile = blockIdx.x;            // 0..63 : 8x8 grid of 8x8 tiles
    int cc = blockIdx.y;              // 0..15 : 64-ch chunks
    int b = blockIdx.z;
    int th0 = (tile >> 3) * 8, tw0 = (tile & 7) * 8;
    int t = threadIdx.x;
    int c0 = cc * 64;
    for (int l = t; l < 6400; l += 256) {
        int lh = l / 640, rem = l % 640, lw = rem / 64, lc = rem % 64;
        int gh = th0 + lh - 1, gw = tw0 + lw - 1;
        float v = 0.f;
        if (gh >= 0 && gh < HHH && gw >= 0 && gw < WWW)
            v = g_h1[(size_t)((b << 12) + (gh << 6) + gw) * HIDD + c0 + lc];
        s[l] = v;
    }
    __syncthreads();
    int oc = t & 63;
    int cg = c0 + oc;
    float wt[9];
    #pragma unroll
    for (int k = 0; k < 9; k++) wt[k] = dw_w[cg*9 + k];
    float bias = dw_b[cg];
    for (int o = t; o < 4096; o += 256) {
        int oh = o >> 9, ow = (o >> 6) & 7;
        float acc = bias;
        #pragma unroll
        for (int kh = 0; kh < 3; kh++)
            #pragma unroll
            for (int kw = 0; kw < 3; kw++)
                acc += s[(oh + kh)*640 + (ow + kw)*64 + oc] * wt[kh*3 + kw];
        size_t row = (size_t)((b << 12) + ((th0 + oh) << 6) + (tw0 + ow));
        g_h2bf[row * HIDD + cg] = __float2bfloat16(geluf(acc));
    }
}

// ---------------- CSDA channel stats ----------------
__global__ void avgmax_kernel() {
    int b = blockIdx.y, chunk = blockIdx.x, c = threadIdx.x;
    float s = 0.f, m = -1e30f;
    int base = b * NNN + chunk * 128;
    for (int r = 0; r < 128; r++) {
        float v = g_x[(size_t)(base + r) * CCH + c];
        s += v; m = fmaxf(m, v);
    }
    atomicAdd(&g_avg[b * CCH + c], s);
    atomicMaxF(&g_mx[b * CCH + c], m);
}

__global__ void ca_kernel(const float* __restrict__ w1, const float* __restrict__ w2) {
    int b = blockIdx.x, t = threadIdx.x;
    __shared__ float sav[CCH], smx[CCH], hid[32];
    sav[t] = g_avg[b * CCH + t] * (1.0f / NNN);
    smx[t] = g_mx[b * CCH + t];
    __syncthreads();
    if (t < 16) {
        float a = 0.f;
        for (int c = 0; c < CCH; c++) a += sav[c] * w1[t * CCH + c];
        hid[t] = fmaxf(a, 0.f);
    } else if (t < 32) {
        int j = t - 16;
        float a = 0.f;
        for (int c = 0; c < CCH; c++) a += smx[c] * w1[j * CCH + c];
        hid[16 + j] = fmaxf(a, 0.f);
    }
    __syncthreads();
    float a = 0.f;
    #pragma unroll
    for (int j = 0; j < 16; j++) a += (hid[j] + hid[16 + j]) * w2[t * 16 + j];
    g_cab[b * CCH + t] = sigmoidf_(a);
}

// ---------------- spatial map: mean/max over channels of x*ca ----------------
__global__ void smap_kernel() {
    int gid  = blockIdx.x * blockDim.x + threadIdx.x;
    int warp = gid >> 5, lane = gid & 31;
    if (warp >= MTOT) return;
    int b = warp >> 12;
    const float* row = g_x + (size_t)warp * CCH;
    const float* ca  = g_cab + b * CCH;
    float4 a = ((const float4*)row)[lane*2];
    float4 c4 = ((const float4*)ca)[lane*2];
    float4 b4 = ((const float4*)row)[lane*2+1];
    float4 d4 = ((const float4*)ca)[lane*2+1];
    float v0=a.x*c4.x, v1=a.y*c4.y, v2=a.z*c4.z, v3=a.w*c4.w;
    float v4=b4.x*d4.x, v5=b4.y*d4.y, v6=b4.z*d4.z, v7=b4.w*d4.w;
    float s = v0+v1+v2+v3+v4+v5+v6+v7;
    float m = fmaxf(fmaxf(fmaxf(v0,v1),fmaxf(v2,v3)), fmaxf(fmaxf(v4,v5),fmaxf(v6,v7)));
    #pragma unroll
    for (int off = 16; off; off >>= 1) {
        s += __shfl_xor_sync(0xffffffffu, s, off);
        m = fmaxf(m, __shfl_xor_sync(0xffffffffu, m, off));
    }
    if (lane == 0) {
        g_smean[warp] = s * (1.0f / CCH);
        g_smax[warp]  = m;
    }
}

// ---------------- spatial attention 7x7 conv + sigmoid ----------------
__global__ void sa_kernel(const float* __restrict__ sp_w, const float* __restrict__ sp_b) {
    int idx = blockIdx.x * blockDim.x + threadIdx.x;   // b*N+n
    int b = idx >> 12, n = idx & 4095;
    int h = n >> 6, w = n & 63;
    float acc = sp_b[0];
    for (int kh = 0; kh < 7; kh++) {
        int hh = h + kh - 3;
        if (hh < 0 || hh >= HHH) continue;
        for (int kw = 0; kw < 7; kw++) {
            int ww = w + kw - 3;
            if (ww < 0 || ww >= WWW) continue;
            int nn = b * NNN + hh * 64 + ww;
            acc += g_smean[nn] * sp_w[kh*7 + kw] + g_smax[nn] * sp_w[49 + kh*7 + kw];
        }
    }
    g_sa[idx] = sigmoidf_(acc);
}

// ---------------- final: out = x * ca * sa ----------------
__global__ void final_kernel(float* __restrict__ out) {
    int gid = blockIdx.x * blockDim.x + threadIdx.x;
    size_t idx4 = (size_t)gid * 4;
    int row = (int)(idx4 >> 8);
    int c   = (int)(idx4 & 255);
    int b   = row >> 12;
    float sa = g_sa[row];
    float4 ca = *(const float4*)(g_cab + b * CCH + c);
    float4 xv = *(const float4*)(g_x + idx4);
    float4 o;
    o.x = xv.x * ca.x * sa; o.y = xv.y * ca.y * sa;
    o.z = xv.z * ca.z * sa; o.w = xv.w * ca.w * sa;
    *(float4*)(out + idx4) = o;
}

// ---------------- launch ----------------
extern "C" void kernel_launch(void* const* d_in, const int* in_sizes, int n_in,
                              void* d_out, int out_size) {
    const float* x      = (const float*)d_in[0];
    const float* n1_g   = (const float*)d_in[3];
    const float* n1_b   = (const float*)d_in[4];
    const float* sr_w   = (const float*)d_in[5];
    const float* sr_b   = (const float*)d_in[6];
    const float* an_g   = (const float*)d_in[7];
    const float* an_b   = (const float*)d_in[8];
    const float* qkv_w  = (const float*)d_in[9];
    const float* proj_w = (const float*)d_in[10];
    const float* proj_b = (const float*)d_in[11];
    const float* n2_g   = (const float*)d_in[12];
    const float* n2_b   = (const float*)d_in[13];
    const float* fc1_w  = (const float*)d_in[14];
    const float* fc1_b  = (const float*)d_in[15];
    const float* dw_w   = (const float*)d_in[16];
    const float* dw_b   = (const float*)d_in[17];
    const float* fc2_w  = (const float*)d_in[18];
    const float* fc2_b  = (const float*)d_in[19];
    const float* ca_w1  = (const float*)d_in[20];
    const float* ca_w2  = (const float*)d_in[21];
    const float* sp_w   = (const float*)d_in[22];
    const float* sp_b   = (const float*)d_in[23];
    float* out = (float*)d_out;

    float *p_xn, *p_qkv, *p_x, *p_h1;
    __nv_bfloat16 *p_xabf, *p_xnbf, *p_attnbf, *p_h2bf, *p_wqkv, *p_wproj, *p_wfc1, *p_wfc2;
    cudaGetSymbolAddress((void**)&p_xn,    g_xn);
    cudaGetSymbolAddress((void**)&p_qkv,   g_qkv);
    cudaGetSymbolAddress((void**)&p_x,     g_x);
    cudaGetSymbolAddress((void**)&p_h1,    g_h1);
    cudaGetSymbolAddress((void**)&p_xabf,  g_xabf);
    cudaGetSymbolAddress((void**)&p_xnbf,  g_xnbf);
    cudaGetSymbolAddress((void**)&p_attnbf,g_attnbf);
    cudaGetSymbolAddress((void**)&p_h2bf,  g_h2bf);
    cudaGetSymbolAddress((void**)&p_wqkv,  g_wqkv);
    cudaGetSymbolAddress((void**)&p_wproj, g_wproj);
    cudaGetSymbolAddress((void**)&p_wfc1,  g_wfc1);
    cudaGetSymbolAddress((void**)&p_wfc2,  g_wfc2);

    init_kernel<<<512, 256>>>();
    cvt_kernel<<<(3*CCH*CCH+255)/256, 256>>>(qkv_w,  p_wqkv,  3*CCH*CCH);
    cvt_kernel<<<(CCH*CCH+255)/256, 256>>>(proj_w, p_wproj, CCH*CCH);
    cvt_kernel<<<(HIDD*CCH+255)/256, 256>>>(fc1_w,  p_wfc1,  HIDD*CCH);
    cvt_kernel<<<(CCH*HIDD+255)/256, 256>>>(fc2_w,  p_wfc2,  CCH*HIDD);

    // --- attention branch ---
    ln_kernel<false><<<MTOT/8, 256>>>(x, n1_g, n1_b, p_xn, nullptr);
    sr_an_kernel<<<MTOT, 256>>>(sr_w, sr_b, an_g, an_b);
    gemm_bf16<0><<<dim3(768/128, MTOT/128), 256>>>(p_xabf, p_wqkv, nullptr, nullptr, nullptr,
                                                   p_qkv, 768, 256);
    qstats_kernel<<<dim3(32, BB), 256>>>();
    qfinal_kernel<<<BB, 256>>>();
    ctx_kernel<<<dim3(8, BB*NHEAD), 256>>>();
    attn_kernel<<<MTOT/64, 256>>>();
    gemm_bf16<2><<<dim3(256/128, MTOT/128), 256>>>(p_attnbf, p_wproj, proj_b, p_xn, x,
                                                   p_x, 256, 256);

    // --- MixFFN ---
    ln_kernel<true><<<MTOT/8, 256>>>(p_x, n2_g, n2_b, nullptr, p_xnbf);
    gemm_bf16<1><<<dim3(1024/128, MTOT/128), 256>>>(p_xnbf, p_wfc1, fc1_b, nullptr, nullptr,
                                                    p_h1, 1024, 256);
    dw_kernel<<<dim3(64, 16, 16), 256>>>(dw_w, dw_b);
    gemm_bf16<3><<<dim3(256/128, MTOT/128), 256>>>(p_h2bf, p_wfc2, fc2_b, p_x, nullptr,
                                                   p_x, 256, 1024);

    // --- CSDA ---
    avgmax_kernel<<<dim3(32, BB), 256>>>();
    ca_kernel<<<BB, 256>>>(ca_w1, ca_w2);
    smap_kernel<<<MTOT/8, 256>>>();
    sa_kernel<<<MTOT/256, 256>>>(sp_w, sp_b);
    final_kernel<<<(MTOT*CCH/4)/256, 256>>>(out);
}

// round 5
// speedup vs baseline: 3.3330x; 1.0354x over previous
#include <cuda_runtime.h>
#include <cuda_bf16.h>
#include <math.h>
#include <stdint.h>

// ---------------- problem constants ----------------
#define BB    16
#define NNN   4096
#define CCH   256
#define HHH   64
#define WWW   64
#define HIDD  1024
#define NHEAD 8
#define HDIM  32
#define MTOT  (BB*NNN)          // 65536 rows

// ---------------- scratch (device globals; no allocs allowed) ----------------
__device__ float g_xn  [MTOT*CCH];            // ln1 out (fp32, reused for residuals)
__device__ float g_q   [MTOT*CCH];            // q (fp32 for softmax precision)
__device__ float g_x   [MTOT*CCH];            // trunk fp32
__device__ __nv_bfloat16 g_kbf   [MTOT*CCH];  // k bf16
__device__ __nv_bfloat16 g_vbf   [MTOT*CCH];  // v bf16
__device__ __nv_bfloat16 g_h1bf  [MTOT*HIDD]; // fc1 out bf16
__device__ __nv_bfloat16 g_xabf  [MTOT*CCH];  // attn-branch gemm A
__device__ __nv_bfloat16 g_xnbf  [MTOT*CCH];  // ln2 out (fc1 A)
__device__ __nv_bfloat16 g_attnbf[MTOT*CCH];  // proj A
__device__ __nv_bfloat16 g_h2bf  [MTOT*HIDD]; // fc2 A
__device__ __nv_bfloat16 g_wqkv [3*CCH*CCH];
__device__ __nv_bfloat16 g_wproj[CCH*CCH];
__device__ __nv_bfloat16 g_wfc1 [HIDD*CCH];
__device__ __nv_bfloat16 g_wfc2 [CCH*HIDD];
__device__ float g_ctx [BB*NHEAD*HDIM*HDIM];
__device__ float g_qpm [BB*32*CCH];
__device__ float g_qps [BB*32*CCH];
__device__ float g_qmax[BB*CCH];
__device__ float g_qsum[BB*CCH];
__device__ float g_avg [BB*CCH];
__device__ float g_mx  [BB*CCH];
__device__ float g_cab [BB*CCH];
__device__ float g_smean[MTOT];
__device__ float g_smax [MTOT];
__device__ float g_sa   [MTOT];

// ---------------- helpers ----------------
__device__ __forceinline__ float geluf(float x) {
    return 0.5f * x * (1.0f + erff(x * 0.70710678118654752f));
}
__device__ __forceinline__ float sigmoidf_(float x) {
    return 1.0f / (1.0f + expf(-x));
}
__device__ __forceinline__ void atomicMaxF(float* addr, float v) {
    int* ai = (int*)addr;
    int old = *ai;
    while (__int_as_float(old) < v) {
        int prev = atomicCAS(ai, old, __float_as_int(v));
        if (prev == old) break;
        old = prev;
    }
}

// ---------------- init (per-call, deterministic reset) ----------------
__global__ void init_kernel() {
    int i = blockIdx.x * blockDim.x + threadIdx.x;
    if (i < BB*NHEAD*HDIM*HDIM) g_ctx[i] = 0.f;
    if (i < BB*CCH) {
        g_avg[i]  = 0.f;
        g_mx[i]   = -1e30f;
    }
}

// ---------------- fp32 -> bf16 weight convert ----------------
__global__ void cvt_kernel(const float* __restrict__ src, __nv_bfloat16* __restrict__ dst, int n) {
    int i = blockIdx.x * blockDim.x + threadIdx.x;
    if (i < n) dst[i] = __float2bfloat16(src[i]);
}

// ---------------- LayerNorm over C=256, one warp per row ----------------
template<bool BFOUT>
__global__ void ln_kernel(const float* __restrict__ in,
                          const float* __restrict__ gg,
                          const float* __restrict__ bb,
                          float* __restrict__ out,
                          __nv_bfloat16* __restrict__ outbf) {
    int gid  = blockIdx.x * blockDim.x + threadIdx.x;
    int warp = gid >> 5;
    int lane = gid & 31;
    if (warp >= MTOT) return;
    const float* row = in + (size_t)warp * CCH;
    float4 a = ((const float4*)row)[lane*2];
    float4 b = ((const float4*)row)[lane*2+1];
    float s1 = a.x+a.y+a.z+a.w + b.x+b.y+b.z+b.w;
    float s2 = a.x*a.x+a.y*a.y+a.z*a.z+a.w*a.w + b.x*b.x+b.y*b.y+b.z*b.z+b.w*b.w;
    #pragma unroll
    for (int off = 16; off; off >>= 1) {
        s1 += __shfl_xor_sync(0xffffffffu, s1, off);
        s2 += __shfl_xor_sync(0xffffffffu, s2, off);
    }
    float mean = s1 * (1.0f/CCH);
    float var  = s2 * (1.0f/CCH) - mean*mean;
    float rstd = rsqrtf(var + 1e-5f);
    float4 g0 = ((const float4*)gg)[lane*2];
    float4 g1 = ((const float4*)gg)[lane*2+1];
    float4 b0 = ((const float4*)bb)[lane*2];
    float4 b1 = ((const float4*)bb)[lane*2+1];
    float4 o0, o1;
    o0.x=(a.x-mean)*rstd*g0.x+b0.x; o0.y=(a.y-mean)*rstd*g0.y+b0.y;
    o0.z=(a.z-mean)*rstd*g0.z+b0.z; o0.w=(a.w-mean)*rstd*g0.w+b0.w;
    o1.x=(b.x-mean)*rstd*g1.x+b1.x; o1.y=(b.y-mean)*rstd*g1.y+b1.y;
    o1.z=(b.z-mean)*rstd*g1.z+b1.z; o1.w=(b.w-mean)*rstd*g1.w+b1.w;
    if (BFOUT) {
        union { __nv_bfloat162 h[4]; uint4 u; } pk;
        pk.h[0]=__float22bfloat162_rn(make_float2(o0.x,o0.y));
        pk.h[1]=__float22bfloat162_rn(make_float2(o0.z,o0.w));
        pk.h[2]=__float22bfloat162_rn(make_float2(o1.x,o1.y));
        pk.h[3]=__float22bfloat162_rn(make_float2(o1.z,o1.w));
        ((uint4*)(outbf + (size_t)warp*CCH))[lane] = pk.u;
    } else {
        float* orow = out + (size_t)warp * CCH;
        ((float4*)orow)[lane*2]   = o0;
        ((float4*)orow)[lane*2+1] = o1;
    }
}

// ---------------- sr dwconv 3x3 + LN + gelu + residual -> xa (bf16) ----------
__global__ void sr_an_kernel(const float* __restrict__ sr_w, const float* __restrict__ sr_b,
                             const float* __restrict__ an_g, const float* __restrict__ an_b) {
    int row = blockIdx.x;                 // b*N + n
    int b = row >> 12, n = row & 4095;
    int h = n >> 6, w = n & 63;
    int c = threadIdx.x;
    float acc = sr_b[c];
    #pragma unroll
    for (int kh = 0; kh < 3; kh++) {
        int hh = h + kh - 1;
        if (hh < 0 || hh >= HHH) continue;
        #pragma unroll
        for (int kw = 0; kw < 3; kw++) {
            int ww = w + kw - 1;
            if (ww < 0 || ww >= WWW) continue;
            size_t src = ((size_t)((b<<12) | (hh<<6) | ww) << 8) + c;
            acc += g_xn[src] * sr_w[c*9 + kh*3 + kw];
        }
    }
    float s1 = acc, s2 = acc*acc;
    #pragma unroll
    for (int off = 16; off; off >>= 1) {
        s1 += __shfl_xor_sync(0xffffffffu, s1, off);
        s2 += __shfl_xor_sync(0xffffffffu, s2, off);
    }
    __shared__ float r1[8], r2[8];
    int lane = c & 31, wid = c >> 5;
    if (lane == 0) { r1[wid] = s1; r2[wid] = s2; }
    __syncthreads();
    if (c == 0) {
        float a = 0.f, q = 0.f;
        #pragma unroll
        for (int i = 0; i < 8; i++) { a += r1[i]; q += r2[i]; }
        float mean = a * (1.0f/CCH);
        float var  = q * (1.0f/CCH) - mean*mean;
        r1[0] = mean; r2[0] = rsqrtf(var + 1e-5f);
    }
    __syncthreads();
    float mean = r1[0], rstd = r2[0];
    float yn = (acc - mean) * rstd * an_g[c] + an_b[c];
    size_t idx = ((size_t)row << 8) + c;
    g_xabf[idx] = __float2bfloat16(g_xn[idx] + geluf(yn));
}

// ---------------- bf16 tensor-core GEMM (3-stage cp.async ring) ----------------
// out[M,Nout] = A[M,K]bf16 @ Wt[Nout,K]bf16^T (+epi)
// EPI: 0 none, 1 +bias, 2 +bias+add1+add2, 3 +bias+add1
#define SAST 40   // smem row stride in bf16 units (80B, conflict-free for LDSM)
#define NSTAGE 3

__device__ __forceinline__ void ldsm4(unsigned& r0, unsigned& r1, unsigned& r2, unsigned& r3,
                                      const __nv_bfloat16* p) {
    unsigned addr = (unsigned)__cvta_generic_to_shared(p);
    asm volatile("ldmatrix.sync.aligned.m8n8.x4.shared.b16 {%0,%1,%2,%3}, [%4];"
                 : "=r"(r0), "=r"(r1), "=r"(r2), "=r"(r3) : "r"(addr));
}
__device__ __forceinline__ void mma_bf16(float* d, const unsigned* a, const unsigned* b) {
    asm volatile(
        "mma.sync.aligned.m16n8k16.row.col.f32.bf16.bf16.f32 "
        "{%0,%1,%2,%3}, {%4,%5,%6,%7}, {%8,%9}, {%0,%1,%2,%3};"
        : "+f"(d[0]), "+f"(d[1]), "+f"(d[2]), "+f"(d[3])
        : "r"(a[0]), "r"(a[1]), "r"(a[2]), "r"(a[3]), "r"(b[0]), "r"(b[1]));
}
__device__ __forceinline__ void cpasync16(__nv_bfloat16* dst, const __nv_bfloat16* src) {
    unsigned saddr = (unsigned)__cvta_generic_to_shared(dst);
    asm volatile("cp.async.cg.shared.global [%0], [%1], 16;" :: "r"(saddr), "l"(src));
}

template<int EPI, bool BFOUT>
__global__ void __launch_bounds__(256, 2)
gemm_bf16(const __nv_bfloat16* __restrict__ A, const __nv_bfloat16* __restrict__ Wt,
          const float* __restrict__ bias,
          const float* __restrict__ add1, const float* __restrict__ add2,
          void* __restrict__ outp, int Nout, int K) {
    __shared__ __nv_bfloat16 As[NSTAGE][128*SAST];
    __shared__ __nv_bfloat16 Bs[NSTAGE][128*SAST];

    const int t = threadIdx.x;
    const int warp = t >> 5, lane = t & 31;
    const int wm = (warp & 3) * 32;
    const int wn = (warp >> 2) * 64;
    const int grp = lane >> 2;
    const int kq  = lane & 3;
    const int row0 = blockIdx.y * 128;
    const int col0 = blockIdx.x * 128;

    // chunk mapping for cp.async: 512 16B chunks per matrix per tile, 2 per thread
    const int c0r = t >> 2,         c0s = (t & 3) * 8;
    const int c1r = (t + 256) >> 2, c1s = ((t + 256) & 3) * 8;

    // lane-dependent LDSM source offsets (within current k16 sub-block)
    const int a_row = (lane & 7) + ((lane >> 3) & 1) * 8;
    const int a_kof = (lane >> 4) * 8;
    const int b_row = (lane & 7) + (lane >> 4) * 8;
    const int b_kof = ((lane >> 3) & 1) * 8;

    float acc[2][8][4];
    #pragma unroll
    for (int i = 0; i < 2; i++)
        #pragma unroll
        for (int j = 0; j < 8; j++)
            #pragma unroll
            for (int q = 0; q < 4; q++) acc[i][j][q] = 0.f;

    const int ntiles = K >> 5;   // BK=32

    // prologue: stages 0 and 1
    #pragma unroll
    for (int s = 0; s < 2; s++) {
        int kg = s << 5;
        cpasync16(&As[s][c0r*SAST + c0s], A  + (size_t)(row0 + c0r) * K + kg + c0s);
        cpasync16(&As[s][c1r*SAST + c1s], A  + (size_t)(row0 + c1r) * K + kg + c1s);
        cpasync16(&Bs[s][c0r*SAST + c0s], Wt + (size_t)(col0 + c0r) * K + kg + c0s);
        cpasync16(&Bs[s][c1r*SAST + c1s], Wt + (size_t)(col0 + c1r) * K + kg + c1s);
        asm volatile("cp.async.commit_group;");
    }

    for (int kt = 0; kt < ntiles; kt++) {
        if (kt == ntiles - 1) asm volatile("cp.async.wait_group 0;");
        else                  asm volatile("cp.async.wait_group 1;");
        __syncthreads();
        // issue loads for stage kt+2 (into buffer (kt+2)%3 == (kt-1)%3, freed by the sync)
        if (kt + 2 < ntiles) {
            int nb = (kt + 2) % NSTAGE;
            int kg = (kt + 2) << 5;
            cpasync16(&As[nb][c0r*SAST + c0s], A  + (size_t)(row0 + c0r) * K + kg + c0s);
            cpasync16(&As[nb][c1r*SAST + c1s], A  + (size_t)(row0 + c1r) * K + kg + c1s);
            cpasync16(&Bs[nb][c0r*SAST + c0s], Wt + (size_t)(col0 + c0r) * K + kg + c0s);
            cpasync16(&Bs[nb][c1r*SAST + c1s], Wt + (size_t)(col0 + c1r) * K + kg + c1s);
            asm volatile("cp.async.commit_group;");
        }
        const int buf = kt % NSTAGE;
        #pragma unroll
        for (int s = 0; s < 2; s++) {
            const int kb = s * 16;
            unsigned af[2][4], bf[4][4];
            #pragma unroll
            for (int i = 0; i < 2; i++)
                ldsm4(af[i][0], af[i][1], af[i][2], af[i][3],
                      &As[buf][(wm + i*16 + a_row)*SAST + kb + a_kof]);
            #pragma unroll
            for (int j2 = 0; j2 < 4; j2++)
                ldsm4(bf[j2][0], bf[j2][1], bf[j2][2], bf[j2][3],
                      &Bs[buf][(wn + j2*16 + b_row)*SAST + kb + b_kof]);
            #pragma unroll
            for (int i = 0; i < 2; i++)
                #pragma unroll
                for (int j = 0; j < 8; j++)
                    mma_bf16(acc[i][j], af[i], &bf[j >> 1][(j & 1) * 2]);
        }
    }

    // epilogue (c-frag: c0,c1 -> (grp, 2kq/2kq+1); c2,c3 -> grp+8)
    #pragma unroll
    for (int i = 0; i < 2; i++) {
        int r_lo = row0 + wm + i * 16 + grp;
        #pragma unroll
        for (int j = 0; j < 8; j++) {
            int cidx = col0 + wn + j * 8 + kq * 2;
            float bv0 = 0.f, bv1 = 0.f;
            if (EPI >= 1) { bv0 = bias[cidx]; bv1 = bias[cidx + 1]; }
            size_t o_lo = (size_t)r_lo * Nout + cidx;
            size_t o_hi = o_lo + (size_t)8 * Nout;
            float v0 = acc[i][j][0] + bv0;
            float v1 = acc[i][j][1] + bv1;
            float v2 = acc[i][j][2] + bv0;
            float v3 = acc[i][j][3] + bv1;
            if (EPI == 2) {
                v0 += add1[o_lo] + add2[o_lo];
                v1 += add1[o_lo + 1] + add2[o_lo + 1];
                v2 += add1[o_hi] + add2[o_hi];
                v3 += add1[o_hi + 1] + add2[o_hi + 1];
            }
            if (EPI == 3) {
                v0 += add1[o_lo];     v1 += add1[o_lo + 1];
                v2 += add1[o_hi];     v3 += add1[o_hi + 1];
            }
            if (BFOUT) {
                __nv_bfloat16* ob = (__nv_bfloat16*)outp;
                *(__nv_bfloat162*)(ob + o_lo) = __float22bfloat162_rn(make_float2(v0, v1));
                *(__nv_bfloat162*)(ob + o_hi) = __float22bfloat162_rn(make_float2(v2, v3));
            } else {
                float* of = (float*)outp;
                *(float2*)(of + o_lo) = make_float2(v0, v1);
                *(float2*)(of + o_hi) = make_float2(v2, v3);
            }
        }
    }
}

// ---------------- q stats: online per-chunk max/sumexp + reduce ----------------
__global__ void qstats_kernel() {
    int b = blockIdx.y, chunk = blockIdx.x, c = threadIdx.x;
    float m = -1e30f, s = 0.f;
    int base = b * NNN + chunk * 128;
    for (int r = 0; r < 128; r++) {
        float v = g_q[(size_t)(base + r) * CCH + c];
        if (v > m) { s = s * expf(m - v) + 1.f; m = v; }
        else s += expf(v - m);
    }
    g_qpm[(b*32 + chunk)*CCH + c] = m;
    g_qps[(b*32 + chunk)*CCH + c] = s;
}
__global__ void qfinal_kernel() {
    int b = blockIdx.x, c = threadIdx.x;
    float m = -1e30f;
    for (int k = 0; k < 32; k++) m = fmaxf(m, g_qpm[(b*32 + k)*CCH + c]);
    float s = 0.f;
    for (int k = 0; k < 32; k++) s += g_qps[(b*32 + k)*CCH + c] * expf(g_qpm[(b*32 + k)*CCH + c] - m);
    g_qmax[b*CCH + c] = m;
    g_qsum[b*CCH + c] = s;
}

// ---------------- ctx = softmax_d(k)^T v  (fused k-softmax, bf16 in) ---------
__global__ void ctx_kernel() {
    int chunk = blockIdx.x;           // 0..7 : 512 rows each
    int bh = blockIdx.y;              // b*8+h
    int b = bh >> 3, h = bh & 7;
    int w = threadIdx.x >> 5, lane = threadIdx.x & 31;
    __shared__ float ks[32][33], vs[32][33];
    float acc[4] = {0.f, 0.f, 0.f, 0.f};
    int base = b * NNN + chunk * 512;
    for (int tile = 0; tile < 16; tile++) {
        #pragma unroll
        for (int rr = 0; rr < 4; rr++) {
            int rl = w * 4 + rr;
            size_t row = (size_t)(base + tile * 32 + rl);
            float kv = __bfloat162float(g_kbf[row * CCH + h * 32 + lane]);
            float mx = kv;
            #pragma unroll
            for (int off = 16; off; off >>= 1) mx = fmaxf(mx, __shfl_xor_sync(0xffffffffu, mx, off));
            float e = expf(kv - mx);
            float ss = e;
            #pragma unroll
            for (int off = 16; off; off >>= 1) ss += __shfl_xor_sync(0xffffffffu, ss, off);
            ks[rl][lane] = e / ss;
            vs[rl][lane] = __bfloat162float(g_vbf[row * CCH + h * 32 + lane]);
        }
        __syncthreads();
        for (int r = 0; r < 32; r++) {
            float vv = vs[r][lane];
            #pragma unroll
            for (int i = 0; i < 4; i++) acc[i] += ks[r][w*4 + i] * vv;
        }
        __syncthreads();
    }
    #pragma unroll
    for (int i = 0; i < 4; i++)
        atomicAdd(&g_ctx[bh * 1024 + (w*4 + i) * 32 + lane], acc[i]);
}

// ---------------- attn = softmax_N(q) @ ctx  (warp per head, bf16 out) -------
__global__ void attn_kernel() {
    int blk = blockIdx.x;             // 1024 blocks, 64 rows each
    int w = threadIdx.x >> 5, lane = threadIdx.x & 31;
    int b = blk >> 6;
    int h = w;
    float c[32];
    const float* cp = g_ctx + ((size_t)((b << 3) + h)) * 1024 + lane;
    #pragma unroll
    for (int d = 0; d < 32; d++) c[d] = cp[d * 32];
    float qm = g_qmax[b*CCH + h*32 + lane];
    float qi = 1.0f / g_qsum[b*CCH + h*32 + lane];
    int row0 = blk * 64;
    for (int r = 0; r < 64; r++) {
        size_t row = (size_t)(row0 + r);
        float qv = g_q[row * CCH + h*32 + lane];
        float qe = expf(qv - qm) * qi;
        float a0 = 0.f, a1 = 0.f;
        #pragma unroll
        for (int d = 0; d < 32; d += 2) {
            a0 += __shfl_sync(0xffffffffu, qe, d)     * c[d];
            a1 += __shfl_sync(0xffffffffu, qe, d + 1) * c[d + 1];
        }
        g_attnbf[row * CCH + h*32 + lane] = __float2bfloat16(a0 + a1);
    }
}

// ---------------- MixFFN dwconv 3x3 + gelu (tiled, bf16 in/out) --------------
__global__ void __launch_bounds__(256) dw_kernel(const float* __restrict__ dw_w,
                                                 const float* __restrict__ dw_b) {
    __shared__ float s[10*10*64];
    int tile = blockIdx.x;            // 0..63 : 8x8 grid of 8x8 tiles
    int cc = blockIdx.y;              // 0..15 : 64-ch chunks
    int b = blockIdx.z;
    int th0 = (tile >> 3) * 8, tw0 = (tile & 7) * 8;
    int t = threadIdx.x;
    int c0 = cc * 64;
    for (int l = t; l < 6400; l += 256) {
        int lh = l / 640, rem = l % 640, lw = rem / 64, lc = rem % 64;
        int gh = th0 + lh - 1, gw = tw0 + lw - 1;
        float v = 0.f;
        if (gh >= 0 && gh < HHH && gw >= 0 && gw < WWW)
            v = __bfloat162float(g_h1bf[(size_t)((b << 12) + (gh << 6) + gw) * HIDD + c0 + lc]);
        s[l] = v;
    }
    __syncthreads();
    int oc = t & 63;
    int cg = c0 + oc;
    float wt[9];
    #pragma unroll
    for (int k = 0; k < 9; k++) wt[k] = dw_w[cg*9 + k];
    float bias = dw_b[cg];
    for (int o = t; o < 4096; o += 256) {
        int oh = o >> 9, ow = (o >> 6) & 7;
        float acc = bias;
        #pragma unroll
        for (int kh = 0; kh < 3; kh++)
            #pragma unroll
            for (int kw = 0; kw < 3; kw++)
                acc += s[(oh + kh)*640 + (ow + kw)*64 + oc] * wt[kh*3 + kw];
        size_t row = (size_t)((b << 12) + ((th0 + oh) << 6) + (tw0 + ow));
        g_h2bf[row * HIDD + cg] = __float2bfloat16(geluf(acc));
    }
}

// ---------------- CSDA channel stats ----------------
__global__ void avgmax_kernel() {
    int b = blockIdx.y, chunk = blockIdx.x, c = threadIdx.x;
    float s = 0.f, m = -1e30f;
    int base = b * NNN + chunk * 128;
    for (int r = 0; r < 128; r++) {
        float v = g_x[(size_t)(base + r) * CCH + c];
        s += v; m = fmaxf(m, v);
    }
    atomicAdd(&g_avg[b * CCH + c], s);
    atomicMaxF(&g_mx[b * CCH + c], m);
}

__global__ void ca_kernel(const float* __restrict__ w1, const float* __restrict__ w2) {
    int b = blockIdx.x, t = threadIdx.x;
    __shared__ float sav[CCH], smx[CCH], hid[32];
    sav[t] = g_avg[b * CCH + t] * (1.0f / NNN);
    smx[t] = g_mx[b * CCH + t];
    __syncthreads();
    if (t < 16) {
        float a = 0.f;
        for (int c = 0; c < CCH; c++) a += sav[c] * w1[t * CCH + c];
        hid[t] = fmaxf(a, 0.f);
    } else if (t < 32) {
        int j = t - 16;
        float a = 0.f;
        for (int c = 0; c < CCH; c++) a += smx[c] * w1[j * CCH + c];
        hid[16 + j] = fmaxf(a, 0.f);
    }
    __syncthreads();
    float a = 0.f;
    #pragma unroll
    for (int j = 0; j < 16; j++) a += (hid[j] + hid[16 + j]) * w2[t * 16 + j];
    g_cab[b * CCH + t] = sigmoidf_(a);
}

// ---------------- spatial map: mean/max over channels of x*ca ----------------
__global__ void smap_kernel() {
    int gid  = blockIdx.x * blockDim.x + threadIdx.x;
    int warp = gid >> 5, lane = gid & 31;
    if (warp >= MTOT) return;
    int b = warp >> 12;
    const float* row = g_x + (size_t)warp * CCH;
    const float* ca  = g_cab + b * CCH;
    float4 a = ((const float4*)row)[lane*2];
    float4 c4 = ((const float4*)ca)[lane*2];
    float4 b4 = ((const float4*)row)[lane*2+1];
    float4 d4 = ((const float4*)ca)[lane*2+1];
    float v0=a.x*c4.x, v1=a.y*c4.y, v2=a.z*c4.z, v3=a.w*c4.w;
    float v4=b4.x*d4.x, v5=b4.y*d4.y, v6=b4.z*d4.z, v7=b4.w*d4.w;
    float s = v0+v1+v2+v3+v4+v5+v6+v7;
    float m = fmaxf(fmaxf(fmaxf(v0,v1),fmaxf(v2,v3)), fmaxf(fmaxf(v4,v5),fmaxf(v6,v7)));
    #pragma unroll
    for (int off = 16; off; off >>= 1) {
        s += __shfl_xor_sync(0xffffffffu, s, off);
        m = fmaxf(m, __shfl_xor_sync(0xffffffffu, m, off));
    }
    if (lane == 0) {
        g_smean[warp] = s * (1.0f / CCH);
        g_smax[warp]  = m;
    }
}

// ---------------- spatial attention 7x7 conv + sigmoid ----------------
__global__ void sa_kernel(const float* __restrict__ sp_w, const float* __restrict__ sp_b) {
    int idx = blockIdx.x * blockDim.x + threadIdx.x;   // b*N+n
    int b = idx >> 12, n = idx & 4095;
    int h = n >> 6, w = n & 63;
    float acc = sp_b[0];
    for (int kh = 0; kh < 7; kh++) {
        int hh = h + kh - 3;
        if (hh < 0 || hh >= HHH) continue;
        for (int kw = 0; kw < 7; kw++) {
            int ww = w + kw - 3;
            if (ww < 0 || ww >= WWW) continue;
            int nn = b * NNN + hh * 64 + ww;
            acc += g_smean[nn] * sp_w[kh*7 + kw] + g_smax[nn] * sp_w[49 + kh*7 + kw];
        }
    }
    g_sa[idx] = sigmoidf_(acc);
}

// ---------------- final: out = x * ca * sa ----------------
__global__ void final_kernel(float* __restrict__ out) {
    int gid = blockIdx.x * blockDim.x + threadIdx.x;
    size_t idx4 = (size_t)gid * 4;
    int row = (int)(idx4 >> 8);
    int c   = (int)(idx4 & 255);
    int b   = row >> 12;
    float sa = g_sa[row];
    float4 ca = *(const float4*)(g_cab + b * CCH + c);
    float4 xv = *(const float4*)(g_x + idx4);
    float4 o;
    o.x = xv.x * ca.x * sa; o.y = xv.y * ca.y * sa;
    o.z = xv.z * ca.z * sa; o.w = xv.w * ca.w * sa;
    *(float4*)(out + idx4) = o;
}

// ---------------- launch ----------------
extern "C" void kernel_launch(void* const* d_in, const int* in_sizes, int n_in,
                              void* d_out, int out_size) {
    const float* x      = (const float*)d_in[0];
    const float* n1_g   = (const float*)d_in[3];
    const float* n1_b   = (const float*)d_in[4];
    const float* sr_w   = (const float*)d_in[5];
    const float* sr_b   = (const float*)d_in[6];
    const float* an_g   = (const float*)d_in[7];
    const float* an_b   = (const float*)d_in[8];
    const float* qkv_w  = (const float*)d_in[9];
    const float* proj_w = (const float*)d_in[10];
    const float* proj_b = (const float*)d_in[11];
    const float* n2_g   = (const float*)d_in[12];
    const float* n2_b   = (const float*)d_in[13];
    const float* fc1_w  = (const float*)d_in[14];
    const float* fc1_b  = (const float*)d_in[15];
    const float* dw_w   = (const float*)d_in[16];
    const float* dw_b   = (const float*)d_in[17];
    const float* fc2_w  = (const float*)d_in[18];
    const float* fc2_b  = (const float*)d_in[19];
    const float* ca_w1  = (const float*)d_in[20];
    const float* ca_w2  = (const float*)d_in[21];
    const float* sp_w   = (const float*)d_in[22];
    const float* sp_b   = (const float*)d_in[23];
    float* out = (float*)d_out;

    float *p_xn, *p_q, *p_x;
    __nv_bfloat16 *p_kbf, *p_vbf, *p_h1bf, *p_xabf, *p_xnbf, *p_attnbf, *p_h2bf;
    __nv_bfloat16 *p_wqkv, *p_wproj, *p_wfc1, *p_wfc2;
    cudaGetSymbolAddress((void**)&p_xn,    g_xn);
    cudaGetSymbolAddress((void**)&p_q,     g_q);
    cudaGetSymbolAddress((void**)&p_x,     g_x);
    cudaGetSymbolAddress((void**)&p_kbf,   g_kbf);
    cudaGetSymbolAddress((void**)&p_vbf,   g_vbf);
    cudaGetSymbolAddress((void**)&p_h1bf,  g_h1bf);
    cudaGetSymbolAddress((void**)&p_xabf,  g_xabf);
    cudaGetSymbolAddress((void**)&p_xnbf,  g_xnbf);
    cudaGetSymbolAddress((void**)&p_attnbf,g_attnbf);
    cudaGetSymbolAddress((void**)&p_h2bf,  g_h2bf);
    cudaGetSymbolAddress((void**)&p_wqkv,  g_wqkv);
    cudaGetSymbolAddress((void**)&p_wproj, g_wproj);
    cudaGetSymbolAddress((void**)&p_wfc1,  g_wfc1);
    cudaGetSymbolAddress((void**)&p_wfc2,  g_wfc2);

    init_kernel<<<512, 256>>>();
    cvt_kernel<<<(3*CCH*CCH+255)/256, 256>>>(qkv_w,  p_wqkv,  3*CCH*CCH);
    cvt_kernel<<<(CCH*CCH+255)/256, 256>>>(proj_w, p_wproj, CCH*CCH);
    cvt_kernel<<<(HIDD*CCH+255)/256, 256>>>(fc1_w,  p_wfc1,  HIDD*CCH);
    cvt_kernel<<<(CCH*HIDD+255)/256, 256>>>(fc2_w,  p_wfc2,  CCH*HIDD);

    // --- attention branch ---
    ln_kernel<false><<<MTOT/8, 256>>>(x, n1_g, n1_b, p_xn, nullptr);
    sr_an_kernel<<<MTOT, 256>>>(sr_w, sr_b, an_g, an_b);
    // qkv split into three 256-col GEMMs: q fp32, k bf16, v bf16
    gemm_bf16<0,false><<<dim3(2, MTOT/128), 256>>>(p_xabf, p_wqkv,
        nullptr, nullptr, nullptr, p_q, 256, 256);
    gemm_bf16<0,true><<<dim3(2, MTOT/128), 256>>>(p_xabf, p_wqkv + 256*256,
        nullptr, nullptr, nullptr, p_kbf, 256, 256);
    gemm_bf16<0,true><<<dim3(2, MTOT/128), 256>>>(p_xabf, p_wqkv + 512*256,
        nullptr, nullptr, nullptr, p_vbf, 256, 256);
    qstats_kernel<<<dim3(32, BB), 256>>>();
    qfinal_kernel<<<BB, 256>>>();
    ctx_kernel<<<dim3(8, BB*NHEAD), 256>>>();
    attn_kernel<<<MTOT/64, 256>>>();
    gemm_bf16<2,false><<<dim3(2, MTOT/128), 256>>>(p_attnbf, p_wproj, proj_b, p_xn, x,
                                                   p_x, 256, 256);

    // --- MixFFN ---
    ln_kernel<true><<<MTOT/8, 256>>>(p_x, n2_g, n2_b, nullptr, p_xnbf);
    gemm_bf16<1,true><<<dim3(8, MTOT/128), 256>>>(p_xnbf, p_wfc1, fc1_b, nullptr, nullptr,
                                                  p_h1bf, 1024, 256);
    dw_kernel<<<dim3(64, 16, 16), 256>>>(dw_w, dw_b);
    gemm_bf16<3,false><<<dim3(2, MTOT/128), 256>>>(p_h2bf, p_wfc2, fc2_b, p_x, nullptr,
                                                   p_x, 256, 1024);

    // --- CSDA ---
    avgmax_kernel<<<dim3(32, BB), 256>>>();
    ca_kernel<<<BB, 256>>>(ca_w1, ca_w2);
    smap_kernel<<<MTOT/8, 256>>>();
    sa_kernel<<<MTOT/256, 256>>>(sp_w, sp_b);
    final_kernel<<<(MTOT*CCH/4)/256, 256>>>(out);
}

// round 6
// speedup vs baseline: 3.3447x; 1.0035x over previous
#include <cuda_runtime.h>
#include <cuda_bf16.h>
#include <math.h>
#include <stdint.h>

// ---------------- problem constants ----------------
#define BB    16
#define NNN   4096
#define CCH   256
#define HHH   64
#define WWW   64
#define HIDD  1024
#define NHEAD 8
#define HDIM  32
#define MTOT  (BB*NNN)          // 65536 rows

// ---------------- scratch (device globals; no allocs allowed) ----------------
__device__ float g_xn  [MTOT*CCH];            // ln1 out (fp32, reused for residuals)
__device__ float g_q   [MTOT*CCH];            // q (fp32 for softmax precision)
__device__ float g_x   [MTOT*CCH];            // trunk fp32
__device__ __nv_bfloat16 g_kbf   [MTOT*CCH];  // k bf16
__device__ __nv_bfloat16 g_vbf   [MTOT*CCH];  // v bf16
__device__ __nv_bfloat16 g_h1bf  [MTOT*HIDD]; // fc1 out bf16
__device__ __nv_bfloat16 g_xabf  [MTOT*CCH];  // attn-branch gemm A
__device__ __nv_bfloat16 g_xnbf  [MTOT*CCH];  // ln2 out (fc1 A)
__device__ __nv_bfloat16 g_attnbf[MTOT*CCH];  // proj A
__device__ __nv_bfloat16 g_h2bf  [MTOT*HIDD]; // fc2 A
__device__ __nv_bfloat16 g_wqkv [3*CCH*CCH];
__device__ __nv_bfloat16 g_wproj[CCH*CCH];
__device__ __nv_bfloat16 g_wfc1 [HIDD*CCH];
__device__ __nv_bfloat16 g_wfc2 [CCH*HIDD];
__device__ float g_ctx [BB*NHEAD*HDIM*HDIM];
__device__ float g_qpm [BB*32*CCH];
__device__ float g_qps [BB*32*CCH];
__device__ float g_qmax[BB*CCH];
__device__ float g_qsum[BB*CCH];
__device__ float g_avg [BB*CCH];
__device__ float g_mx  [BB*CCH];
__device__ float g_cab [BB*CCH];
__device__ float g_smean[MTOT];
__device__ float g_smax [MTOT];
__device__ float g_sa   [MTOT];

// ---------------- helpers ----------------
__device__ __forceinline__ float geluf(float x) {
    return 0.5f * x * (1.0f + erff(x * 0.70710678118654752f));
}
__device__ __forceinline__ float sigmoidf_(float x) {
    return 1.0f / (1.0f + expf(-x));
}
__device__ __forceinline__ void atomicMaxF(float* addr, float v) {
    int* ai = (int*)addr;
    int old = *ai;
    while (__int_as_float(old) < v) {
        int prev = atomicCAS(ai, old, __float_as_int(v));
        if (prev == old) break;
        old = prev;
    }
}

// ---------------- init (per-call, deterministic reset) ----------------
__global__ void init_kernel() {
    int i = blockIdx.x * blockDim.x + threadIdx.x;
    if (i < BB*NHEAD*HDIM*HDIM) g_ctx[i] = 0.f;
    if (i < BB*CCH) {
        g_avg[i]  = 0.f;
        g_mx[i]   = -1e30f;
    }
}

// ---------------- fp32 -> bf16 weight convert (all weights, one launch) ------
#define NW_QKV  (3*CCH*CCH)               // 196608
#define NW_PROJ (CCH*CCH)                 // 65536
#define NW_FC1  (HIDD*CCH)                // 262144
#define NW_FC2  (CCH*HIDD)                // 262144
#define NW_TOT  (NW_QKV + NW_PROJ + NW_FC1 + NW_FC2)   // 786432

__global__ void cvt_all_kernel(const float* __restrict__ qkv_w,
                               const float* __restrict__ proj_w,
                               const float* __restrict__ fc1_w,
                               const float* __restrict__ fc2_w) {
    int i = blockIdx.x * blockDim.x + threadIdx.x;
    if (i < NW_QKV) { g_wqkv[i] = __float2bfloat16(qkv_w[i]); return; }
    int j = i - NW_QKV;
    if (j < NW_PROJ) { g_wproj[j] = __float2bfloat16(proj_w[j]); return; }
    j -= NW_PROJ;
    if (j < NW_FC1) { g_wfc1[j] = __float2bfloat16(fc1_w[j]); return; }
    j -= NW_FC1;
    if (j < NW_FC2) { g_wfc2[j] = __float2bfloat16(fc2_w[j]); }
}

// ---------------- LayerNorm over C=256, one warp per row ----------------
template<bool BFOUT>
__global__ void ln_kernel(const float* __restrict__ in,
                          const float* __restrict__ gg,
                          const float* __restrict__ bb,
                          float* __restrict__ out,
                          __nv_bfloat16* __restrict__ outbf) {
    int gid  = blockIdx.x * blockDim.x + threadIdx.x;
    int warp = gid >> 5;
    int lane = gid & 31;
    if (warp >= MTOT) return;
    const float* row = in + (size_t)warp * CCH;
    float4 a = ((const float4*)row)[lane*2];
    float4 b = ((const float4*)row)[lane*2+1];
    float s1 = a.x+a.y+a.z+a.w + b.x+b.y+b.z+b.w;
    float s2 = a.x*a.x+a.y*a.y+a.z*a.z+a.w*a.w + b.x*b.x+b.y*b.y+b.z*b.z+b.w*b.w;
    #pragma unroll
    for (int off = 16; off; off >>= 1) {
        s1 += __shfl_xor_sync(0xffffffffu, s1, off);
        s2 += __shfl_xor_sync(0xffffffffu, s2, off);
    }
    float mean = s1 * (1.0f/CCH);
    float var  = s2 * (1.0f/CCH) - mean*mean;
    float rstd = rsqrtf(var + 1e-5f);
    float4 g0 = ((const float4*)gg)[lane*2];
    float4 g1 = ((const float4*)gg)[lane*2+1];
    float4 b0 = ((const float4*)bb)[lane*2];
    float4 b1 = ((const float4*)bb)[lane*2+1];
    float4 o0, o1;
    o0.x=(a.x-mean)*rstd*g0.x+b0.x; o0.y=(a.y-mean)*rstd*g0.y+b0.y;
    o0.z=(a.z-mean)*rstd*g0.z+b0.z; o0.w=(a.w-mean)*rstd*g0.w+b0.w;
    o1.x=(b.x-mean)*rstd*g1.x+b1.x; o1.y=(b.y-mean)*rstd*g1.y+b1.y;
    o1.z=(b.z-mean)*rstd*g1.z+b1.z; o1.w=(b.w-mean)*rstd*g1.w+b1.w;
    if (BFOUT) {
        union { __nv_bfloat162 h[4]; uint4 u; } pk;
        pk.h[0]=__float22bfloat162_rn(make_float2(o0.x,o0.y));
        pk.h[1]=__float22bfloat162_rn(make_float2(o0.z,o0.w));
        pk.h[2]=__float22bfloat162_rn(make_float2(o1.x,o1.y));
        pk.h[3]=__float22bfloat162_rn(make_float2(o1.z,o1.w));
        ((uint4*)(outbf + (size_t)warp*CCH))[lane] = pk.u;
    } else {
        float* orow = out + (size_t)warp * CCH;
        ((float4*)orow)[lane*2]   = o0;
        ((float4*)orow)[lane*2+1] = o1;
    }
}

// ---------------- sr dwconv 3x3 + LN + gelu + residual -> xa (bf16) ----------
__global__ void sr_an_kernel(const float* __restrict__ sr_w, const float* __restrict__ sr_b,
                             const float* __restrict__ an_g, const float* __restrict__ an_b) {
    int row = blockIdx.x;                 // b*N + n
    int b = row >> 12, n = row & 4095;
    int h = n >> 6, w = n & 63;
    int c = threadIdx.x;
    float acc = sr_b[c];
    #pragma unroll
    for (int kh = 0; kh < 3; kh++) {
        int hh = h + kh - 1;
        if (hh < 0 || hh >= HHH) continue;
        #pragma unroll
        for (int kw = 0; kw < 3; kw++) {
            int ww = w + kw - 1;
            if (ww < 0 || ww >= WWW) continue;
            size_t src = ((size_t)((b<<12) | (hh<<6) | ww) << 8) + c;
            acc += g_xn[src] * sr_w[c*9 + kh*3 + kw];
        }
    }
    float s1 = acc, s2 = acc*acc;
    #pragma unroll
    for (int off = 16; off; off >>= 1) {
        s1 += __shfl_xor_sync(0xffffffffu, s1, off);
        s2 += __shfl_xor_sync(0xffffffffu, s2, off);
    }
    __shared__ float r1[8], r2[8];
    int lane = c & 31, wid = c >> 5;
    if (lane == 0) { r1[wid] = s1; r2[wid] = s2; }
    __syncthreads();
    if (c == 0) {
        float a = 0.f, q = 0.f;
        #pragma unroll
        for (int i = 0; i < 8; i++) { a += r1[i]; q += r2[i]; }
        float mean = a * (1.0f/CCH);
        float var  = q * (1.0f/CCH) - mean*mean;
        r1[0] = mean; r2[0] = rsqrtf(var + 1e-5f);
    }
    __syncthreads();
    float mean = r1[0], rstd = r2[0];
    float yn = (acc - mean) * rstd * an_g[c] + an_b[c];
    size_t idx = ((size_t)row << 8) + c;
    g_xabf[idx] = __float2bfloat16(g_xn[idx] + geluf(yn));
}

// ---------------- bf16 tensor-core GEMM (BK=64, 3-stage cp.async ring) -------
// out[M,Nout] = A[M,K]bf16 @ Wt[Nout,K]bf16^T (+epi)
// EPI: 0 none, 1 +bias, 2 +bias+add1+add2, 3 +bias+add1
#define SAST 72     // smem row stride in bf16 (144B: 4-bank shift/row, LDSM-clean)
#define NSTAGE 3
#define STG_ELEMS (128*SAST)                         // per matrix per stage
#define GEMM_DSMEM (NSTAGE * STG_ELEMS * 2 * 2)      // bytes, A+B

__device__ __forceinline__ void ldsm4(unsigned& r0, unsigned& r1, unsigned& r2, unsigned& r3,
                                      const __nv_bfloat16* p) {
    unsigned addr = (unsigned)__cvta_generic_to_shared(p);
    asm volatile("ldmatrix.sync.aligned.m8n8.x4.shared.b16 {%0,%1,%2,%3}, [%4];"
                 : "=r"(r0), "=r"(r1), "=r"(r2), "=r"(r3) : "r"(addr));
}
__device__ __forceinline__ void mma_bf16(float* d, const unsigned* a, const unsigned* b) {
    asm volatile(
        "mma.sync.aligned.m16n8k16.row.col.f32.bf16.bf16.f32 "
        "{%0,%1,%2,%3}, {%4,%5,%6,%7}, {%8,%9}, {%0,%1,%2,%3};"
        : "+f"(d[0]), "+f"(d[1]), "+f"(d[2]), "+f"(d[3])
        : "r"(a[0]), "r"(a[1]), "r"(a[2]), "r"(a[3]), "r"(b[0]), "r"(b[1]));
}
__device__ __forceinline__ void cpasync16(unsigned saddr, const __nv_bfloat16* src) {
    asm volatile("cp.async.cg.shared.global [%0], [%1], 16;" :: "r"(saddr), "l"(src));
}

template<int EPI, bool BFOUT>
__global__ void __launch_bounds__(256, 2)
gemm_bf16(const __nv_bfloat16* __restrict__ A, const __nv_bfloat16* __restrict__ Wt,
          const float* __restrict__ bias,
          const float* __restrict__ add1, const float* __restrict__ add2,
          void* __restrict__ outp, int Nout, int K) {
    extern __shared__ __nv_bfloat16 smbuf[];
    __nv_bfloat16* As = smbuf;
    __nv_bfloat16* Bs = smbuf + NSTAGE * STG_ELEMS;
    const unsigned As_s = (unsigned)__cvta_generic_to_shared(As);
    const unsigned Bs_s = (unsigned)__cvta_generic_to_shared(Bs);

    const int t = threadIdx.x;
    const int warp = t >> 5, lane = t & 31;
    const int wm = (warp & 3) * 32;
    const int wn = (warp >> 2) * 64;
    const int grp = lane >> 2;
    const int kq  = lane & 3;
    const int row0 = blockIdx.y * 128;
    const int col0 = blockIdx.x * 128;

    // cp.async mapping: per stage per matrix = 128 rows x 64 cols = 1024 chunks of 16B.
    // thread t handles chunks t, t+256, t+512, t+768: row = ch>>3, scol = (ch&7)*8
    // lane-dependent LDSM source offsets (within a k16 sub-block)
    const int a_row = (lane & 7) + ((lane >> 3) & 1) * 8;
    const int a_kof = (lane >> 4) * 8;
    const int b_row = (lane & 7) + (lane >> 4) * 8;
    const int b_kof = ((lane >> 3) & 1) * 8;

    float acc[2][8][4];
    #pragma unroll
    for (int i = 0; i < 2; i++)
        #pragma unroll
        for (int j = 0; j < 8; j++)
            #pragma unroll
            for (int q = 0; q < 4; q++) acc[i][j][q] = 0.f;

    const int ntiles = K >> 6;   // BK=64

    // prologue: stages 0 and 1
    #pragma unroll
    for (int s = 0; s < 2; s++) {
        if (s < ntiles) {
            int kg = s << 6;
            #pragma unroll
            for (int cpart = 0; cpart < 4; cpart++) {
                int ch = t + cpart * 256;
                int r = ch >> 3, sc = (ch & 7) * 8;
                unsigned so = (unsigned)(s * STG_ELEMS + r * SAST + sc) * 2;
                cpasync16(As_s + so, A  + (size_t)(row0 + r) * K + kg + sc);
                cpasync16(Bs_s + so, Wt + (size_t)(col0 + r) * K + kg + sc);
            }
        }
        asm volatile("cp.async.commit_group;");
    }

    for (int kt = 0; kt < ntiles; kt++) {
        if (kt == ntiles - 1) asm volatile("cp.async.wait_group 0;");
        else                  asm volatile("cp.async.wait_group 1;");
        __syncthreads();
        if (kt + 2 < ntiles) {
            int st = (kt + 2) % NSTAGE;
            int kg = (kt + 2) << 6;
            #pragma unroll
            for (int cpart = 0; cpart < 4; cpart++) {
                int ch = t + cpart * 256;
                int r = ch >> 3, sc = (ch & 7) * 8;
                unsigned so = (unsigned)(st * STG_ELEMS + r * SAST + sc) * 2;
                cpasync16(As_s + so, A  + (size_t)(row0 + r) * K + kg + sc);
                cpasync16(Bs_s + so, Wt + (size_t)(col0 + r) * K + kg + sc);
            }
            asm volatile("cp.async.commit_group;");
        } else {
            asm volatile("cp.async.commit_group;");   // keep group count in lockstep
        }
        const int sb = (kt % NSTAGE) * STG_ELEMS;
        #pragma unroll
        for (int s = 0; s < 4; s++) {
            const int kb = s * 16;
            unsigned af[2][4], bf[4][4];
            #pragma unroll
            for (int i = 0; i < 2; i++)
                ldsm4(af[i][0], af[i][1], af[i][2], af[i][3],
                      &As[sb + (wm + i*16 + a_row)*SAST + kb + a_kof]);
            #pragma unroll
            for (int j2 = 0; j2 < 4; j2++)
                ldsm4(bf[j2][0], bf[j2][1], bf[j2][2], bf[j2][3],
                      &Bs[sb + (wn + j2*16 + b_row)*SAST + kb + b_kof]);
            #pragma unroll
            for (int i = 0; i < 2; i++)
                #pragma unroll
                for (int j = 0; j < 8; j++)
                    mma_bf16(acc[i][j], af[i], &bf[j >> 1][(j & 1) * 2]);
        }
    }

    // epilogue (c-frag: c0,c1 -> (grp, 2kq/2kq+1); c2,c3 -> grp+8)
    #pragma unroll
    for (int i = 0; i < 2; i++) {
        int r_lo = row0 + wm + i * 16 + grp;
        #pragma unroll
        for (int j = 0; j < 8; j++) {
            int cidx = col0 + wn + j * 8 + kq * 2;
            float bv0 = 0.f, bv1 = 0.f;
            if (EPI >= 1) { bv0 = bias[cidx]; bv1 = bias[cidx + 1]; }
            size_t o_lo = (size_t)r_lo * Nout + cidx;
            size_t o_hi = o_lo + (size_t)8 * Nout;
            float v0 = acc[i][j][0] + bv0;
            float v1 = acc[i][j][1] + bv1;
            float v2 = acc[i][j][2] + bv0;
            float v3 = acc[i][j][3] + bv1;
            if (EPI == 2) {
                v0 += add1[o_lo] + add2[o_lo];
                v1 += add1[o_lo + 1] + add2[o_lo + 1];
                v2 += add1[o_hi] + add2[o_hi];
                v3 += add1[o_hi + 1] + add2[o_hi + 1];
            }
            if (EPI == 3) {
                v0 += add1[o_lo];     v1 += add1[o_lo + 1];
                v2 += add1[o_hi];     v3 += add1[o_hi + 1];
            }
            if (BFOUT) {
                __nv_bfloat16* ob = (__nv_bfloat16*)outp;
                *(__nv_bfloat162*)(ob + o_lo) = __float22bfloat162_rn(make_float2(v0, v1));
                *(__nv_bfloat162*)(ob + o_hi) = __float22bfloat162_rn(make_float2(v2, v3));
            } else {
                float* of = (float*)outp;
                *(float2*)(of + o_lo) = make_float2(v0, v1);
                *(float2*)(of + o_hi) = make_float2(v2, v3);
            }
        }
    }
}

// ---------------- q stats: online per-chunk max/sumexp + reduce ----------------
__global__ void qstats_kernel() {
    int b = blockIdx.y, chunk = blockIdx.x, c = threadIdx.x;
    float m = -1e30f, s = 0.f;
    int base = b * NNN + chunk * 128;
    for (int r = 0; r < 128; r++) {
        float v = g_q[(size_t)(base + r) * CCH + c];
        if (v > m) { s = s * expf(m - v) + 1.f; m = v; }
        else s += expf(v - m);
    }
    g_qpm[(b*32 + chunk)*CCH + c] = m;
    g_qps[(b*32 + chunk)*CCH + c] = s;
}
__global__ void qfinal_kernel() {
    int b = blockIdx.x, c = threadIdx.x;
    float m = -1e30f;
    for (int k = 0; k < 32; k++) m = fmaxf(m, g_qpm[(b*32 + k)*CCH + c]);
    float s = 0.f;
    for (int k = 0; k < 32; k++) s += g_qps[(b*32 + k)*CCH + c] * expf(g_qpm[(b*32 + k)*CCH + c] - m);
    g_qmax[b*CCH + c] = m;
    g_qsum[b*CCH + c] = s;
}

// ---------------- ctx = softmax_d(k)^T v  (fused k-softmax, bf16 in) ---------
__global__ void ctx_kernel() {
    int chunk = blockIdx.x;           // 0..7 : 512 rows each
    int bh = blockIdx.y;              // b*8+h
    int b = bh >> 3, h = bh & 7;
    int w = threadIdx.x >> 5, lane = threadIdx.x & 31;
    __shared__ float ks[32][33], vs[32][33];
    float acc[4] = {0.f, 0.f, 0.f, 0.f};
    int base = b * NNN + chunk * 512;
    for (int tile = 0; tile < 16; tile++) {
        #pragma unroll
        for (int rr = 0; rr < 4; rr++) {
            int rl = w * 4 + rr;
            size_t row = (size_t)(base + tile * 32 + rl);
            float kv = __bfloat162float(g_kbf[row * CCH + h * 32 + lane]);
            float mx = kv;
            #pragma unroll
            for (int off = 16; off; off >>= 1) mx = fmaxf(mx, __shfl_xor_sync(0xffffffffu, mx, off));
            float e = expf(kv - mx);
            float ss = e;
            #pragma unroll
            for (int off = 16; off; off >>= 1) ss += __shfl_xor_sync(0xffffffffu, ss, off);
            ks[rl][lane] = e / ss;
            vs[rl][lane] = __bfloat162float(g_vbf[row * CCH + h * 32 + lane]);
        }
        __syncthreads();
        for (int r = 0; r < 32; r++) {
            float vv = vs[r][lane];
            #pragma unroll
            for (int i = 0; i < 4; i++) acc[i] += ks[r][w*4 + i] * vv;
        }
        __syncthreads();
    }
    #pragma unroll
    for (int i = 0; i < 4; i++)
        atomicAdd(&g_ctx[bh * 1024 + (w*4 + i) * 32 + lane], acc[i]);
}

// ---------------- attn = softmax_N(q) @ ctx  (warp per head, bf16 out) -------
__global__ void attn_kernel() {
    int blk = blockIdx.x;             // 1024 blocks, 64 rows each
    int w = threadIdx.x >> 5, lane = threadIdx.x & 31;
    int b = blk >> 6;
    int h = w;
    float c[32];
    const float* cp = g_ctx + ((size_t)((b << 3) + h)) * 1024 + lane;
    #pragma unroll
    for (int d = 0; d < 32; d++) c[d] = cp[d * 32];
    float qm = g_qmax[b*CCH + h*32 + lane];
    float qi = 1.0f / g_qsum[b*CCH + h*32 + lane];
    int row0 = blk * 64;
    for (int r = 0; r < 64; r++) {
        size_t row = (size_t)(row0 + r);
        float qv = g_q[row * CCH + h*32 + lane];
        float qe = expf(qv - qm) * qi;
        float a0 = 0.f, a1 = 0.f;
        #pragma unroll
        for (int d = 0; d < 32; d += 2) {
            a0 += __shfl_sync(0xffffffffu, qe, d)     * c[d];
            a1 += __shfl_sync(0xffffffffu, qe, d + 1) * c[d + 1];
        }
        g_attnbf[row * CCH + h*32 + lane] = __float2bfloat16(a0 + a1);
    }
}

// ---------------- MixFFN dwconv 3x3 + gelu (tiled, bf16 in/out) --------------
__global__ void __launch_bounds__(256) dw_kernel(const float* __restrict__ dw_w,
                                                 const float* __restrict__ dw_b) {
    __shared__ float s[10*10*64];
    int tile = blockIdx.x;            // 0..63 : 8x8 grid of 8x8 tiles
    int cc = blockIdx.y;              // 0..15 : 64-ch chunks
    int b = blockIdx.z;
    int th0 = (tile >> 3) * 8, tw0 = (tile & 7) * 8;
    int t = threadIdx.x;
    int c0 = cc * 64;
    for (int l = t; l < 6400; l += 256) {
        int lh = l / 640, rem = l % 640, lw = rem / 64, lc = rem % 64;
        int gh = th0 + lh - 1, gw = tw0 + lw - 1;
        float v = 0.f;
        if (gh >= 0 && gh < HHH && gw >= 0 && gw < WWW)
            v = __bfloat162float(g_h1bf[(size_t)((b << 12) + (gh << 6) + gw) * HIDD + c0 + lc]);
        s[l] = v;
    }
    __syncthreads();
    int oc = t & 63;
    int cg = c0 + oc;
    float wt[9];
    #pragma unroll
    for (int k = 0; k < 9; k++) wt[k] = dw_w[cg*9 + k];
    float bias = dw_b[cg];
    for (int o = t; o < 4096; o += 256) {
        int oh = o >> 9, ow = (o >> 6) & 7;
        float acc = bias;
        #pragma unroll
        for (int kh = 0; kh < 3; kh++)
            #pragma unroll
            for (int kw = 0; kw < 3; kw++)
                acc += s[(oh + kh)*640 + (ow + kw)*64 + oc] * wt[kh*3 + kw];
        size_t row = (size_t)((b << 12) + ((th0 + oh) << 6) + (tw0 + ow));
        g_h2bf[row * HIDD + cg] = __float2bfloat16(geluf(acc));
    }
}

// ---------------- CSDA channel stats ----------------
__global__ void avgmax_kernel() {
    int b = blockIdx.y, chunk = blockIdx.x, c = threadIdx.x;
    float s = 0.f, m = -1e30f;
    int base = b * NNN + chunk * 128;
    for (int r = 0; r < 128; r++) {
        float v = g_x[(size_t)(base + r) * CCH + c];
        s += v; m = fmaxf(m, v);
    }
    atomicAdd(&g_avg[b * CCH + c], s);
    atomicMaxF(&g_mx[b * CCH + c], m);
}

__global__ void ca_kernel(const float* __restrict__ w1, const float* __restrict__ w2) {
    int b = blockIdx.x, t = threadIdx.x;
    __shared__ float sav[CCH], smx[CCH], hid[32];
    sav[t] = g_avg[b * CCH + t] * (1.0f / NNN);
    smx[t] = g_mx[b * CCH + t];
    __syncthreads();
    if (t < 16) {
        float a = 0.f;
        for (int c = 0; c < CCH; c++) a += sav[c] * w1[t * CCH + c];
        hid[t] = fmaxf(a, 0.f);
    } else if (t < 32) {
        int j = t - 16;
        float a = 0.f;
        for (int c = 0; c < CCH; c++) a += smx[c] * w1[j * CCH + c];
        hid[16 + j] = fmaxf(a, 0.f);
    }
    __syncthreads();
    float a = 0.f;
    #pragma unroll
    for (int j = 0; j < 16; j++) a += (hid[j] + hid[16 + j]) * w2[t * 16 + j];
    g_cab[b * CCH + t] = sigmoidf_(a);
}

// ---------------- spatial map: mean/max over channels of x*ca ----------------
__global__ void smap_kernel() {
    int gid  = blockIdx.x * blockDim.x + threadIdx.x;
    int warp = gid >> 5, lane = gid & 31;
    if (warp >= MTOT) return;
    int b = warp >> 12;
    const float* row = g_x + (size_t)warp * CCH;
    const float* ca  = g_cab + b * CCH;
    float4 a = ((const float4*)row)[lane*2];
    float4 c4 = ((const float4*)ca)[lane*2];
    float4 b4 = ((const float4*)row)[lane*2+1];
    float4 d4 = ((const float4*)ca)[lane*2+1];
    float v0=a.x*c4.x, v1=a.y*c4.y, v2=a.z*c4.z, v3=a.w*c4.w;
    float v4=b4.x*d4.x, v5=b4.y*d4.y, v6=b4.z*d4.z, v7=b4.w*d4.w;
    float s = v0+v1+v2+v3+v4+v5+v6+v7;
    float m = fmaxf(fmaxf(fmaxf(v0,v1),fmaxf(v2,v3)), fmaxf(fmaxf(v4,v5),fmaxf(v6,v7)));
    #pragma unroll
    for (int off = 16; off; off >>= 1) {
        s += __shfl_xor_sync(0xffffffffu, s, off);
        m = fmaxf(m, __shfl_xor_sync(0xffffffffu, m, off));
    }
    if (lane == 0) {
        g_smean[warp] = s * (1.0f / CCH);
        g_smax[warp]  = m;
    }
}

// ---------------- spatial attention 7x7 conv + sigmoid ----------------
__global__ void sa_kernel(const float* __restrict__ sp_w, const float* __restrict__ sp_b) {
    int idx = blockIdx.x * blockDim.x + threadIdx.x;   // b*N+n
    int b = idx >> 12, n = idx & 4095;
    int h = n >> 6, w = n & 63;
    float acc = sp_b[0];
    for (int kh = 0; kh < 7; kh++) {
        int hh = h + kh - 3;
        if (hh < 0 || hh >= HHH) continue;
        for (int kw = 0; kw < 7; kw++) {
            int ww = w + kw - 3;
            if (ww < 0 || ww >= WWW) continue;
            int nn = b * NNN + hh * 64 + ww;
            acc += g_smean[nn] * sp_w[kh*7 + kw] + g_smax[nn] * sp_w[49 + kh*7 + kw];
        }
    }
    g_sa[idx] = sigmoidf_(acc);
}

// ---------------- final: out = x * ca * sa ----------------
__global__ void final_kernel(float* __restrict__ out) {
    int gid = blockIdx.x * blockDim.x + threadIdx.x;
    size_t idx4 = (size_t)gid * 4;
    int row = (int)(idx4 >> 8);
    int c   = (int)(idx4 & 255);
    int b   = row >> 12;
    float sa = g_sa[row];
    float4 ca = *(const float4*)(g_cab + b * CCH + c);
    float4 xv = *(const float4*)(g_x + idx4);
    float4 o;
    o.x = xv.x * ca.x * sa; o.y = xv.y * ca.y * sa;
    o.z = xv.z * ca.z * sa; o.w = xv.w * ca.w * sa;
    *(float4*)(out + idx4) = o;
}

// ---------------- launch ----------------
extern "C" void kernel_launch(void* const* d_in, const int* in_sizes, int n_in,
                              void* d_out, int out_size) {
    const float* x      = (const float*)d_in[0];
    const float* n1_g   = (const float*)d_in[3];
    const float* n1_b   = (const float*)d_in[4];
    const float* sr_w   = (const float*)d_in[5];
    const float* sr_b   = (const float*)d_in[6];
    const float* an_g   = (const float*)d_in[7];
    const float* an_b   = (const float*)d_in[8];
    const float* qkv_w  = (const float*)d_in[9];
    const float* proj_w = (const float*)d_in[10];
    const float* proj_b = (const float*)d_in[11];
    const float* n2_g   = (const float*)d_in[12];
    const float* n2_b   = (const float*)d_in[13];
    const float* fc1_w  = (const float*)d_in[14];
    const float* fc1_b  = (const float*)d_in[15];
    const float* dw_w   = (const float*)d_in[16];
    const float* dw_b   = (const float*)d_in[17];
    const float* fc2_w  = (const float*)d_in[18];
    const float* fc2_b  = (const float*)d_in[19];
    const float* ca_w1  = (const float*)d_in[20];
    const float* ca_w2  = (const float*)d_in[21];
    const float* sp_w   = (const float*)d_in[22];
    const float* sp_b   = (const float*)d_in[23];
    float* out = (float*)d_out;

    float *p_xn, *p_q, *p_x;
    __nv_bfloat16 *p_kbf, *p_vbf, *p_h1bf, *p_xabf, *p_xnbf, *p_attnbf, *p_h2bf;
    __nv_bfloat16 *p_wqkv, *p_wproj, *p_wfc1, *p_wfc2;
    cudaGetSymbolAddress((void**)&p_xn,    g_xn);
    cudaGetSymbolAddress((void**)&p_q,     g_q);
    cudaGetSymbolAddress((void**)&p_x,     g_x);
    cudaGetSymbolAddress((void**)&p_kbf,   g_kbf);
    cudaGetSymbolAddress((void**)&p_vbf,   g_vbf);
    cudaGetSymbolAddress((void**)&p_h1bf,  g_h1bf);
    cudaGetSymbolAddress((void**)&p_xabf,  g_xabf);
    cudaGetSymbolAddress((void**)&p_xnbf,  g_xnbf);
    cudaGetSymbolAddress((void**)&p_attnbf,g_attnbf);
    cudaGetSymbolAddress((void**)&p_h2bf,  g_h2bf);
    cudaGetSymbolAddress((void**)&p_wqkv,  g_wqkv);
    cudaGetSymbolAddress((void**)&p_wproj, g_wproj);
    cudaGetSymbolAddress((void**)&p_wfc1,  g_wfc1);
    cudaGetSymbolAddress((void**)&p_wfc2,  g_wfc2);

    cudaFuncSetAttribute(gemm_bf16<0,false>, cudaFuncAttributeMaxDynamicSharedMemorySize, GEMM_DSMEM);
    cudaFuncSetAttribute(gemm_bf16<0,true >, cudaFuncAttributeMaxDynamicSharedMemorySize, GEMM_DSMEM);
    cudaFuncSetAttribute(gemm_bf16<1,true >, cudaFuncAttributeMaxDynamicSharedMemorySize, GEMM_DSMEM);
    cudaFuncSetAttribute(gemm_bf16<2,false>, cudaFuncAttributeMaxDynamicSharedMemorySize, GEMM_DSMEM);
    cudaFuncSetAttribute(gemm_bf16<3,false>, cudaFuncAttributeMaxDynamicSharedMemorySize, GEMM_DSMEM);

    init_kernel<<<512, 256>>>();
    cvt_all_kernel<<<(NW_TOT+255)/256, 256>>>(qkv_w, proj_w, fc1_w, fc2_w);

    // --- attention branch ---
    ln_kernel<false><<<MTOT/8, 256>>>(x, n1_g, n1_b, p_xn, nullptr);
    sr_an_kernel<<<MTOT, 256>>>(sr_w, sr_b, an_g, an_b);
    // qkv split into three 256-col GEMMs: q fp32, k bf16, v bf16
    gemm_bf16<0,false><<<dim3(2, MTOT/128), 256, GEMM_DSMEM>>>(p_xabf, p_wqkv,
        nullptr, nullptr, nullptr, p_q, 256, 256);
    gemm_bf16<0,true><<<dim3(2, MTOT/128), 256, GEMM_DSMEM>>>(p_xabf, p_wqkv + 256*256,
        nullptr, nullptr, nullptr, p_kbf, 256, 256);
    gemm_bf16<0,true><<<dim3(2, MTOT/128), 256, GEMM_DSMEM>>>(p_xabf, p_wqkv + 512*256,
        nullptr, nullptr, nullptr, p_vbf, 256, 256);
    qstats_kernel<<<dim3(32, BB), 256>>>();
    qfinal_kernel<<<BB, 256>>>();
    ctx_kernel<<<dim3(8, BB*NHEAD), 256>>>();
    attn_kernel<<<MTOT/64, 256>>>();
    gemm_bf16<2,false><<<dim3(2, MTOT/128), 256, GEMM_DSMEM>>>(p_attnbf, p_wproj, proj_b,
        p_xn, x, p_x, 256, 256);

    // --- MixFFN ---
    ln_kernel<true><<<MTOT/8, 256>>>(p_x, n2_g, n2_b, nullptr, p_xnbf);
    gemm_bf16<1,true><<<dim3(8, MTOT/128), 256, GEMM_DSMEM>>>(p_xnbf, p_wfc1, fc1_b,
        nullptr, nullptr, p_h1bf, 1024, 256);
    dw_kernel<<<dim3(64, 16, 16), 256>>>(dw_w, dw_b);
    gemm_bf16<3,false><<<dim3(2, MTOT/128), 256, GEMM_DSMEM>>>(p_h2bf, p_wfc2, fc2_b,
        p_x, nullptr, p_x, 256, 1024);

    // --- CSDA ---
    avgmax_kernel<<<dim3(32, BB), 256>>>();
    ca_kernel<<<BB, 256>>>(ca_w1, ca_w2);
    smap_kernel<<<MTOT/8, 256>>>();
    sa_kernel<<<MTOT/256, 256>>>(sp_w, sp_b);
    final_kernel<<<(MTOT*CCH/4)/256, 256>>>(out);
}

// round 11
// speedup vs baseline: 3.4542x; 1.0328x over previous
#include <cuda_runtime.h>
#include <cuda_bf16.h>
#include <math.h>
#include <stdint.h>

// ---------------- problem constants ----------------
#define BB    16
#define NNN   4096
#define CCH   256
#define HHH   64
#define WWW   64
#define HIDD  1024
#define NHEAD 8
#define HDIM  32
#define MTOT  (BB*NNN)          // 65536 rows

// ---------------- scratch (device globals; no allocs allowed) ----------------
__device__ float g_xn  [MTOT*CCH];            // ln1 out (fp32, reused for residuals)
__device__ float g_q   [MTOT*CCH];            // q (fp32 for softmax precision)
__device__ float g_x   [MTOT*CCH];            // trunk fp32 (also sr-conv scratch early)
__device__ __nv_bfloat16 g_kbf   [MTOT*CCH];  // k bf16
__device__ __nv_bfloat16 g_vbf   [MTOT*CCH];  // v bf16
__device__ __nv_bfloat16 g_h1bf  [MTOT*HIDD]; // fc1 out bf16
__device__ __nv_bfloat16 g_xabf  [MTOT*CCH];  // attn-branch gemm A
__device__ __nv_bfloat16 g_xnbf  [MTOT*CCH];  // ln2 out (fc1 A)
__device__ __nv_bfloat16 g_attnbf[MTOT*CCH];  // proj A
__device__ __nv_bfloat16 g_h2bf  [MTOT*HIDD]; // fc2 A
__device__ __nv_bfloat16 g_wqkv [3*CCH*CCH];
__device__ __nv_bfloat16 g_wproj[CCH*CCH];
__device__ __nv_bfloat16 g_wfc1 [HIDD*CCH];
__device__ __nv_bfloat16 g_wfc2 [CCH*HIDD];
__device__ float g_ctx [BB*NHEAD*HDIM*HDIM];
__device__ float g_qpm [BB*32*CCH];
__device__ float g_qps [BB*32*CCH];
__device__ float g_qmax[BB*CCH];
__device__ float g_qsum[BB*CCH];
__device__ float g_avg [BB*CCH];
__device__ float g_mx  [BB*CCH];
__device__ float g_cab [BB*CCH];
__device__ float g_smean[MTOT];
__device__ float g_smax [MTOT];
__device__ float g_sa   [MTOT];

// ---------------- helpers ----------------
__device__ __forceinline__ float geluf(float x) {
    return 0.5f * x * (1.0f + erff(x * 0.70710678118654752f));
}
__device__ __forceinline__ float sigmoidf_(float x) {
    return 1.0f / (1.0f + expf(-x));
}
__device__ __forceinline__ void atomicMaxF(float* addr, float v) {
    int* ai = (int*)addr;
    int old = *ai;
    while (__int_as_float(old) < v) {
        int prev = atomicCAS(ai, old, __float_as_int(v));
        if (prev == old) break;
        old = prev;
    }
}

// ---------------- init (per-call, deterministic reset) ----------------
__global__ void init_kernel() {
    int i = blockIdx.x * blockDim.x + threadIdx.x;
    if (i < BB*NHEAD*HDIM*HDIM) g_ctx[i] = 0.f;
    if (i < BB*CCH) {
        g_avg[i]  = 0.f;
        g_mx[i]   = -1e30f;
    }
}

// ---------------- fp32 -> bf16 weight convert (all weights, one launch) ------
#define NW_QKV  (3*CCH*CCH)
#define NW_PROJ (CCH*CCH)
#define NW_FC1  (HIDD*CCH)
#define NW_FC2  (CCH*HIDD)
#define NW_TOT  (NW_QKV + NW_PROJ + NW_FC1 + NW_FC2)

__global__ void cvt_all_kernel(const float* __restrict__ qkv_w,
                               const float* __restrict__ proj_w,
                               const float* __restrict__ fc1_w,
                               const float* __restrict__ fc2_w) {
    int i = blockIdx.x * blockDim.x + threadIdx.x;
    if (i < NW_QKV) { g_wqkv[i] = __float2bfloat16(qkv_w[i]); return; }
    int j = i - NW_QKV;
    if (j < NW_PROJ) { g_wproj[j] = __float2bfloat16(proj_w[j]); return; }
    j -= NW_PROJ;
    if (j < NW_FC1) { g_wfc1[j] = __float2bfloat16(fc1_w[j]); return; }
    j -= NW_FC1;
    if (j < NW_FC2) { g_wfc2[j] = __float2bfloat16(fc2_w[j]); }
}

// ---------------- LayerNorm over C=256, one warp per row ----------------
template<bool BFOUT>
__global__ void ln_kernel(const float* __restrict__ in,
                          const float* __restrict__ gg,
                          const float* __restrict__ bb,
                          float* __restrict__ out,
                          __nv_bfloat16* __restrict__ outbf) {
    int gid  = blockIdx.x * blockDim.x + threadIdx.x;
    int warp = gid >> 5;
    int lane = gid & 31;
    if (warp >= MTOT) return;
    const float* row = in + (size_t)warp * CCH;
    float4 a = ((const float4*)row)[lane*2];
    float4 b = ((const float4*)row)[lane*2+1];
    float s1 = a.x+a.y+a.z+a.w + b.x+b.y+b.z+b.w;
    float s2 = a.x*a.x+a.y*a.y+a.z*a.z+a.w*a.w + b.x*b.x+b.y*b.y+b.z*b.z+b.w*b.w;
    #pragma unroll
    for (int off = 16; off; off >>= 1) {
        s1 += __shfl_xor_sync(0xffffffffu, s1, off);
        s2 += __shfl_xor_sync(0xffffffffu, s2, off);
    }
    float mean = s1 * (1.0f/CCH);
    float var  = s2 * (1.0f/CCH) - mean*mean;
    float rstd = rsqrtf(var + 1e-5f);
    float4 g0 = ((const float4*)gg)[lane*2];
    float4 g1 = ((const float4*)gg)[lane*2+1];
    float4 b0 = ((const float4*)bb)[lane*2];
    float4 b1 = ((const float4*)bb)[lane*2+1];
    float4 o0, o1;
    o0.x=(a.x-mean)*rstd*g0.x+b0.x; o0.y=(a.y-mean)*rstd*g0.y+b0.y;
    o0.z=(a.z-mean)*rstd*g0.z+b0.z; o0.w=(a.w-mean)*rstd*g0.w+b0.w;
    o1.x=(b.x-mean)*rstd*g1.x+b1.x; o1.y=(b.y-mean)*rstd*g1.y+b1.y;
    o1.z=(b.z-mean)*rstd*g1.z+b1.z; o1.w=(b.w-mean)*rstd*g1.w+b1.w;
    if (BFOUT) {
        union { __nv_bfloat162 h[4]; uint4 u; } pk;
        pk.h[0]=__float22bfloat162_rn(make_float2(o0.x,o0.y));
        pk.h[1]=__float22bfloat162_rn(make_float2(o0.z,o0.w));
        pk.h[2]=__float22bfloat162_rn(make_float2(o1.x,o1.y));
        pk.h[3]=__float22bfloat162_rn(make_float2(o1.z,o1.w));
        ((uint4*)(outbf + (size_t)warp*CCH))[lane] = pk.u;
    } else {
        float* orow = out + (size_t)warp * CCH;
        ((float4*)orow)[lane*2]   = o0;
        ((float4*)orow)[lane*2+1] = o1;
    }
}

// ---------------- sr dwconv 3x3, tiled (writes fp32 conv out into g_x) -------
__global__ void __launch_bounds__(256) sr_conv_kernel(const float* __restrict__ sr_w,
                                                      const float* __restrict__ sr_b) {
    __shared__ float s[10*10*64];
    int tile = blockIdx.x;            // 0..63 : 8x8 grid of 8x8 tiles
    int cc = blockIdx.y;              // 0..3 : 64-ch chunks
    int b = blockIdx.z;
    int th0 = (tile >> 3) * 8, tw0 = (tile & 7) * 8;
    int t = threadIdx.x;
    int c0 = cc * 64;
    for (int l = t; l < 6400; l += 256) {
        int lh = l / 640, rem = l % 640, lw = rem / 64, lc = rem % 64;
        int gh = th0 + lh - 1, gw = tw0 + lw - 1;
        float v = 0.f;
        if (gh >= 0 && gh < HHH && gw >= 0 && gw < WWW)
            v = g_xn[((size_t)((b << 12) + (gh << 6) + gw) << 8) + c0 + lc];
        s[l] = v;
    }
    __syncthreads();
    int oc = t & 63;
    int cg = c0 + oc;
    float wt[9];
    #pragma unroll
    for (int k = 0; k < 9; k++) wt[k] = sr_w[cg*9 + k];
    float bias = sr_b[cg];
    for (int o = t; o < 4096; o += 256) {
        int oh = o >> 9, ow = (o >> 6) & 7;
        float acc = bias;
        #pragma unroll
        for (int kh = 0; kh < 3; kh++)
            #pragma unroll
            for (int kw = 0; kw < 3; kw++)
                acc += s[(oh + kh)*640 + (ow + kw)*64 + oc] * wt[kh*3 + kw];
        size_t row = (size_t)((b << 12) + ((th0 + oh) << 6) + (tw0 + ow));
        g_x[(row << 8) + cg] = acc;
    }
}

// ---------------- LN(conv) + gelu + residual(xn) -> xa bf16, warp per row ----
__global__ void sr_ln_kernel(const float* __restrict__ an_g, const float* __restrict__ an_b) {
    int gid  = blockIdx.x * blockDim.x + threadIdx.x;
    int warp = gid >> 5;
    int lane = gid & 31;
    if (warp >= MTOT) return;
    const float* row = g_x + (size_t)warp * CCH;
    float4 a = ((const float4*)row)[lane*2];
    float4 b = ((const float4*)row)[lane*2+1];
    float s1 = a.x+a.y+a.z+a.w + b.x+b.y+b.z+b.w;
    float s2 = a.x*a.x+a.y*a.y+a.z*a.z+a.w*a.w + b.x*b.x+b.y*b.y+b.z*b.z+b.w*b.w;
    #pragma unroll
    for (int off = 16; off; off >>= 1) {
        s1 += __shfl_xor_sync(0xffffffffu, s1, off);
        s2 += __shfl_xor_sync(0xffffffffu, s2, off);
    }
    float mean = s1 * (1.0f/CCH);
    float var  = s2 * (1.0f/CCH) - mean*mean;
    float rstd = rsqrtf(var + 1e-5f);
    float4 g0 = ((const float4*)an_g)[lane*2];
    float4 g1 = ((const float4*)an_g)[lane*2+1];
    float4 b0 = ((const float4*)an_b)[lane*2];
    float4 b1 = ((const float4*)an_b)[lane*2+1];
    const float* xnrow = g_xn + (size_t)warp * CCH;
    float4 x0 = ((const float4*)xnrow)[lane*2];
    float4 x1 = ((const float4*)xnrow)[lane*2+1];
    float o0 = x0.x + geluf((a.x-mean)*rstd*g0.x+b0.x);
    float o1 = x0.y + geluf((a.y-mean)*rstd*g0.y+b0.y);
    float o2 = x0.z + geluf((a.z-mean)*rstd*g0.z+b0.z);
    float o3 = x0.w + geluf((a.w-mean)*rstd*g0.w+b0.w);
    float o4 = x1.x + geluf((b.x-mean)*rstd*g1.x+b1.x);
    float o5 = x1.y + geluf((b.y-mean)*rstd*g1.y+b1.y);
    float o6 = x1.z + geluf((b.z-mean)*rstd*g1.z+b1.z);
    float o7 = x1.w + geluf((b.w-mean)*rstd*g1.w+b1.w);
    union { __nv_bfloat162 h[4]; uint4 u; } pk;
    pk.h[0]=__float22bfloat162_rn(make_float2(o0,o1));
    pk.h[1]=__float22bfloat162_rn(make_float2(o2,o3));
    pk.h[2]=__float22bfloat162_rn(make_float2(o4,o5));
    pk.h[3]=__float22bfloat162_rn(make_float2(o6,o7));
    ((uint4*)(g_xabf + (size_t)warp*CCH))[lane] = pk.u;
}

// ---------------- bf16 tensor-core GEMM (BK=64, 3-stage cp.async ring) -------
// out[M,Nout] = A[M,K]bf16 @ Wt[Nout,K]bf16^T (+epi)
// EPI: 0 none, 1 +bias, 2 +bias+add1+add2, 3 +bias+add1
#define SAST 72
#define NSTAGE 3
#define STG_ELEMS (128*SAST)
#define GEMM_DSMEM (NSTAGE * STG_ELEMS * 2 * 2)

__device__ __forceinline__ void ldsm4(unsigned& r0, unsigned& r1, unsigned& r2, unsigned& r3,
                                      const __nv_bfloat16* p) {
    unsigned addr = (unsigned)__cvta_generic_to_shared(p);
    asm volatile("ldmatrix.sync.aligned.m8n8.x4.shared.b16 {%0,%1,%2,%3}, [%4];"
                 : "=r"(r0), "=r"(r1), "=r"(r2), "=r"(r3) : "r"(addr));
}
__device__ __forceinline__ void mma_bf16(float* d, const unsigned* a, const unsigned* b) {
    asm volatile(
        "mma.sync.aligned.m16n8k16.row.col.f32.bf16.bf16.f32 "
        "{%0,%1,%2,%3}, {%4,%5,%6,%7}, {%8,%9}, {%0,%1,%2,%3};"
        : "+f"(d[0]), "+f"(d[1]), "+f"(d[2]), "+f"(d[3])
        : "r"(a[0]), "r"(a[1]), "r"(a[2]), "r"(a[3]), "r"(b[0]), "r"(b[1]));
}
__device__ __forceinline__ void cpasync16(unsigned saddr, const __nv_bfloat16* src) {
    asm volatile("cp.async.cg.shared.global [%0], [%1], 16;" :: "r"(saddr), "l"(src));
}

template<int EPI, bool BFOUT>
__global__ void __launch_bounds__(256, 2)
gemm_bf16(const __nv_bfloat16* __restrict__ A, const __nv_bfloat16* __restrict__ Wt,
          const float* __restrict__ bias,
          const float* __restrict__ add1, const float* __restrict__ add2,
          void* __restrict__ outp, int Nout, int K) {
    extern __shared__ __nv_bfloat16 smbuf[];
    __nv_bfloat16* As = smbuf;
    __nv_bfloat16* Bs = smbuf + NSTAGE * STG_ELEMS;
    const unsigned As_s = (unsigned)__cvta_generic_to_shared(As);
    const unsigned Bs_s = (unsigned)__cvta_generic_to_shared(Bs);

    const int t = threadIdx.x;
    const int warp = t >> 5, lane = t & 31;
    const int wm = (warp & 3) * 32;
    const int wn = (warp >> 2) * 64;
    const int grp = lane >> 2;
    const int kq  = lane & 3;
    const int row0 = blockIdx.y * 128;
    const int col0 = blockIdx.x * 128;

    const int a_row = (lane & 7) + ((lane >> 3) & 1) * 8;
    const int a_kof = (lane >> 4) * 8;
    const int b_row = (lane & 7) + (lane >> 4) * 8;
    const int b_kof = ((lane >> 3) & 1) * 8;

    float acc[2][8][4];
    #pragma unroll
    for (int i = 0; i < 2; i++)
        #pragma unroll
        for (int j = 0; j < 8; j++)
            #pragma unroll
            for (int q = 0; q < 4; q++) acc[i][j][q] = 0.f;

    const int ntiles = K >> 6;   // BK=64

    #pragma unroll
    for (int s = 0; s < 2; s++) {
        if (s < ntiles) {
            int kg = s << 6;
            #pragma unroll
            for (int cpart = 0; cpart < 4; cpart++) {
                int ch = t + cpart * 256;
                int r = ch >> 3, sc = (ch & 7) * 8;
                unsigned so = (unsigned)(s * STG_ELEMS + r * SAST + sc) * 2;
                cpasync16(As_s + so, A  + (size_t)(row0 + r) * K + kg + sc);
                cpasync16(Bs_s + so, Wt + (size_t)(col0 + r) * K + kg + sc);
            }
        }
        asm volatile("cp.async.commit_group;");
    }

    for (int kt = 0; kt < ntiles; kt++) {
        if (kt == ntiles - 1) asm volatile("cp.async.wait_group 0;");
        else                  asm volatile("cp.async.wait_group 1;");
        __syncthreads();
        if (kt + 2 < ntiles) {
            int st = (kt + 2) % NSTAGE;
            int kg = (kt + 2) << 6;
            #pragma unroll
            for (int cpart = 0; cpart < 4; cpart++) {
                int ch = t + cpart * 256;
                int r = ch >> 3, sc = (ch & 7) * 8;
                unsigned so = (unsigned)(st * STG_ELEMS + r * SAST + sc) * 2;
                cpasync16(As_s + so, A  + (size_t)(row0 + r) * K + kg + sc);
                cpasync16(Bs_s + so, Wt + (size_t)(col0 + r) * K + kg + sc);
            }
            asm volatile("cp.async.commit_group;");
        } else {
            asm volatile("cp.async.commit_group;");
        }
        const int sb = (kt % NSTAGE) * STG_ELEMS;
        #pragma unroll
        for (int s = 0; s < 4; s++) {
            const int kb = s * 16;
            unsigned af[2][4], bf[4][4];
            #pragma unroll
            for (int i = 0; i < 2; i++)
                ldsm4(af[i][0], af[i][1], af[i][2], af[i][3],
                      &As[sb + (wm + i*16 + a_row)*SAST + kb + a_kof]);
            #pragma unroll
            for (int j2 = 0; j2 < 4; j2++)
                ldsm4(bf[j2][0], bf[j2][1], bf[j2][2], bf[j2][3],
                      &Bs[sb + (wn + j2*16 + b_row)*SAST + kb + b_kof]);
            #pragma unroll
            for (int i = 0; i < 2; i++)
                #pragma unroll
                for (int j = 0; j < 8; j++)
                    mma_bf16(acc[i][j], af[i], &bf[j >> 1][(j & 1) * 2]);
        }
    }

    #pragma unroll
    for (int i = 0; i < 2; i++) {
        int r_lo = row0 + wm + i * 16 + grp;
        #pragma unroll
        for (int j = 0; j < 8; j++) {
            int cidx = col0 + wn + j * 8 + kq * 2;
            float bv0 = 0.f, bv1 = 0.f;
            if (EPI >= 1) { bv0 = bias[cidx]; bv1 = bias[cidx + 1]; }
            size_t o_lo = (size_t)r_lo * Nout + cidx;
            size_t o_hi = o_lo + (size_t)8 * Nout;
            float v0 = acc[i][j][0] + bv0;
            float v1 = acc[i][j][1] + bv1;
            float v2 = acc[i][j][2] + bv0;
            float v3 = acc[i][j][3] + bv1;
            if (EPI == 2) {
                v0 += add1[o_lo] + add2[o_lo];
                v1 += add1[o_lo + 1] + add2[o_lo + 1];
                v2 += add1[o_hi] + add2[o_hi];
                v3 += add1[o_hi + 1] + add2[o_hi + 1];
            }
            if (EPI == 3) {
                v0 += add1[o_lo];     v1 += add1[o_lo + 1];
                v2 += add1[o_hi];     v3 += add1[o_hi + 1];
            }
            if (BFOUT) {
                __nv_bfloat16* ob = (__nv_bfloat16*)outp;
                *(__nv_bfloat162*)(ob + o_lo) = __float22bfloat162_rn(make_float2(v0, v1));
                *(__nv_bfloat162*)(ob + o_hi) = __float22bfloat162_rn(make_float2(v2, v3));
            } else {
                float* of = (float*)outp;
                *(float2*)(of + o_lo) = make_float2(v0, v1);
                *(float2*)(of + o_hi) = make_float2(v2, v3);
            }
        }
    }
}

// ---------------- q stats: online per-chunk max/sumexp + reduce ----------------
__global__ void qstats_kernel() {
    int b = blockIdx.y, chunk = blockIdx.x, c = threadIdx.x;
    float m = -1e30f, s = 0.f;
    int base = b * NNN + chunk * 128;
    for (int r = 0; r < 128; r++) {
        float v = g_q[(size_t)(base + r) * CCH + c];
        if (v > m) { s = s * expf(m - v) + 1.f; m = v; }
        else s += expf(v - m);
    }
    g_qpm[(b*32 + chunk)*CCH + c] = m;
    g_qps[(b*32 + chunk)*CCH + c] = s;
}
__global__ void qfinal_kernel() {
    int b = blockIdx.x, c = threadIdx.x;
    float m = -1e30f;
    for (int k = 0; k < 32; k++) m = fmaxf(m, g_qpm[(b*32 + k)*CCH + c]);
    float s = 0.f;
    for (int k = 0; k < 32; k++) s += g_qps[(b*32 + k)*CCH + c] * expf(g_qpm[(b*32 + k)*CCH + c] - m);
    g_qmax[b*CCH + c] = m;
    g_qsum[b*CCH + c] = s;
}

// ---------------- ctx = softmax_d(k)^T v  (fused k-softmax, bf16 in) ---------
__global__ void ctx_kernel() {
    int chunk = blockIdx.x;           // 0..7 : 512 rows each
    int bh = blockIdx.y;              // b*8+h
    int b = bh >> 3, h = bh & 7;
    int w = threadIdx.x >> 5, lane = threadIdx.x & 31;
    __shared__ float ks[32][33], vs[32][33];
    float acc[4] = {0.f, 0.f, 0.f, 0.f};
    int base = b * NNN + chunk * 512;
    for (int tile = 0; tile < 16; tile++) {
        #pragma unroll
        for (int rr = 0; rr < 4; rr++) {
            int rl = w * 4 + rr;
            size_t row = (size_t)(base + tile * 32 + rl);
            float kv = __bfloat162float(g_kbf[row * CCH + h * 32 + lane]);
            float mx = kv;
            #pragma unroll
            for (int off = 16; off; off >>= 1) mx = fmaxf(mx, __shfl_xor_sync(0xffffffffu, mx, off));
            float e = expf(kv - mx);
            float ss = e;
            #pragma unroll
            for (int off = 16; off; off >>= 1) ss += __shfl_xor_sync(0xffffffffu, ss, off);
            ks[rl][lane] = e / ss;
            vs[rl][lane] = __bfloat162float(g_vbf[row * CCH + h * 32 + lane]);
        }
        __syncthreads();
        for (int r = 0; r < 32; r++) {
            float vv = vs[r][lane];
            #pragma unroll
            for (int i = 0; i < 4; i++) acc[i] += ks[r][w*4 + i] * vv;
        }
        __syncthreads();
    }
    #pragma unroll
    for (int i = 0; i < 4; i++)
        atomicAdd(&g_ctx[bh * 1024 + (w*4 + i) * 32 + lane], acc[i]);
}

// ---------------- attn = softmax_N(q) @ ctx  (warp per head, bf16 out) -------
__global__ void attn_kernel() {
    int blk = blockIdx.x;             // 1024 blocks, 64 rows each
    int w = threadIdx.x >> 5, lane = threadIdx.x & 31;
    int b = blk >> 6;
    int h = w;
    float c[32];
    const float* cp = g_ctx + ((size_t)((b << 3) + h)) * 1024 + lane;
    #pragma unroll
    for (int d = 0; d < 32; d++) c[d] = cp[d * 32];
    float qm = g_qmax[b*CCH + h*32 + lane];
    float qi = 1.0f / g_qsum[b*CCH + h*32 + lane];
    int row0 = blk * 64;
    for (int r = 0; r < 64; r++) {
        size_t row = (size_t)(row0 + r);
        float qv = g_q[row * CCH + h*32 + lane];
        float qe = expf(qv - qm) * qi;
        float a0 = 0.f, a1 = 0.f;
        #pragma unroll
        for (int d = 0; d < 32; d += 2) {
            a0 += __shfl_sync(0xffffffffu, qe, d)     * c[d];
            a1 += __shfl_sync(0xffffffffu, qe, d + 1) * c[d + 1];
        }
        g_attnbf[row * CCH + h*32 + lane] = __float2bfloat16(a0 + a1);
    }
}

// ---------------- MixFFN dwconv 3x3 + gelu (tiled, bf16 in/out) --------------
__global__ void __launch_bounds__(256) dw_kernel(const float* __restrict__ dw_w,
                                                 const float* __restrict__ dw_b) {
    __shared__ float s[10*10*64];
    int tile = blockIdx.x;            // 0..63 : 8x8 grid of 8x8 tiles
    int cc = blockIdx.y;              // 0..15 : 64-ch chunks
    int b = blockIdx.z;
    int th0 = (tile >> 3) * 8, tw0 = (tile & 7) * 8;
    int t = threadIdx.x;
    int c0 = cc * 64;
    for (int l = t; l < 6400; l += 256) {
        int lh = l / 640, rem = l % 640, lw = rem / 64, lc = rem % 64;
        int gh = th0 + lh - 1, gw = tw0 + lw - 1;
        float v = 0.f;
        if (gh >= 0 && gh < HHH && gw >= 0 && gw < WWW)
            v = __bfloat162float(g_h1bf[(size_t)((b << 12) + (gh << 6) + gw) * HIDD + c0 + lc]);
        s[l] = v;
    }
    __syncthreads();
    int oc = t & 63;
    int cg = c0 + oc;
    float wt[9];
    #pragma unroll
    for (int k = 0; k < 9; k++) wt[k] = dw_w[cg*9 + k];
    float bias = dw_b[cg];
    for (int o = t; o < 4096; o += 256) {
        int oh = o >> 9, ow = (o >> 6) & 7;
        float acc = bias;
        #pragma unroll
        for (int kh = 0; kh < 3; kh++)
            #pragma unroll
            for (int kw = 0; kw < 3; kw++)
                acc += s[(oh + kh)*640 + (ow + kw)*64 + oc] * wt[kh*3 + kw];
        size_t row = (size_t)((b << 12) + ((th0 + oh) << 6) + (tw0 + ow));
        g_h2bf[row * HIDD + cg] = __float2bfloat16(geluf(acc));
    }
}

// ---------------- CSDA channel stats ----------------
__global__ void avgmax_kernel() {
    int b = blockIdx.y, chunk = blockIdx.x, c = threadIdx.x;
    float s = 0.f, m = -1e30f;
    int base = b * NNN + chunk * 128;
    for (int r = 0; r < 128; r++) {
        float v = g_x[(size_t)(base + r) * CCH + c];
        s += v; m = fmaxf(m, v);
    }
    atomicAdd(&g_avg[b * CCH + c], s);
    atomicMaxF(&g_mx[b * CCH + c], m);
}

__global__ void ca_kernel(const float* __restrict__ w1, const float* __restrict__ w2) {
    int b = blockIdx.x, t = threadIdx.x;
    __shared__ float sav[CCH], smx[CCH], hid[32];
    sav[t] = g_avg[b * CCH + t] * (1.0f / NNN);
    smx[t] = g_mx[b * CCH + t];
    __syncthreads();
    if (t < 16) {
        float a = 0.f;
        for (int c = 0; c < CCH; c++) a += sav[c] * w1[t * CCH + c];
        hid[t] = fmaxf(a, 0.f);
    } else if (t < 32) {
        int j = t - 16;
        float a = 0.f;
        for (int c = 0; c < CCH; c++) a += smx[c] * w1[j * CCH + c];
        hid[16 + j] = fmaxf(a, 0.f);
    }
    __syncthreads();
    float a = 0.f;
    #pragma unroll
    for (int j = 0; j < 16; j++) a += (hid[j] + hid[16 + j]) * w2[t * 16 + j];
    g_cab[b * CCH + t] = sigmoidf_(a);
}

// ---------------- spatial map: mean/max over channels of x*ca ----------------
__global__ void smap_kernel() {
    int gid  = blockIdx.x * blockDim.x + threadIdx.x;
    int warp = gid >> 5, lane = gid & 31;
    if (warp >= MTOT) return;
    int b = warp >> 12;
    const float* row = g_x + (size_t)warp * CCH;
    const float* ca  = g_cab + b * CCH;
    float4 a = ((const float4*)row)[lane*2];
    float4 c4 = ((const float4*)ca)[lane*2];
    float4 b4 = ((const float4*)row)[lane*2+1];
    float4 d4 = ((const float4*)ca)[lane*2+1];
    float v0=a.x*c4.x, v1=a.y*c4.y, v2=a.z*c4.z, v3=a.w*c4.w;
    float v4=b4.x*d4.x, v5=b4.y*d4.y, v6=b4.z*d4.z, v7=b4.w*d4.w;
    float s = v0+v1+v2+v3+v4+v5+v6+v7;
    float m = fmaxf(fmaxf(fmaxf(v0,v1),fmaxf(v2,v3)), fmaxf(fmaxf(v4,v5),fmaxf(v6,v7)));
    #pragma unroll
    for (int off = 16; off; off >>= 1) {
        s += __shfl_xor_sync(0xffffffffu, s, off);
        m = fmaxf(m, __shfl_xor_sync(0xffffffffu, m, off));
    }
    if (lane == 0) {
        g_smean[warp] = s * (1.0f / CCH);
        g_smax[warp]  = m;
    }
}

// ---------------- spatial attention 7x7 conv + sigmoid ----------------
__global__ void sa_kernel(const float* __restrict__ sp_w, const float* __restrict__ sp_b) {
    int idx = blockIdx.x * blockDim.x + threadIdx.x;   // b*N+n
    int b = idx >> 12, n = idx & 4095;
    int h = n >> 6, w = n & 63;
    float acc = sp_b[0];
    for (int kh = 0; kh < 7; kh++) {
        int hh = h + kh - 3;
        if (hh < 0 || hh >= HHH) continue;
        for (int kw = 0; kw < 7; kw++) {
            int ww = w + kw - 3;
            if (ww < 0 || ww >= WWW) continue;
            int nn = b * NNN + hh * 64 + ww;
            acc += g_smean[nn] * sp_w[kh*7 + kw] + g_smax[nn] * sp_w[49 + kh*7 + kw];
        }
    }
    g_sa[idx] = sigmoidf_(acc);
}

// ---------------- final: out = x * ca * sa ----------------
__global__ void final_kernel(float* __restrict__ out) {
    int gid = blockIdx.x * blockDim.x + threadIdx.x;
    size_t idx4 = (size_t)gid * 4;
    int row = (int)(idx4 >> 8);
    int c   = (int)(idx4 & 255);
    int b   = row >> 12;
    float sa = g_sa[row];
    float4 ca = *(const float4*)(g_cab + b * CCH + c);
    float4 xv = *(const float4*)(g_x + idx4);
    float4 o;
    o.x = xv.x * ca.x * sa; o.y = xv.y * ca.y * sa;
    o.z = xv.z * ca.z * sa; o.w = xv.w * ca.w * sa;
    *(float4*)(out + idx4) = o;
}

// ---------------- launch ----------------
extern "C" void kernel_launch(void* const* d_in, const int* in_sizes, int n_in,
                              void* d_out, int out_size) {
    const float* x      = (const float*)d_in[0];
    const float* n1_g   = (const float*)d_in[3];
    const float* n1_b   = (const float*)d_in[4];
    const float* sr_w   = (const float*)d_in[5];
    const float* sr_b   = (const float*)d_in[6];
    const float* an_g   = (const float*)d_in[7];
    const float* an_b   = (const float*)d_in[8];
    const float* qkv_w  = (const float*)d_in[9];
    const float* proj_w = (const float*)d_in[10];
    const float* proj_b = (const float*)d_in[11];
    const float* n2_g   = (const float*)d_in[12];
    const float* n2_b   = (const float*)d_in[13];
    const float* fc1_w  = (const float*)d_in[14];
    const float* fc1_b  = (const float*)d_in[15];
    const float* dw_w   = (const float*)d_in[16];
    const float* dw_b   = (const float*)d_in[17];
    const float* fc2_w  = (const float*)d_in[18];
    const float* fc2_b  = (const float*)d_in[19];
    const float* ca_w1  = (const float*)d_in[20];
    const float* ca_w2  = (const float*)d_in[21];
    const float* sp_w   = (const float*)d_in[22];
    const float* sp_b   = (const float*)d_in[23];
    float* out = (float*)d_out;

    float *p_xn, *p_q, *p_x;
    __nv_bfloat16 *p_kbf, *p_vbf, *p_h1bf, *p_xabf, *p_xnbf, *p_attnbf, *p_h2bf;
    __nv_bfloat16 *p_wqkv, *p_wproj, *p_wfc1, *p_wfc2;
    cudaGetSymbolAddress((void**)&p_xn,    g_xn);
    cudaGetSymbolAddress((void**)&p_q,     g_q);
    cudaGetSymbolAddress((void**)&p_x,     g_x);
    cudaGetSymbolAddress((void**)&p_kbf,   g_kbf);
    cudaGetSymbolAddress((void**)&p_vbf,   g_vbf);
    cudaGetSymbolAddress((void**)&p_h1bf,  g_h1bf);
    cudaGetSymbolAddress((void**)&p_xabf,  g_xabf);
    cudaGetSymbolAddress((void**)&p_xnbf,  g_xnbf);
    cudaGetSymbolAddress((void**)&p_attnbf,g_attnbf);
    cudaGetSymbolAddress((void**)&p_h2bf,  g_h2bf);
    cudaGetSymbolAddress((void**)&p_wqkv,  g_wqkv);
    cudaGetSymbolAddress((void**)&p_wproj, g_wproj);
    cudaGetSymbolAddress((void**)&p_wfc1,  g_wfc1);
    cudaGetSymbolAddress((void**)&p_wfc2,  g_wfc2);

    cudaFuncSetAttribute(gemm_bf16<0,false>, cudaFuncAttributeMaxDynamicSharedMemorySize, GEMM_DSMEM);
    cudaFuncSetAttribute(gemm_bf16<0,true >, cudaFuncAttributeMaxDynamicSharedMemorySize, GEMM_DSMEM);
    cudaFuncSetAttribute(gemm_bf16<1,true >, cudaFuncAttributeMaxDynamicSharedMemorySize, GEMM_DSMEM);
    cudaFuncSetAttribute(gemm_bf16<2,false>, cudaFuncAttributeMaxDynamicSharedMemorySize, GEMM_DSMEM);
    cudaFuncSetAttribute(gemm_bf16<3,false>, cudaFuncAttributeMaxDynamicSharedMemorySize, GEMM_DSMEM);

    init_kernel<<<512, 256>>>();
    cvt_all_kernel<<<(NW_TOT+255)/256, 256>>>(qkv_w, proj_w, fc1_w, fc2_w);

    // --- attention branch ---
    ln_kernel<false><<<MTOT/8, 256>>>(x, n1_g, n1_b, p_xn, nullptr);
    sr_conv_kernel<<<dim3(64, 4, 16), 256>>>(sr_w, sr_b);     // conv out -> g_x (scratch)
    sr_ln_kernel<<<MTOT/8, 256>>>(an_g, an_b);                // -> g_xabf
    // qkv split into three 256-col GEMMs: q fp32, k bf16, v bf16
    gemm_bf16<0,false><<<dim3(2, MTOT/128), 256, GEMM_DSMEM>>>(p_xabf, p_wqkv,
        nullptr, nullptr, nullptr, p_q, 256, 256);
    gemm_bf16<0,true><<<dim3(2, MTOT/128), 256, GEMM_DSMEM>>>(p_xabf, p_wqkv + 256*256,
        nullptr, nullptr, nullptr, p_kbf, 256, 256);
    gemm_bf16<0,true><<<dim3(2, MTOT/128), 256, GEMM_DSMEM>>>(p_xabf, p_wqkv + 512*256,
        nullptr, nullptr, nullptr, p_vbf, 256, 256);
    qstats_kernel<<<dim3(32, BB), 256>>>();
    qfinal_kernel<<<BB, 256>>>();
    ctx_kernel<<<dim3(8, BB*NHEAD), 256>>>();
    attn_kernel<<<MTOT/64, 256>>>();
    gemm_bf16<2,false><<<dim3(2, MTOT/128), 256, GEMM_DSMEM>>>(p_attnbf, p_wproj, proj_b,
        p_xn, x, p_x, 256, 256);

    // --- MixFFN ---
    ln_kernel<true><<<MTOT/8, 256>>>(p_x, n2_g, n2_b, nullptr, p_xnbf);
    gemm_bf16<1,true><<<dim3(8, MTOT/128), 256, GEMM_DSMEM>>>(p_xnbf, p_wfc1, fc1_b,
        nullptr, nullptr, p_h1bf, 1024, 256);
    dw_kernel<<<dim3(64, 16, 16), 256>>>(dw_w, dw_b);
    gemm_bf16<3,false><<<dim3(2, MTOT/128), 256, GEMM_DSMEM>>>(p_h2bf, p_wfc2, fc2_b,
        p_x, nullptr, p_x, 256, 1024);

    // --- CSDA ---
    avgmax_kernel<<<dim3(32, BB), 256>>>();
    ca_kernel<<<BB, 256>>>(ca_w1, ca_w2);
    smap_kernel<<<MTOT/8, 256>>>();
    sa_kernel<<<MTOT/256, 256>>>(sp_w, sp_b);
    final_kernel<<<(MTOT*CCH/4)/256, 256>>>(out);
}

// round 13
// speedup vs baseline: 3.6009x; 1.0425x over previous
#include <cuda_runtime.h>
#include <cuda_bf16.h>
#include <math.h>
#include <stdint.h>

// ---------------- problem constants ----------------
#define BB    16
#define NNN   4096
#define CCH   256
#define HHH   64
#define WWW   64
#define HIDD  1024
#define NHEAD 8
#define HDIM  32
#define MTOT  (BB*NNN)          // 65536 rows

// ---------------- scratch (device globals; no allocs allowed) ----------------
__device__ float g_xn  [MTOT*CCH];            // ln1 out (fp32, reused for residuals)
__device__ float g_q   [MTOT*CCH];            // q (fp32 for softmax precision)
__device__ float g_x   [MTOT*CCH];            // trunk fp32 (also sr-conv scratch early)
__device__ __nv_bfloat16 g_kvbf  [MTOT*2*CCH];// k (cols 0-255) + v (cols 256-511) bf16
__device__ __nv_bfloat16 g_h1bf  [MTOT*HIDD]; // fc1 out bf16
__device__ __nv_bfloat16 g_xabf  [MTOT*CCH];  // attn-branch gemm A
__device__ __nv_bfloat16 g_xnbf  [MTOT*CCH];  // ln2 out (fc1 A)
__device__ __nv_bfloat16 g_attnbf[MTOT*CCH];  // proj A
__device__ __nv_bfloat16 g_h2bf  [MTOT*HIDD]; // fc2 A
__device__ __nv_bfloat16 g_wqkv [3*CCH*CCH];
__device__ __nv_bfloat16 g_wproj[CCH*CCH];
__device__ __nv_bfloat16 g_wfc1 [HIDD*CCH];
__device__ __nv_bfloat16 g_wfc2 [CCH*HIDD];
__device__ float g_ctx [BB*NHEAD*HDIM*HDIM];
__device__ float g_qpm [BB*32*CCH];
__device__ float g_qps [BB*32*CCH];
__device__ float g_qmax[BB*CCH];
__device__ float g_qsum[BB*CCH];
__device__ float g_avg [BB*CCH];
__device__ float g_mx  [BB*CCH];
__device__ float g_cab [BB*CCH];
__device__ float g_smean[MTOT];
__device__ float g_smax [MTOT];
__device__ float g_sa   [MTOT];

// ---------------- helpers ----------------
__device__ __forceinline__ float geluf(float x) {
    return 0.5f * x * (1.0f + erff(x * 0.70710678118654752f));
}
__device__ __forceinline__ float sigmoidf_(float x) {
    return 1.0f / (1.0f + expf(-x));
}
__device__ __forceinline__ void atomicMaxF(float* addr, float v) {
    int* ai = (int*)addr;
    int old = *ai;
    while (__int_as_float(old) < v) {
        int prev = atomicCAS(ai, old, __float_as_int(v));
        if (prev == old) break;
        old = prev;
    }
}

// ---------------- init (per-call, deterministic reset) ----------------
__global__ void init_kernel() {
    int i = blockIdx.x * blockDim.x + threadIdx.x;
    if (i < BB*NHEAD*HDIM*HDIM) g_ctx[i] = 0.f;
    if (i < BB*CCH) {
        g_avg[i]  = 0.f;
        g_mx[i]   = -1e30f;
    }
}

// ---------------- fp32 -> bf16 weight convert (all weights, one launch) ------
#define NW_QKV  (3*CCH*CCH)
#define NW_PROJ (CCH*CCH)
#define NW_FC1  (HIDD*CCH)
#define NW_FC2  (CCH*HIDD)
#define NW_TOT  (NW_QKV + NW_PROJ + NW_FC1 + NW_FC2)

__global__ void cvt_all_kernel(const float* __restrict__ qkv_w,
                               const float* __restrict__ proj_w,
                               const float* __restrict__ fc1_w,
                               const float* __restrict__ fc2_w) {
    int i = blockIdx.x * blockDim.x + threadIdx.x;
    if (i < NW_QKV) { g_wqkv[i] = __float2bfloat16(qkv_w[i]); return; }
    int j = i - NW_QKV;
    if (j < NW_PROJ) { g_wproj[j] = __float2bfloat16(proj_w[j]); return; }
    j -= NW_PROJ;
    if (j < NW_FC1) { g_wfc1[j] = __float2bfloat16(fc1_w[j]); return; }
    j -= NW_FC1;
    if (j < NW_FC2) { g_wfc2[j] = __float2bfloat16(fc2_w[j]); }
}

// ---------------- LayerNorm over C=256, one warp per row ----------------
template<bool BFOUT>
__global__ void ln_kernel(const float* __restrict__ in,
                          const float* __restrict__ gg,
                          const float* __restrict__ bb,
                          float* __restrict__ out,
                          __nv_bfloat16* __restrict__ outbf) {
    int gid  = blockIdx.x * blockDim.x + threadIdx.x;
    int warp = gid >> 5;
    int lane = gid & 31;
    if (warp >= MTOT) return;
    const float* row = in + (size_t)warp * CCH;
    float4 a = ((const float4*)row)[lane*2];
    float4 b = ((const float4*)row)[lane*2+1];
    float s1 = a.x+a.y+a.z+a.w + b.x+b.y+b.z+b.w;
    float s2 = a.x*a.x+a.y*a.y+a.z*a.z+a.w*a.w + b.x*b.x+b.y*b.y+b.z*b.z+b.w*b.w;
    #pragma unroll
    for (int off = 16; off; off >>= 1) {
        s1 += __shfl_xor_sync(0xffffffffu, s1, off);
        s2 += __shfl_xor_sync(0xffffffffu, s2, off);
    }
    float mean = s1 * (1.0f/CCH);
    float var  = s2 * (1.0f/CCH) - mean*mean;
    float rstd = rsqrtf(var + 1e-5f);
    float4 g0 = ((const float4*)gg)[lane*2];
    float4 g1 = ((const float4*)gg)[lane*2+1];
    float4 b0 = ((const float4*)bb)[lane*2];
    float4 b1 = ((const float4*)bb)[lane*2+1];
    float4 o0, o1;
    o0.x=(a.x-mean)*rstd*g0.x+b0.x; o0.y=(a.y-mean)*rstd*g0.y+b0.y;
    o0.z=(a.z-mean)*rstd*g0.z+b0.z; o0.w=(a.w-mean)*rstd*g0.w+b0.w;
    o1.x=(b.x-mean)*rstd*g1.x+b1.x; o1.y=(b.y-mean)*rstd*g1.y+b1.y;
    o1.z=(b.z-mean)*rstd*g1.z+b1.z; o1.w=(b.w-mean)*rstd*g1.w+b1.w;
    if (BFOUT) {
        union { __nv_bfloat162 h[4]; uint4 u; } pk;
        pk.h[0]=__float22bfloat162_rn(make_float2(o0.x,o0.y));
        pk.h[1]=__float22bfloat162_rn(make_float2(o0.z,o0.w));
        pk.h[2]=__float22bfloat162_rn(make_float2(o1.x,o1.y));
        pk.h[3]=__float22bfloat162_rn(make_float2(o1.z,o1.w));
        ((uint4*)(outbf + (size_t)warp*CCH))[lane] = pk.u;
    } else {
        float* orow = out + (size_t)warp * CCH;
        ((float4*)orow)[lane*2]   = o0;
        ((float4*)orow)[lane*2+1] = o1;
    }
}

// ---------------- sr dwconv 3x3, tiled (writes fp32 conv out into g_x) -------
__global__ void __launch_bounds__(256) sr_conv_kernel(const float* __restrict__ sr_w,
                                                      const float* __restrict__ sr_b) {
    __shared__ float s[10*10*64];
    int tile = blockIdx.x;
    int cc = blockIdx.y;
    int b = blockIdx.z;
    int th0 = (tile >> 3) * 8, tw0 = (tile & 7) * 8;
    int t = threadIdx.x;
    int c0 = cc * 64;
    for (int l = t; l < 6400; l += 256) {
        int lh = l / 640, rem = l % 640, lw = rem / 64, lc = rem % 64;
        int gh = th0 + lh - 1, gw = tw0 + lw - 1;
        float v = 0.f;
        if (gh >= 0 && gh < HHH && gw >= 0 && gw < WWW)
            v = g_xn[((size_t)((b << 12) + (gh << 6) + gw) << 8) + c0 + lc];
        s[l] = v;
    }
    __syncthreads();
    int oc = t & 63;
    int cg = c0 + oc;
    float wt[9];
    #pragma unroll
    for (int k = 0; k < 9; k++) wt[k] = sr_w[cg*9 + k];
    float bias = sr_b[cg];
    for (int o = t; o < 4096; o += 256) {
        int oh = o >> 9, ow = (o >> 6) & 7;
        float acc = bias;
        #pragma unroll
        for (int kh = 0; kh < 3; kh++)
            #pragma unroll
            for (int kw = 0; kw < 3; kw++)
                acc += s[(oh + kh)*640 + (ow + kw)*64 + oc] * wt[kh*3 + kw];
        size_t row = (size_t)((b << 12) + ((th0 + oh) << 6) + (tw0 + ow));
        g_x[(row << 8) + cg] = acc;
    }
}

// ---------------- LN(conv) + gelu + residual(xn) -> xa bf16, warp per row ----
__global__ void sr_ln_kernel(const float* __restrict__ an_g, const float* __restrict__ an_b) {
    int gid  = blockIdx.x * blockDim.x + threadIdx.x;
    int warp = gid >> 5;
    int lane = gid & 31;
    if (warp >= MTOT) return;
    const float* row = g_x + (size_t)warp * CCH;
    float4 a = ((const float4*)row)[lane*2];
    float4 b = ((const float4*)row)[lane*2+1];
    float s1 = a.x+a.y+a.z+a.w + b.x+b.y+b.z+b.w;
    float s2 = a.x*a.x+a.y*a.y+a.z*a.z+a.w*a.w + b.x*b.x+b.y*b.y+b.z*b.z+b.w*b.w;
    #pragma unroll
    for (int off = 16; off; off >>= 1) {
        s1 += __shfl_xor_sync(0xffffffffu, s1, off);
        s2 += __shfl_xor_sync(0xffffffffu, s2, off);
    }
    float mean = s1 * (1.0f/CCH);
    float var  = s2 * (1.0f/CCH) - mean*mean;
    float rstd = rsqrtf(var + 1e-5f);
    float4 g0 = ((const float4*)an_g)[lane*2];
    float4 g1 = ((const float4*)an_g)[lane*2+1];
    float4 b0 = ((const float4*)an_b)[lane*2];
    float4 b1 = ((const float4*)an_b)[lane*2+1];
    const float* xnrow = g_xn + (size_t)warp * CCH;
    float4 x0 = ((const float4*)xnrow)[lane*2];
    float4 x1 = ((const float4*)xnrow)[lane*2+1];
    float o0 = x0.x + geluf((a.x-mean)*rstd*g0.x+b0.x);
    float o1 = x0.y + geluf((a.y-mean)*rstd*g0.y+b0.y);
    float o2 = x0.z + geluf((a.z-mean)*rstd*g0.z+b0.z);
    float o3 = x0.w + geluf((a.w-mean)*rstd*g0.w+b0.w);
    float o4 = x1.x + geluf((b.x-mean)*rstd*g1.x+b1.x);
    float o5 = x1.y + geluf((b.y-mean)*rstd*g1.y+b1.y);
    float o6 = x1.z + geluf((b.z-mean)*rstd*g1.z+b1.z);
    float o7 = x1.w + geluf((b.w-mean)*rstd*g1.w+b1.w);
    union { __nv_bfloat162 h[4]; uint4 u; } pk;
    pk.h[0]=__float22bfloat162_rn(make_float2(o0,o1));
    pk.h[1]=__float22bfloat162_rn(make_float2(o2,o3));
    pk.h[2]=__float22bfloat162_rn(make_float2(o4,o5));
    pk.h[3]=__float22bfloat162_rn(make_float2(o6,o7));
    ((uint4*)(g_xabf + (size_t)warp*CCH))[lane] = pk.u;
}

// ---------------- bf16 tensor-core GEMM (BK=64, 3-stage cp.async ring) -------
// out[M,Nout] = A[M,K]bf16 @ Wt[Nout,K]bf16^T (+epi)
// EPI: 0 none, 1 +bias, 2 +bias+add1+add2, 3 +bias+add1
// STATS: 0 none, 1 per-tile column softmax stats -> g_qpm/g_qps,
//        2 per-tile column sum/max -> atomic g_avg/g_mx
#define SAST 72
#define NSTAGE 3
#define STG_ELEMS (128*SAST)
#define GEMM_DSMEM (NSTAGE * STG_ELEMS * 2 * 2)

__device__ __forceinline__ void ldsm4(unsigned& r0, unsigned& r1, unsigned& r2, unsigned& r3,
                                      const __nv_bfloat16* p) {
    unsigned addr = (unsigned)__cvta_generic_to_shared(p);
    asm volatile("ldmatrix.sync.aligned.m8n8.x4.shared.b16 {%0,%1,%2,%3}, [%4];"
                 : "=r"(r0), "=r"(r1), "=r"(r2), "=r"(r3) : "r"(addr));
}
__device__ __forceinline__ void mma_bf16(float* d, const unsigned* a, const unsigned* b) {
    asm volatile(
        "mma.sync.aligned.m16n8k16.row.col.f32.bf16.bf16.f32 "
        "{%0,%1,%2,%3}, {%4,%5,%6,%7}, {%8,%9}, {%0,%1,%2,%3};"
        : "+f"(d[0]), "+f"(d[1]), "+f"(d[2]), "+f"(d[3])
        : "r"(a[0]), "r"(a[1]), "r"(a[2]), "r"(a[3]), "r"(b[0]), "r"(b[1]));
}
__device__ __forceinline__ void cpasync16(unsigned saddr, const __nv_bfloat16* src) {
    asm volatile("cp.async.cg.shared.global [%0], [%1], 16;" :: "r"(saddr), "l"(src));
}

template<int EPI, bool BFOUT, int STATS>
__global__ void __launch_bounds__(256, 2)
gemm_bf16(const __nv_bfloat16* __restrict__ A, const __nv_bfloat16* __restrict__ Wt,
          const float* __restrict__ bias,
          const float* __restrict__ add1, const float* __restrict__ add2,
          void* __restrict__ outp, int Nout, int K) {
    extern __shared__ __nv_bfloat16 smbuf[];
    __nv_bfloat16* As = smbuf;
    __nv_bfloat16* Bs = smbuf + NSTAGE * STG_ELEMS;
    const unsigned As_s = (unsigned)__cvta_generic_to_shared(As);
    const unsigned Bs_s = (unsigned)__cvta_generic_to_shared(Bs);

    const int t = threadIdx.x;
    const int warp = t >> 5, lane = t & 31;
    const int wm = (warp & 3) * 32;
    const int wn = (warp >> 2) * 64;
    const int grp = lane >> 2;
    const int kq  = lane & 3;
    const int row0 = blockIdx.y * 128;
    const int col0 = blockIdx.x * 128;

    const int a_row = (lane & 7) + ((lane >> 3) & 1) * 8;
    const int a_kof = (lane >> 4) * 8;
    const int b_row = (lane & 7) + (lane >> 4) * 8;
    const int b_kof = ((lane >> 3) & 1) * 8;

    float acc[2][8][4];
    #pragma unroll
    for (int i = 0; i < 2; i++)
        #pragma unroll
        for (int j = 0; j < 8; j++)
            #pragma unroll
            for (int q = 0; q < 4; q++) acc[i][j][q] = 0.f;

    const int ntiles = K >> 6;   // BK=64

    #pragma unroll
    for (int s = 0; s < 2; s++) {
        if (s < ntiles) {
            int kg = s << 6;
            #pragma unroll
            for (int cpart = 0; cpart < 4; cpart++) {
                int ch = t + cpart * 256;
                int r = ch >> 3, sc = (ch & 7) * 8;
                unsigned so = (unsigned)(s * STG_ELEMS + r * SAST + sc) * 2;
                cpasync16(As_s + so, A  + (size_t)(row0 + r) * K + kg + sc);
                cpasync16(Bs_s + so, Wt + (size_t)(col0 + r) * K + kg + sc);
            }
        }
        asm volatile("cp.async.commit_group;");
    }

    for (int kt = 0; kt < ntiles; kt++) {
        if (kt == ntiles - 1) asm volatile("cp.async.wait_group 0;");
        else                  asm volatile("cp.async.wait_group 1;");
        __syncthreads();
        if (kt + 2 < ntiles) {
            int st = (kt + 2) % NSTAGE;
            int kg = (kt + 2) << 6;
            #pragma unroll
            for (int cpart = 0; cpart < 4; cpart++) {
                int ch = t + cpart * 256;
                int r = ch >> 3, sc = (ch & 7) * 8;
                unsigned so = (unsigned)(st * STG_ELEMS + r * SAST + sc) * 2;
                cpasync16(As_s + so, A  + (size_t)(row0 + r) * K + kg + sc);
                cpasync16(Bs_s + so, Wt + (size_t)(col0 + r) * K + kg + sc);
            }
            asm volatile("cp.async.commit_group;");
        } else {
            asm volatile("cp.async.commit_group;");
        }
        const int sb = (kt % NSTAGE) * STG_ELEMS;
        #pragma unroll
        for (int s = 0; s < 4; s++) {
            const int kb = s * 16;
            unsigned af[2][4], bf[4][4];
            #pragma unroll
            for (int i = 0; i < 2; i++)
                ldsm4(af[i][0], af[i][1], af[i][2], af[i][3],
                      &As[sb + (wm + i*16 + a_row)*SAST + kb + a_kof]);
            #pragma unroll
            for (int j2 = 0; j2 < 4; j2++)
                ldsm4(bf[j2][0], bf[j2][1], bf[j2][2], bf[j2][3],
                      &Bs[sb + (wn + j2*16 + b_row)*SAST + kb + b_kof]);
            #pragma unroll
            for (int i = 0; i < 2; i++)
                #pragma unroll
                for (int j = 0; j < 8; j++)
                    mma_bf16(acc[i][j], af[i], &bf[j >> 1][(j & 1) * 2]);
        }
    }

    // per-column online stats for STATS==2 (values AFTER epilogue adds)
    float colsum[STATS == 2 ? 16 : 1];
    float colmax[STATS == 2 ? 16 : 1];
    if (STATS == 2) {
        #pragma unroll
        for (int idx = 0; idx < 16; idx++) { colsum[idx] = 0.f; colmax[idx] = -1e30f; }
    }

    #pragma unroll
    for (int i = 0; i < 2; i++) {
        int r_lo = row0 + wm + i * 16 + grp;
        #pragma unroll
        for (int j = 0; j < 8; j++) {
            int cidx = col0 + wn + j * 8 + kq * 2;
            float bv0 = 0.f, bv1 = 0.f;
            if (EPI >= 1) { bv0 = bias[cidx]; bv1 = bias[cidx + 1]; }
            size_t o_lo = (size_t)r_lo * Nout + cidx;
            size_t o_hi = o_lo + (size_t)8 * Nout;
            float v0 = acc[i][j][0] + bv0;
            float v1 = acc[i][j][1] + bv1;
            float v2 = acc[i][j][2] + bv0;
            float v3 = acc[i][j][3] + bv1;
            if (EPI == 2) {
                v0 += add1[o_lo] + add2[o_lo];
                v1 += add1[o_lo + 1] + add2[o_lo + 1];
                v2 += add1[o_hi] + add2[o_hi];
                v3 += add1[o_hi + 1] + add2[o_hi + 1];
            }
            if (EPI == 3) {
                v0 += add1[o_lo];     v1 += add1[o_lo + 1];
                v2 += add1[o_hi];     v3 += add1[o_hi + 1];
            }
            if (STATS == 2) {
                colsum[j*2+0] += v0 + v2;
                colsum[j*2+1] += v1 + v3;
                colmax[j*2+0] = fmaxf(colmax[j*2+0], fmaxf(v0, v2));
                colmax[j*2+1] = fmaxf(colmax[j*2+1], fmaxf(v1, v3));
            }
            if (BFOUT) {
                __nv_bfloat16* ob = (__nv_bfloat16*)outp;
                *(__nv_bfloat162*)(ob + o_lo) = __float22bfloat162_rn(make_float2(v0, v1));
                *(__nv_bfloat162*)(ob + o_hi) = __float22bfloat162_rn(make_float2(v2, v3));
            } else {
                float* of = (float*)outp;
                *(float2*)(of + o_lo) = make_float2(v0, v1);
                *(float2*)(of + o_hi) = make_float2(v2, v3);
            }
        }
    }

    if (STATS == 1) {
        // softmax stats per tile column over 128 rows; tile == qstats chunk
        __syncthreads();                       // smem stage buffers now reusable
        float* sm_m = (float*)smbuf;           // [128][4]
        float* sm_s = sm_m + 512;              // [128][4]
        const int w4 = warp & 3;
        float colm[16];
        #pragma unroll
        for (int j = 0; j < 8; j++)
            #pragma unroll
            for (int p = 0; p < 2; p++)
                colm[j*2+p] = fmaxf(fmaxf(acc[0][j][p], acc[0][j][p+2]),
                                    fmaxf(acc[1][j][p], acc[1][j][p+2]));
        #pragma unroll
        for (int mask = 4; mask <= 16; mask <<= 1)
            #pragma unroll
            for (int idx = 0; idx < 16; idx++)
                colm[idx] = fmaxf(colm[idx], __shfl_xor_sync(0xffffffffu, colm[idx], mask));
        if (grp == 0) {
            #pragma unroll
            for (int j = 0; j < 8; j++)
                #pragma unroll
                for (int p = 0; p < 2; p++)
                    sm_m[(wn + j*8 + kq*2 + p)*4 + w4] = colm[j*2+p];
        }
        __syncthreads();
        float csum[16];
        #pragma unroll
        for (int j = 0; j < 8; j++)
            #pragma unroll
            for (int p = 0; p < 2; p++) {
                int lc = wn + j*8 + kq*2 + p;
                float gm = fmaxf(fmaxf(sm_m[lc*4+0], sm_m[lc*4+1]),
                                 fmaxf(sm_m[lc*4+2], sm_m[lc*4+3]));
                csum[j*2+p] = expf(acc[0][j][p]   - gm) + expf(acc[0][j][p+2] - gm)
                            + expf(acc[1][j][p]   - gm) + expf(acc[1][j][p+2] - gm);
            }
        #pragma unroll
        for (int mask = 4; mask <= 16; mask <<= 1)
            #pragma unroll
            for (int idx = 0; idx < 16; idx++)
                csum[idx] += __shfl_xor_sync(0xffffffffu, csum[idx], mask);
        if (grp == 0) {
            #pragma unroll
            for (int j = 0; j < 8; j++)
                #pragma unroll
                for (int p = 0; p < 2; p++)
                    sm_s[(wn + j*8 + kq*2 + p)*4 + w4] = csum[j*2+p];
        }
        __syncthreads();
        if (t < 128) {
            float gm = fmaxf(fmaxf(sm_m[t*4+0], sm_m[t*4+1]),
                             fmaxf(sm_m[t*4+2], sm_m[t*4+3]));
            float ts = sm_s[t*4+0] + sm_s[t*4+1] + sm_s[t*4+2] + sm_s[t*4+3];
            g_qpm[(size_t)blockIdx.y * CCH + col0 + t] = gm;
            g_qps[(size_t)blockIdx.y * CCH + col0 + t] = ts;
        }
    }

    if (STATS == 2) {
        __syncthreads();
        float* sm_m = (float*)smbuf;           // [128][4]
        float* sm_s = sm_m + 512;
        const int w4 = warp & 3;
        #pragma unroll
        for (int mask = 4; mask <= 16; mask <<= 1)
            #pragma unroll
            for (int idx = 0; idx < 16; idx++) {
                colsum[idx] += __shfl_xor_sync(0xffffffffu, colsum[idx], mask);
                colmax[idx] = fmaxf(colmax[idx], __shfl_xor_sync(0xffffffffu, colmax[idx], mask));
            }
        if (grp == 0) {
            #pragma unroll
            for (int j = 0; j < 8; j++)
                #pragma unroll
                for (int p = 0; p < 2; p++) {
                    int lc = wn + j*8 + kq*2 + p;
                    sm_s[lc*4 + w4] = colsum[j*2+p];
                    sm_m[lc*4 + w4] = colmax[j*2+p];
                }
        }
        __syncthreads();
        if (t < 128) {
            int b = blockIdx.y >> 5;
            float ts = sm_s[t*4+0] + sm_s[t*4+1] + sm_s[t*4+2] + sm_s[t*4+3];
            float tm = fmaxf(fmaxf(sm_m[t*4+0], sm_m[t*4+1]),
                             fmaxf(sm_m[t*4+2], sm_m[t*4+3]));
            atomicAdd(&g_avg[b*CCH + col0 + t], ts);
            atomicMaxF(&g_mx[b*CCH + col0 + t], tm);
        }
    }
}

// ---------------- qfinal: combine per-chunk softmax stats ----------------
__global__ void qfinal_kernel() {
    int b = blockIdx.x, c = threadIdx.x;
    float m = -1e30f;
    for (int k = 0; k < 32; k++) m = fmaxf(m, g_qpm[(b*32 + k)*CCH + c]);
    float s = 0.f;
    for (int k = 0; k < 32; k++) s += g_qps[(b*32 + k)*CCH + c] * expf(g_qpm[(b*32 + k)*CCH + c] - m);
    g_qmax[b*CCH + c] = m;
    g_qsum[b*CCH + c] = s;
}

// ---------------- ctx = softmax_d(k)^T v  (fused k-softmax, kv bf16) ---------
__global__ void ctx_kernel() {
    int chunk = blockIdx.x;           // 0..7 : 512 rows each
    int bh = blockIdx.y;              // b*8+h
    int b = bh >> 3, h = bh & 7;
    int w = threadIdx.x >> 5, lane = threadIdx.x & 31;
    __shared__ float ks[32][33], vs[32][33];
    float acc[4] = {0.f, 0.f, 0.f, 0.f};
    int base = b * NNN + chunk * 512;
    for (int tile = 0; tile < 16; tile++) {
        #pragma unroll
        for (int rr = 0; rr < 4; rr++) {
            int rl = w * 4 + rr;
            size_t row = (size_t)(base + tile * 32 + rl);
            float kv = __bfloat162float(g_kvbf[row * 512 + h * 32 + lane]);
            float mx = kv;
            #pragma unroll
            for (int off = 16; off; off >>= 1) mx = fmaxf(mx, __shfl_xor_sync(0xffffffffu, mx, off));
            float e = expf(kv - mx);
            float ss = e;
            #pragma unroll
            for (int off = 16; off; off >>= 1) ss += __shfl_xor_sync(0xffffffffu, ss, off);
            ks[rl][lane] = e / ss;
            vs[rl][lane] = __bfloat162float(g_kvbf[row * 512 + 256 + h * 32 + lane]);
        }
        __syncthreads();
        for (int r = 0; r < 32; r++) {
            float vv = vs[r][lane];
            #pragma unroll
            for (int i = 0; i < 4; i++) acc[i] += ks[r][w*4 + i] * vv;
        }
        __syncthreads();
    }
    #pragma unroll
    for (int i = 0; i < 4; i++)
        atomicAdd(&g_ctx[bh * 1024 + (w*4 + i) * 32 + lane], acc[i]);
}

// ---------------- attn = softmax_N(q) @ ctx  (warp per head, bf16 out) -------
__global__ void attn_kernel() {
    int blk = blockIdx.x;             // 1024 blocks, 64 rows each
    int w = threadIdx.x >> 5, lane = threadIdx.x & 31;
    int b = blk >> 6;
    int h = w;
    float c[32];
    const float* cp = g_ctx + ((size_t)((b << 3) + h)) * 1024 + lane;
    #pragma unroll
    for (int d = 0; d < 32; d++) c[d] = cp[d * 32];
    float qm = g_qmax[b*CCH + h*32 + lane];
    float qi = 1.0f / g_qsum[b*CCH + h*32 + lane];
    int row0 = blk * 64;
    for (int r = 0; r < 64; r++) {
        size_t row = (size_t)(row0 + r);
        float qv = g_q[row * CCH + h*32 + lane];
        float qe = expf(qv - qm) * qi;
        float a0 = 0.f, a1 = 0.f;
        #pragma unroll
        for (int d = 0; d < 32; d += 2) {
            a0 += __shfl_sync(0xffffffffu, qe, d)     * c[d];
            a1 += __shfl_sync(0xffffffffu, qe, d + 1) * c[d + 1];
        }
        g_attnbf[row * CCH + h*32 + lane] = __float2bfloat16(a0 + a1);
    }
}

// ---------------- MixFFN dwconv 3x3 + gelu (tiled, bf16 in/out) --------------
__global__ void __launch_bounds__(256) dw_kernel(const float* __restrict__ dw_w,
                                                 const float* __restrict__ dw_b) {
    __shared__ float s[10*10*64];
    int tile = blockIdx.x;
    int cc = blockIdx.y;
    int b = blockIdx.z;
    int th0 = (tile >> 3) * 8, tw0 = (tile & 7) * 8;
    int t = threadIdx.x;
    int c0 = cc * 64;
    for (int l = t; l < 6400; l += 256) {
        int lh = l / 640, rem = l % 640, lw = rem / 64, lc = rem % 64;
        int gh = th0 + lh - 1, gw = tw0 + lw - 1;
        float v = 0.f;
        if (gh >= 0 && gh < HHH && gw >= 0 && gw < WWW)
            v = __bfloat162float(g_h1bf[(size_t)((b << 12) + (gh << 6) + gw) * HIDD + c0 + lc]);
        s[l] = v;
    }
    __syncthreads();
    int oc = t & 63;
    int cg = c0 + oc;
    float wt[9];
    #pragma unroll
    for (int k = 0; k < 9; k++) wt[k] = dw_w[cg*9 + k];
    float bias = dw_b[cg];
    for (int o = t; o < 4096; o += 256) {
        int oh = o >> 9, ow = (o >> 6) & 7;
        float acc = bias;
        #pragma unroll
        for (int kh = 0; kh < 3; kh++)
            #pragma unroll
            for (int kw = 0; kw < 3; kw++)
                acc += s[(oh + kh)*640 + (ow + kw)*64 + oc] * wt[kh*3 + kw];
        size_t row = (size_t)((b << 12) + ((th0 + oh) << 6) + (tw0 + ow));
        g_h2bf[row * HIDD + cg] = __float2bfloat16(geluf(acc));
    }
}

// ---------------- CSDA channel attention MLP ----------------
__global__ void ca_kernel(const float* __restrict__ w1, const float* __restrict__ w2) {
    int b = blockIdx.x, t = threadIdx.x;
    __shared__ float sav[CCH], smx[CCH], hid[32];
    sav[t] = g_avg[b * CCH + t] * (1.0f / NNN);
    smx[t] = g_mx[b * CCH + t];
    __syncthreads();
    if (t < 16) {
        float a = 0.f;
        for (int c = 0; c < CCH; c++) a += sav[c] * w1[t * CCH + c];
        hid[t] = fmaxf(a, 0.f);
    } else if (t < 32) {
        int j = t - 16;
        float a = 0.f;
        for (int c = 0; c < CCH; c++) a += smx[c] * w1[j * CCH + c];
        hid[16 + j] = fmaxf(a, 0.f);
    }
    __syncthreads();
    float a = 0.f;
    #pragma unroll
    for (int j = 0; j < 16; j++) a += (hid[j] + hid[16 + j]) * w2[t * 16 + j];
    g_cab[b * CCH + t] = sigmoidf_(a);
}

// ---------------- spatial map: mean/max over channels of x*ca ----------------
__global__ void smap_kernel() {
    int gid  = blockIdx.x * blockDim.x + threadIdx.x;
    int warp = gid >> 5, lane = gid & 31;
    if (warp >= MTOT) return;
    int b = warp >> 12;
    const float* row = g_x + (size_t)warp * CCH;
    const float* ca  = g_cab + b * CCH;
    float4 a = ((const float4*)row)[lane*2];
    float4 c4 = ((const float4*)ca)[lane*2];
    float4 b4 = ((const float4*)row)[lane*2+1];
    float4 d4 = ((const float4*)ca)[lane*2+1];
    float v0=a.x*c4.x, v1=a.y*c4.y, v2=a.z*c4.z, v3=a.w*c4.w;
    float v4=b4.x*d4.x, v5=b4.y*d4.y, v6=b4.z*d4.z, v7=b4.w*d4.w;
    float s = v0+v1+v2+v3+v4+v5+v6+v7;
    float m = fmaxf(fmaxf(fmaxf(v0,v1),fmaxf(v2,v3)), fmaxf(fmaxf(v4,v5),fmaxf(v6,v7)));
    #pragma unroll
    for (int off = 16; off; off >>= 1) {
        s += __shfl_xor_sync(0xffffffffu, s, off);
        m = fmaxf(m, __shfl_xor_sync(0xffffffffu, m, off));
    }
    if (lane == 0) {
        g_smean[warp] = s * (1.0f / CCH);
        g_smax[warp]  = m;
    }
}

// ---------------- spatial attention 7x7 conv + sigmoid ----------------
__global__ void sa_kernel(const float* __restrict__ sp_w, const float* __restrict__ sp_b) {
    int idx = blockIdx.x * blockDim.x + threadIdx.x;   // b*N+n
    int b = idx >> 12, n = idx & 4095;
    int h = n >> 6, w = n & 63;
    float acc = sp_b[0];
    for (int kh = 0; kh < 7; kh++) {
        int hh = h + kh - 3;
        if (hh < 0 || hh >= HHH) continue;
        for (int kw = 0; kw < 7; kw++) {
            int ww = w + kw - 3;
            if (ww < 0 || ww >= WWW) continue;
            int nn = b * NNN + hh * 64 + ww;
            acc += g_smean[nn] * sp_w[kh*7 + kw] + g_smax[nn] * sp_w[49 + kh*7 + kw];
        }
    }
    g_sa[idx] = sigmoidf_(acc);
}

// ---------------- final: out = x * ca * sa ----------------
__global__ void final_kernel(float* __restrict__ out) {
    int gid = blockIdx.x * blockDim.x + threadIdx.x;
    size_t idx4 = (size_t)gid * 4;
    int row = (int)(idx4 >> 8);
    int c   = (int)(idx4 & 255);
    int b   = row >> 12;
    float sa = g_sa[row];
    float4 ca = *(const float4*)(g_cab + b * CCH + c);
    float4 xv = *(const float4*)(g_x + idx4);
    float4 o;
    o.x = xv.x * ca.x * sa; o.y = xv.y * ca.y * sa;
    o.z = xv.z * ca.z * sa; o.w = xv.w * ca.w * sa;
    *(float4*)(out + idx4) = o;
}

// ---------------- launch ----------------
extern "C" void kernel_launch(void* const* d_in, const int* in_sizes, int n_in,
                              void* d_out, int out_size) {
    const float* x      = (const float*)d_in[0];
    const float* n1_g   = (const float*)d_in[3];
    const float* n1_b   = (const float*)d_in[4];
    const float* sr_w   = (const float*)d_in[5];
    const float* sr_b   = (const float*)d_in[6];
    const float* an_g   = (const float*)d_in[7];
    const float* an_b   = (const float*)d_in[8];
    const float* qkv_w  = (const float*)d_in[9];
    const float* proj_w = (const float*)d_in[10];
    const float* proj_b = (const float*)d_in[11];
    const float* n2_g   = (const float*)d_in[12];
    const float* n2_b   = (const float*)d_in[13];
    const float* fc1_w  = (const float*)d_in[14];
    const float* fc1_b  = (const float*)d_in[15];
    const float* dw_w   = (const float*)d_in[16];
    const float* dw_b   = (const float*)d_in[17];
    const float* fc2_w  = (const float*)d_in[18];
    const float* fc2_b  = (const float*)d_in[19];
    const float* ca_w1  = (const float*)d_in[20];
    const float* ca_w2  = (const float*)d_in[21];
    const float* sp_w   = (const float*)d_in[22];
    const float* sp_b   = (const float*)d_in[23];
    float* out = (float*)d_out;

    float *p_xn, *p_q, *p_x;
    __nv_bfloat16 *p_kvbf, *p_h1bf, *p_xabf, *p_xnbf, *p_attnbf, *p_h2bf;
    __nv_bfloat16 *p_wqkv, *p_wproj, *p_wfc1, *p_wfc2;
    cudaGetSymbolAddress((void**)&p_xn,    g_xn);
    cudaGetSymbolAddress((void**)&p_q,     g_q);
    cudaGetSymbolAddress((void**)&p_x,     g_x);
    cudaGetSymbolAddress((void**)&p_kvbf,  g_kvbf);
    cudaGetSymbolAddress((void**)&p_h1bf,  g_h1bf);
    cudaGetSymbolAddress((void**)&p_xabf,  g_xabf);
    cudaGetSymbolAddress((void**)&p_xnbf,  g_xnbf);
    cudaGetSymbolAddress((void**)&p_attnbf,g_attnbf);
    cudaGetSymbolAddress((void**)&p_h2bf,  g_h2bf);
    cudaGetSymbolAddress((void**)&p_wqkv,  g_wqkv);
    cudaGetSymbolAddress((void**)&p_wproj, g_wproj);
    cudaGetSymbolAddress((void**)&p_wfc1,  g_wfc1);
    cudaGetSymbolAddress((void**)&p_wfc2,  g_wfc2);

    cudaFuncSetAttribute(gemm_bf16<0,false,1>, cudaFuncAttributeMaxDynamicSharedMemorySize, GEMM_DSMEM);
    cudaFuncSetAttribute(gemm_bf16<0,true ,0>, cudaFuncAttributeMaxDynamicSharedMemorySize, GEMM_DSMEM);
    cudaFuncSetAttribute(gemm_bf16<1,true ,0>, cudaFuncAttributeMaxDynamicSharedMemorySize, GEMM_DSMEM);
    cudaFuncSetAttribute(gemm_bf16<2,false,0>, cudaFuncAttributeMaxDynamicSharedMemorySize, GEMM_DSMEM);
    cudaFuncSetAttribute(gemm_bf16<3,false,2>, cudaFuncAttributeMaxDynamicSharedMemorySize, GEMM_DSMEM);

    init_kernel<<<512, 256>>>();
    cvt_all_kernel<<<(NW_TOT+255)/256, 256>>>(qkv_w, proj_w, fc1_w, fc2_w);

    // --- attention branch ---
    ln_kernel<false><<<MTOT/8, 256>>>(x, n1_g, n1_b, p_xn, nullptr);
    sr_conv_kernel<<<dim3(64, 4, 16), 256>>>(sr_w, sr_b);     // conv out -> g_x (scratch)
    sr_ln_kernel<<<MTOT/8, 256>>>(an_g, an_b);                // -> g_xabf
    // q GEMM with fused softmax column stats; k+v merged GEMM (Nout=512)
    gemm_bf16<0,false,1><<<dim3(2, MTOT/128), 256, GEMM_DSMEM>>>(p_xabf, p_wqkv,
        nullptr, nullptr, nullptr, p_q, 256, 256);
    gemm_bf16<0,true,0><<<dim3(4, MTOT/128), 256, GEMM_DSMEM>>>(p_xabf, p_wqkv + 256*256,
        nullptr, nullptr, nullptr, p_kvbf, 512, 256);
    qfinal_kernel<<<BB, 256>>>();
    ctx_kernel<<<dim3(8, BB*NHEAD), 256>>>();
    attn_kernel<<<MTOT/64, 256>>>();
    gemm_bf16<2,false,0><<<dim3(2, MTOT/128), 256, GEMM_DSMEM>>>(p_attnbf, p_wproj, proj_b,
        p_xn, x, p_x, 256, 256);

    // --- MixFFN ---
    ln_kernel<true><<<MTOT/8, 256>>>(p_x, n2_g, n2_b, nullptr, p_xnbf);
    gemm_bf16<1,true,0><<<dim3(8, MTOT/128), 256, GEMM_DSMEM>>>(p_xnbf, p_wfc1, fc1_b,
        nullptr, nullptr, p_h1bf, 1024, 256);
    dw_kernel<<<dim3(64, 16, 16), 256>>>(dw_w, dw_b);
    // fc2 GEMM with fused channel avg/max stats
    gemm_bf16<3,false,2><<<dim3(2, MTOT/128), 256, GEMM_DSMEM>>>(p_h2bf, p_wfc2, fc2_b,
        p_x, nullptr, p_x, 256, 1024);

    // --- CSDA ---
    ca_kernel<<<BB, 256>>>(ca_w1, ca_w2);
    smap_kernel<<<MTOT/8, 256>>>();
    sa_kernel<<<MTOT/256, 256>>>(sp_w, sp_b);
    final_kernel<<<(MTOT*CCH/4)/256, 256>>>(out);
}